// round 5
// baseline (speedup 1.0000x reference)
#include <cuda_runtime.h>
#include <cuda_bf16.h>
#include <cstdint>
#include <math.h>

// ---------------------------------------------------------------------------
// Transformer block: LN1 -> QKV -> causal MHA -> proj(+res) -> LN2 -> FC1+GELU
//                    -> FC2(+res).  B=2, S=2048, D=1024, H=16, hd=64, FF=4096.
// All GEMMs + attention use TF32 mma.sync (m16n8k8) with fp32 accumulation.
// ---------------------------------------------------------------------------

#define DIM    1024
#define HIDDEN 4096
#define SEQ    2048
#define NTOK   4096   // B * S
#define NH     16
#define HD     64

// Scratch (allocation-free rule: device globals)
__device__ float g_h   [NTOK * DIM];      // LN output (reused for LN1 and LN2)
__device__ float g_qkv [NTOK * 3 * DIM];
__device__ float g_attn[NTOK * DIM];
__device__ float g_x1  [NTOK * DIM];
__device__ float g_mid [NTOK * HIDDEN];

// ---------------------------------------------------------------------------
// TF32 helpers
// ---------------------------------------------------------------------------
__device__ __forceinline__ uint32_t f2tf(float x) {
    uint32_t u;
    asm("cvt.rna.tf32.f32 %0, %1;" : "=r"(u) : "f"(x));
    return u;
}
__device__ __forceinline__ float f2tff(float x) { return __uint_as_float(f2tf(x)); }

__device__ __forceinline__ void mma8(float c[4], const uint32_t a[4], const uint32_t b[2]) {
    asm volatile(
        "mma.sync.aligned.m16n8k8.row.col.f32.tf32.tf32.f32 "
        "{%0,%1,%2,%3}, {%4,%5,%6,%7}, {%8,%9}, {%0,%1,%2,%3};"
        : "+f"(c[0]), "+f"(c[1]), "+f"(c[2]), "+f"(c[3])
        : "r"(a[0]), "r"(a[1]), "r"(a[2]), "r"(a[3]), "r"(b[0]), "r"(b[1]));
}

__device__ __forceinline__ float gelu_f(float v) {
    return 0.5f * v * (1.0f + erff(v * 0.70710678118654752440f));
}

// ---------------------------------------------------------------------------
// LayerNorm: one 256-thread block per row of 1024
// ---------------------------------------------------------------------------
__global__ __launch_bounds__(256) void ln_kernel(
    const float* __restrict__ x, const float* __restrict__ g,
    const float* __restrict__ be, float* __restrict__ out)
{
    const int row = blockIdx.x;
    const int tid = threadIdx.x;
    const float4 v = *(const float4*)(x + (size_t)row * DIM + (tid << 2));
    float s = v.x + v.y + v.z + v.w;
    float q = v.x * v.x + v.y * v.y + v.z * v.z + v.w * v.w;
    #pragma unroll
    for (int off = 16; off; off >>= 1) {
        s += __shfl_xor_sync(0xffffffffu, s, off);
        q += __shfl_xor_sync(0xffffffffu, q, off);
    }
    __shared__ float ss[8], sq[8];
    if ((tid & 31) == 0) { ss[tid >> 5] = s; sq[tid >> 5] = q; }
    __syncthreads();
    float ts = 0.f, tq = 0.f;
    #pragma unroll
    for (int i = 0; i < 8; i++) { ts += ss[i]; tq += sq[i]; }
    const float mu  = ts * (1.0f / DIM);
    const float var = tq * (1.0f / DIM) - mu * mu;
    const float inv = rsqrtf(var + 1e-5f);
    const float4 gg = *(const float4*)(g  + (tid << 2));
    const float4 bb = *(const float4*)(be + (tid << 2));
    float4 r;
    r.x = (v.x - mu) * inv * gg.x + bb.x;
    r.y = (v.y - mu) * inv * gg.y + bb.y;
    r.z = (v.z - mu) * inv * gg.z + bb.z;
    r.w = (v.w - mu) * inv * gg.w + bb.w;
    *(float4*)(out + (size_t)row * DIM + (tid << 2)) = r;
}

// ---------------------------------------------------------------------------
// GEMM: C[M,N] = A[M,K] @ W[K,N] + bias  (opt GELU, opt +residual)
// CTA tile 128x128, k-tile 32. 8 warps in 4x2; warp tile 32x64 (2x8 m16n8).
// ---------------------------------------------------------------------------
template <bool GELU_, bool RESID_>
__global__ __launch_bounds__(256) void gemm_kernel(
    const float* __restrict__ A, const float* __restrict__ W,
    const float* __restrict__ bias, const float* __restrict__ R,
    float* __restrict__ C, int M, int N, int K)
{
    __shared__ float As[128][36];   // +4 pad: conflict-free A-frag LDS
    __shared__ float Bs[32][132];   // +4 pad

    const int tid  = threadIdx.x;
    const int warp = tid >> 5, lane = tid & 31;
    const int wm = warp >> 1, wn = warp & 1;
    const int bm = blockIdx.y << 7, bn = blockIdx.x << 7;

    float acc[2][8][4];
    #pragma unroll
    for (int i = 0; i < 2; i++)
        #pragma unroll
        for (int j = 0; j < 8; j++)
            #pragma unroll
            for (int k = 0; k < 4; k++) acc[i][j][k] = 0.f;

    for (int k0 = 0; k0 < K; k0 += 32) {
        // Stage A tile 128x32 (tf32-rounded)
        #pragma unroll
        for (int i = 0; i < 4; i++) {
            int idx = tid + (i << 8);
            int r = idx >> 3, c = (idx & 7) << 2;
            float4 v = *(const float4*)&A[(size_t)(bm + r) * K + k0 + c];
            v.x = f2tff(v.x); v.y = f2tff(v.y); v.z = f2tff(v.z); v.w = f2tff(v.w);
            *(float4*)&As[r][c] = v;
        }
        // Stage B tile 32x128
        #pragma unroll
        for (int i = 0; i < 4; i++) {
            int idx = tid + (i << 8);
            int r = idx >> 5, c = (idx & 31) << 2;
            float4 v = *(const float4*)&W[(size_t)(k0 + r) * N + bn + c];
            v.x = f2tff(v.x); v.y = f2tff(v.y); v.z = f2tff(v.z); v.w = f2tff(v.w);
            *(float4*)&Bs[r][c] = v;
        }
        __syncthreads();

        #pragma unroll
        for (int kk = 0; kk < 32; kk += 8) {
            uint32_t af[2][4], bf[8][2];
            #pragma unroll
            for (int mt = 0; mt < 2; mt++) {
                int r  = (wm << 5) + (mt << 4) + (lane >> 2);
                int cA = kk + (lane & 3);
                af[mt][0] = __float_as_uint(As[r    ][cA    ]);
                af[mt][1] = __float_as_uint(As[r + 8][cA    ]);
                af[mt][2] = __float_as_uint(As[r    ][cA + 4]);
                af[mt][3] = __float_as_uint(As[r + 8][cA + 4]);
            }
            #pragma unroll
            for (int nt = 0; nt < 8; nt++) {
                int cB = (wn << 6) + (nt << 3) + (lane >> 2);
                int rB = kk + (lane & 3);
                bf[nt][0] = __float_as_uint(Bs[rB    ][cB]);
                bf[nt][1] = __float_as_uint(Bs[rB + 4][cB]);
            }
            #pragma unroll
            for (int mt = 0; mt < 2; mt++)
                #pragma unroll
                for (int nt = 0; nt < 8; nt++)
                    mma8(acc[mt][nt], af[mt], bf[nt]);
        }
        __syncthreads();
    }

    // Epilogue
    #pragma unroll
    for (int mt = 0; mt < 2; mt++) {
        #pragma unroll
        for (int nt = 0; nt < 8; nt++) {
            int row0 = bm + (wm << 5) + (mt << 4) + (lane >> 2);
            int col  = bn + (wn << 6) + (nt << 3) + ((lane & 3) << 1);
            #pragma unroll
            for (int half = 0; half < 2; half++) {
                int row = row0 + half * 8;
                float v0 = acc[mt][nt][half * 2 + 0] + bias[col];
                float v1 = acc[mt][nt][half * 2 + 1] + bias[col + 1];
                if (GELU_) { v0 = gelu_f(v0); v1 = gelu_f(v1); }
                if (RESID_) {
                    v0 += R[(size_t)row * N + col];
                    v1 += R[(size_t)row * N + col + 1];
                }
                C[(size_t)row * N + col]     = v0;
                C[(size_t)row * N + col + 1] = v1;
            }
        }
    }
}

// ---------------------------------------------------------------------------
// Causal flash attention.
// grid = (S/128, NH, B); 256 threads = 8 warps, each warp owns 16 query rows.
// KV block = 64. Q/K/V/P staged in dynamic smem (stride 68 floats).
// qkv layout: [B][S][3][NH][HD] fp32.
// ---------------------------------------------------------------------------
#define ASTRIDE 68
__global__ __launch_bounds__(256) void attn_kernel(
    const float* __restrict__ qkv, float* __restrict__ outp)
{
    extern __shared__ float sm[];
    float (*Qs)[ASTRIDE] = (float(*)[ASTRIDE])(sm);                 // 128 rows
    float (*Ks)[ASTRIDE] = (float(*)[ASTRIDE])(sm + 128 * ASTRIDE); //  64 rows
    float (*Vs)[ASTRIDE] = (float(*)[ASTRIDE])(sm + 192 * ASTRIDE); //  64 rows
    float (*Ps)[ASTRIDE] = (float(*)[ASTRIDE])(sm + 256 * ASTRIDE); // 128 rows

    const int qb = blockIdx.x, h = blockIdx.y, b = blockIdx.z;
    const int tid = threadIdx.x, warp = tid >> 5, lane = tid & 31;
    const int q0 = qb << 7;

    // Load Q block (128 x 64), tf32-rounded
    const float* qbase = qkv + (size_t)(b * SEQ + q0) * (3 * DIM) + h * HD;
    #pragma unroll
    for (int i = 0; i < 8; i++) {
        int idx = tid + (i << 8);
        int r = idx >> 4, c = (idx & 15) << 2;
        float4 v = *(const float4*)(qbase + (size_t)r * (3 * DIM) + c);
        v.x = f2tff(v.x); v.y = f2tff(v.y); v.z = f2tff(v.z); v.w = f2tff(v.w);
        *(float4*)&Qs[r][c] = v;
    }

    float o[8][4];
    #pragma unroll
    for (int i = 0; i < 8; i++)
        #pragma unroll
        for (int j = 0; j < 4; j++) o[i][j] = 0.f;
    float m0 = -1e30f, m1 = -1e30f, l0 = 0.f, l1 = 0.f;

    const int ar = (warp << 4) + (lane >> 2);   // local query row (c0/c1); +8 for c2/c3
    const int nkb = (q0 >> 6) + 2;              // causal KV-block count

    for (int kb = 0; kb < nkb; kb++) {
        __syncthreads();   // previous iteration's K/V fully consumed
        const float* kptr = qkv + (size_t)(b * SEQ + (kb << 6)) * (3 * DIM) + DIM + h * HD;
        #pragma unroll
        for (int i = 0; i < 4; i++) {
            int idx = tid + (i << 8);
            int r = idx >> 4, c = (idx & 15) << 2;
            float4 kv = *(const float4*)(kptr + (size_t)r * (3 * DIM) + c);
            float4 vv = *(const float4*)(kptr + (size_t)r * (3 * DIM) + DIM + c);
            kv.x = f2tff(kv.x); kv.y = f2tff(kv.y); kv.z = f2tff(kv.z); kv.w = f2tff(kv.w);
            vv.x = f2tff(vv.x); vv.y = f2tff(vv.y); vv.z = f2tff(vv.z); vv.w = f2tff(vv.w);
            *(float4*)&Ks[r][c] = kv;
            *(float4*)&Vs[r][c] = vv;
        }
        __syncthreads();

        // S = Q @ K^T  (warp: 16 rows x 64 kv cols)
        float s[8][4];
        #pragma unroll
        for (int i = 0; i < 8; i++)
            #pragma unroll
            for (int j = 0; j < 4; j++) s[i][j] = 0.f;

        #pragma unroll
        for (int kk = 0; kk < 64; kk += 8) {
            uint32_t a[4];
            a[0] = __float_as_uint(Qs[ar    ][kk + (lane & 3)    ]);
            a[1] = __float_as_uint(Qs[ar + 8][kk + (lane & 3)    ]);
            a[2] = __float_as_uint(Qs[ar    ][kk + (lane & 3) + 4]);
            a[3] = __float_as_uint(Qs[ar + 8][kk + (lane & 3) + 4]);
            #pragma unroll
            for (int nt = 0; nt < 8; nt++) {
                uint32_t bfr[2];
                int n = (nt << 3) + (lane >> 2);
                bfr[0] = __float_as_uint(Ks[n][kk + (lane & 3)    ]);
                bfr[1] = __float_as_uint(Ks[n][kk + (lane & 3) + 4]);
                mma8(s[nt], a, bfr);
            }
        }

        // scale + causal mask + online softmax
        const int grow0 = q0 + ar;
        const int grow1 = grow0 + 8;
        const int cbase = (kb << 6) + ((lane & 3) << 1);
        float mn0 = m0, mn1 = m1;
        #pragma unroll
        for (int nt = 0; nt < 8; nt++) {
            int c0 = cbase + (nt << 3);
            s[nt][0] = (c0     <= grow0) ? s[nt][0] * 0.125f : -1e30f;
            s[nt][1] = (c0 + 1 <= grow0) ? s[nt][1] * 0.125f : -1e30f;
            s[nt][2] = (c0     <= grow1) ? s[nt][2] * 0.125f : -1e30f;
            s[nt][3] = (c0 + 1 <= grow1) ? s[nt][3] * 0.125f : -1e30f;
            mn0 = fmaxf(mn0, fmaxf(s[nt][0], s[nt][1]));
            mn1 = fmaxf(mn1, fmaxf(s[nt][2], s[nt][3]));
        }
        mn0 = fmaxf(mn0, __shfl_xor_sync(0xffffffffu, mn0, 1));
        mn0 = fmaxf(mn0, __shfl_xor_sync(0xffffffffu, mn0, 2));
        mn1 = fmaxf(mn1, __shfl_xor_sync(0xffffffffu, mn1, 1));
        mn1 = fmaxf(mn1, __shfl_xor_sync(0xffffffffu, mn1, 2));

        const float corr0 = __expf(m0 - mn0);
        const float corr1 = __expf(m1 - mn1);
        m0 = mn0; m1 = mn1;

        float rs0 = 0.f, rs1 = 0.f;
        #pragma unroll
        for (int nt = 0; nt < 8; nt++) {
            float p0 = __expf(s[nt][0] - m0);
            float p1 = __expf(s[nt][1] - m0);
            float p2 = __expf(s[nt][2] - m1);
            float p3 = __expf(s[nt][3] - m1);
            rs0 += p0 + p1; rs1 += p2 + p3;
            int pc = (nt << 3) + ((lane & 3) << 1);
            Ps[ar    ][pc]     = f2tff(p0);
            Ps[ar    ][pc + 1] = f2tff(p1);
            Ps[ar + 8][pc]     = f2tff(p2);
            Ps[ar + 8][pc + 1] = f2tff(p3);
        }
        rs0 += __shfl_xor_sync(0xffffffffu, rs0, 1);
        rs0 += __shfl_xor_sync(0xffffffffu, rs0, 2);
        rs1 += __shfl_xor_sync(0xffffffffu, rs1, 1);
        rs1 += __shfl_xor_sync(0xffffffffu, rs1, 2);
        l0 = l0 * corr0 + rs0;
        l1 = l1 * corr1 + rs1;
        #pragma unroll
        for (int nt = 0; nt < 8; nt++) {
            o[nt][0] *= corr0; o[nt][1] *= corr0;
            o[nt][2] *= corr1; o[nt][3] *= corr1;
        }
        __syncwarp();   // Ps visible to whole warp (P region is warp-private)

        // O += P @ V  (warp: 16 rows x 64 d cols, k = 64 kv)
        #pragma unroll
        for (int kk = 0; kk < 64; kk += 8) {
            uint32_t a[4];
            a[0] = __float_as_uint(Ps[ar    ][kk + (lane & 3)    ]);
            a[1] = __float_as_uint(Ps[ar + 8][kk + (lane & 3)    ]);
            a[2] = __float_as_uint(Ps[ar    ][kk + (lane & 3) + 4]);
            a[3] = __float_as_uint(Ps[ar + 8][kk + (lane & 3) + 4]);
            #pragma unroll
            for (int nt = 0; nt < 8; nt++) {
                uint32_t bfr[2];
                int n = (nt << 3) + (lane >> 2);
                bfr[0] = __float_as_uint(Vs[kk + (lane & 3)    ][n]);
                bfr[1] = __float_as_uint(Vs[kk + (lane & 3) + 4][n]);
                mma8(o[nt], a, bfr);
            }
        }
    }

    // Write: out[b, q0+row, h*64 + col]
    const float inv0 = 1.0f / l0;
    const float inv1 = 1.0f / l1;
    #pragma unroll
    for (int nt = 0; nt < 8; nt++) {
        int col = h * HD + (nt << 3) + ((lane & 3) << 1);
        size_t base0 = (size_t)(b * SEQ + q0 + ar) * DIM + col;
        size_t base1 = base0 + (size_t)8 * DIM;
        outp[base0]     = o[nt][0] * inv0;
        outp[base0 + 1] = o[nt][1] * inv0;
        outp[base1]     = o[nt][2] * inv1;
        outp[base1 + 1] = o[nt][3] * inv1;
    }
}

// ---------------------------------------------------------------------------
// Launch
// ---------------------------------------------------------------------------
extern "C" void kernel_launch(void* const* d_in, const int* in_sizes, int n_in,
                              void* d_out, int out_size)
{
    const float* x      = (const float*)d_in[0];
    const float* w_qkv  = (const float*)d_in[1];
    const float* b_qkv  = (const float*)d_in[2];
    const float* w_proj = (const float*)d_in[3];
    const float* b_proj = (const float*)d_in[4];
    const float* g1     = (const float*)d_in[5];
    const float* beta1  = (const float*)d_in[6];
    const float* g2     = (const float*)d_in[7];
    const float* beta2  = (const float*)d_in[8];
    const float* w_fc1  = (const float*)d_in[9];
    const float* b_fc1  = (const float*)d_in[10];
    const float* w_fc2  = (const float*)d_in[11];
    const float* b_fc2  = (const float*)d_in[12];
    float* out = (float*)d_out;

    float *h, *qkv, *attn, *x1, *mid;
    cudaGetSymbolAddress((void**)&h,    g_h);
    cudaGetSymbolAddress((void**)&qkv,  g_qkv);
    cudaGetSymbolAddress((void**)&attn, g_attn);
    cudaGetSymbolAddress((void**)&x1,   g_x1);
    cudaGetSymbolAddress((void**)&mid,  g_mid);

    const int ATTN_SMEM = 384 * ASTRIDE * (int)sizeof(float);  // ~102 KB
    cudaFuncSetAttribute(attn_kernel, cudaFuncAttributeMaxDynamicSharedMemorySize, ATTN_SMEM);

    // 1) LN1
    ln_kernel<<<NTOK, 256>>>(x, g1, beta1, h);
    // 2) QKV = h @ w_qkv + b_qkv        [4096,1024]x[1024,3072]
    gemm_kernel<false, false><<<dim3(3 * DIM / 128, NTOK / 128), 256>>>(
        h, w_qkv, b_qkv, nullptr, qkv, NTOK, 3 * DIM, DIM);
    // 3) Causal MHA
    attn_kernel<<<dim3(SEQ / 128, NH, 2), 256, ATTN_SMEM>>>(qkv, attn);
    // 4) x1 = x + attn @ w_proj + b_proj
    gemm_kernel<false, true><<<dim3(DIM / 128, NTOK / 128), 256>>>(
        attn, w_proj, b_proj, x, x1, NTOK, DIM, DIM);
    // 5) LN2
    ln_kernel<<<NTOK, 256>>>(x1, g2, beta2, h);
    // 6) mid = gelu(h @ w_fc1 + b_fc1)   [4096,1024]x[1024,4096]
    gemm_kernel<true, false><<<dim3(HIDDEN / 128, NTOK / 128), 256>>>(
        h, w_fc1, b_fc1, nullptr, mid, NTOK, HIDDEN, DIM);
    // 7) out = x1 + mid @ w_fc2 + b_fc2  [4096,4096]x[4096,1024]
    gemm_kernel<false, true><<<dim3(DIM / 128, NTOK / 128), 256>>>(
        mid, w_fc2, b_fc2, x1, out, NTOK, DIM, HIDDEN);
}

// round 9
// speedup vs baseline: 1.0429x; 1.0429x over previous
#include <cuda_runtime.h>
#include <cuda_bf16.h>
#include <cstdint>
#include <math.h>

// ---------------------------------------------------------------------------
// Transformer block: LN1 -> QKV -> causal MHA -> proj(+res) -> LN2 -> FC1+GELU
//                    -> FC2(+res).  B=2, S=2048, D=1024, H=16, hd=64, FF=4096.
// TF32 mma.sync (m16n8k8) everywhere, fp32 accumulation.
// Design: (a) all GEMM operands pre-rounded to tf32 at the producer, so the
// GEMM mainloop has ZERO cvt ops; (b) GEMM mainloop uses cp.async 2-stage
// double buffering in dynamic smem.
// ---------------------------------------------------------------------------

#define DIM    1024
#define HIDDEN 4096
#define SEQ    2048
#define NTOK   4096   // B * S
#define NH     16
#define HD     64

// Scratch (allocation-free rule: device globals)
__device__ float g_h    [NTOK * DIM];       // LN output (tf32-rounded)
__device__ float g_qkv  [NTOK * 3 * DIM];   // tf32-rounded
__device__ float g_attn [NTOK * DIM];       // tf32-rounded
__device__ float g_x1   [NTOK * DIM];       // full fp32 (residual stream)
__device__ float g_mid  [NTOK * HIDDEN];    // tf32-rounded
// tf32-rounded weight copies
__device__ float g_wqkv [DIM * 3 * DIM];
__device__ float g_wproj[DIM * DIM];
__device__ float g_wfc1 [DIM * HIDDEN];
__device__ float g_wfc2 [HIDDEN * DIM];

// ---------------------------------------------------------------------------
// TF32 helpers
// ---------------------------------------------------------------------------
__device__ __forceinline__ uint32_t f2tf(float x) {
    uint32_t u;
    asm("cvt.rna.tf32.f32 %0, %1;" : "=r"(u) : "f"(x));
    return u;
}
__device__ __forceinline__ float f2tff(float x) { return __uint_as_float(f2tf(x)); }

__device__ __forceinline__ void mma8(float c[4], const uint32_t a[4], const uint32_t b[2]) {
    asm volatile(
        "mma.sync.aligned.m16n8k8.row.col.f32.tf32.tf32.f32 "
        "{%0,%1,%2,%3}, {%4,%5,%6,%7}, {%8,%9}, {%0,%1,%2,%3};"
        : "+f"(c[0]), "+f"(c[1]), "+f"(c[2]), "+f"(c[3])
        : "r"(a[0]), "r"(a[1]), "r"(a[2]), "r"(a[3]), "r"(b[0]), "r"(b[1]));
}

__device__ __forceinline__ void cpa16(uint32_t dst, const void* src) {
    asm volatile("cp.async.cg.shared.global [%0], [%1], 16;" :: "r"(dst), "l"(src) : "memory");
}
#define CP_COMMIT() asm volatile("cp.async.commit_group;" ::: "memory")
#define CP_WAIT1()  asm volatile("cp.async.wait_group 1;" ::: "memory")
#define CP_WAIT0()  asm volatile("cp.async.wait_group 0;" ::: "memory")

__device__ __forceinline__ float gelu_f(float v) {
    return 0.5f * v * (1.0f + erff(v * 0.70710678118654752440f));
}

// ---------------------------------------------------------------------------
// Elementwise tf32 round-copy (for weights), float4 per thread
// ---------------------------------------------------------------------------
__global__ __launch_bounds__(256) void round_copy(
    const float* __restrict__ s, float* __restrict__ d)
{
    int i = (blockIdx.x * 256 + threadIdx.x) << 2;
    float4 v = *(const float4*)(s + i);
    v.x = f2tff(v.x); v.y = f2tff(v.y); v.z = f2tff(v.z); v.w = f2tff(v.w);
    *(float4*)(d + i) = v;
}

// ---------------------------------------------------------------------------
// LayerNorm: one 256-thread block per row of 1024.  Output tf32-rounded
// (it is consumed only as a GEMM A operand).
// ---------------------------------------------------------------------------
__global__ __launch_bounds__(256) void ln_kernel(
    const float* __restrict__ x, const float* __restrict__ g,
    const float* __restrict__ be, float* __restrict__ out)
{
    const int row = blockIdx.x;
    const int tid = threadIdx.x;
    const float4 v = *(const float4*)(x + (size_t)row * DIM + (tid << 2));
    float s = v.x + v.y + v.z + v.w;
    float q = v.x * v.x + v.y * v.y + v.z * v.z + v.w * v.w;
    #pragma unroll
    for (int off = 16; off; off >>= 1) {
        s += __shfl_xor_sync(0xffffffffu, s, off);
        q += __shfl_xor_sync(0xffffffffu, q, off);
    }
    __shared__ float ss[8], sq[8];
    if ((tid & 31) == 0) { ss[tid >> 5] = s; sq[tid >> 5] = q; }
    __syncthreads();
    float ts = 0.f, tq = 0.f;
    #pragma unroll
    for (int i = 0; i < 8; i++) { ts += ss[i]; tq += sq[i]; }
    const float mu  = ts * (1.0f / DIM);
    const float var = tq * (1.0f / DIM) - mu * mu;
    const float inv = rsqrtf(var + 1e-5f);
    const float4 gg = *(const float4*)(g  + (tid << 2));
    const float4 bb = *(const float4*)(be + (tid << 2));
    float4 r;
    r.x = f2tff((v.x - mu) * inv * gg.x + bb.x);
    r.y = f2tff((v.y - mu) * inv * gg.y + bb.y);
    r.z = f2tff((v.z - mu) * inv * gg.z + bb.z);
    r.w = f2tff((v.w - mu) * inv * gg.w + bb.w);
    *(float4*)(out + (size_t)row * DIM + (tid << 2)) = r;
}

// ---------------------------------------------------------------------------
// GEMM: C[M,N] = A[M,K] @ W[K,N] + bias  (opt GELU, opt +residual, opt tf32-
// round of output).  A and W must already be tf32-rounded in gmem.
// CTA tile 128x128, k-tile 32, cp.async 2-stage double buffer (dynamic smem).
// 8 warps in 4x2; warp tile 32x64 (2x8 m16n8).
// ---------------------------------------------------------------------------
#define AS_ELEMS (128 * 36)   // per stage, +4 pad
#define BS_ELEMS (32 * 132)   // per stage, +4 pad
#define GEMM_SMEM ((2 * AS_ELEMS + 2 * BS_ELEMS) * 4)

template <bool GELU_, bool RESID_, bool ROUND_>
__global__ __launch_bounds__(256) void gemm_kernel(
    const float* __restrict__ A, const float* __restrict__ W,
    const float* __restrict__ bias, const float* __restrict__ R,
    float* __restrict__ C, int M, int N, int K)
{
    extern __shared__ float gsm[];
    float* Asm = gsm;                      // 2 stages of [128][36]
    float* Bsm = gsm + 2 * AS_ELEMS;       // 2 stages of [32][132]

    const int tid  = threadIdx.x;
    const int warp = tid >> 5, lane = tid & 31;
    const int wm = warp >> 1, wn = warp & 1;
    const int bm = blockIdx.y << 7, bn = blockIdx.x << 7;

    const uint32_t As_u = (uint32_t)__cvta_generic_to_shared(Asm);
    const uint32_t Bs_u = (uint32_t)__cvta_generic_to_shared(Bsm);

    float acc[2][8][4];
    #pragma unroll
    for (int i = 0; i < 2; i++)
        #pragma unroll
        for (int j = 0; j < 8; j++)
            #pragma unroll
            for (int k = 0; k < 4; k++) acc[i][j][k] = 0.f;

    const int KT = K >> 5;   // number of 32-wide k-tiles

    // Async stage loader: stage s <- k-tile starting at k0 (commits one group)
    auto load_stage = [&](int s, int k0) {
        // A tile 128x32 : 1024 16B chunks, 4 per thread
        #pragma unroll
        for (int i = 0; i < 4; i++) {
            int c  = tid + (i << 8);
            int r  = c >> 3, off = (c & 7) << 2;
            cpa16(As_u + (uint32_t)((s * AS_ELEMS + r * 36 + off) << 2),
                  A + (size_t)(bm + r) * K + k0 + off);
        }
        // B tile 32x128 : 1024 16B chunks, 4 per thread
        #pragma unroll
        for (int i = 0; i < 4; i++) {
            int c  = tid + (i << 8);
            int r  = c >> 5, off = (c & 31) << 2;
            cpa16(Bs_u + (uint32_t)((s * BS_ELEMS + r * 132 + off) << 2),
                  W + (size_t)(k0 + r) * N + bn + off);
        }
        CP_COMMIT();
    };

    load_stage(0, 0);

    for (int kt = 0; kt < KT; kt++) {
        if (kt + 1 < KT) {
            load_stage((kt + 1) & 1, (kt + 1) << 5);
            CP_WAIT1();      // stage kt landed; stage kt+1 still in flight
        } else {
            CP_WAIT0();      // last tile: drain everything
        }
        __syncthreads();

        const float* As_ = Asm + (kt & 1) * AS_ELEMS;
        const float* Bs_ = Bsm + (kt & 1) * BS_ELEMS;

        #pragma unroll
        for (int kk = 0; kk < 32; kk += 8) {
            uint32_t af[2][4], bf[8][2];
            #pragma unroll
            for (int mt = 0; mt < 2; mt++) {
                int r  = (wm << 5) + (mt << 4) + (lane >> 2);
                int cA = kk + (lane & 3);
                af[mt][0] = __float_as_uint(As_[ r      * 36 + cA    ]);
                af[mt][1] = __float_as_uint(As_[(r + 8) * 36 + cA    ]);
                af[mt][2] = __float_as_uint(As_[ r      * 36 + cA + 4]);
                af[mt][3] = __float_as_uint(As_[(r + 8) * 36 + cA + 4]);
            }
            #pragma unroll
            for (int nt = 0; nt < 8; nt++) {
                int cB = (wn << 6) + (nt << 3) + (lane >> 2);
                int rB = kk + (lane & 3);
                bf[nt][0] = __float_as_uint(Bs_[ rB      * 132 + cB]);
                bf[nt][1] = __float_as_uint(Bs_[(rB + 4) * 132 + cB]);
            }
            #pragma unroll
            for (int mt = 0; mt < 2; mt++)
                #pragma unroll
                for (int nt = 0; nt < 8; nt++)
                    mma8(acc[mt][nt], af[mt], bf[nt]);
        }
        __syncthreads();     // stage kt fully consumed before it is overwritten
    }

    // Epilogue
    #pragma unroll
    for (int mt = 0; mt < 2; mt++) {
        #pragma unroll
        for (int nt = 0; nt < 8; nt++) {
            int row0 = bm + (wm << 5) + (mt << 4) + (lane >> 2);
            int col  = bn + (wn << 6) + (nt << 3) + ((lane & 3) << 1);
            const float b0 = __ldg(bias + col);
            const float b1 = __ldg(bias + col + 1);
            #pragma unroll
            for (int half = 0; half < 2; half++) {
                int row = row0 + half * 8;
                float v0 = acc[mt][nt][half * 2 + 0] + b0;
                float v1 = acc[mt][nt][half * 2 + 1] + b1;
                if (GELU_) { v0 = gelu_f(v0); v1 = gelu_f(v1); }
                if (RESID_) {
                    v0 += __ldg(R + (size_t)row * N + col);
                    v1 += __ldg(R + (size_t)row * N + col + 1);
                }
                if (ROUND_) { v0 = f2tff(v0); v1 = f2tff(v1); }
                C[(size_t)row * N + col]     = v0;
                C[(size_t)row * N + col + 1] = v1;
            }
        }
    }
}

// ---------------------------------------------------------------------------
// Causal flash attention.  Inputs (qkv) already tf32-rounded; output rounded.
// grid = (S/128, NH, B); 256 threads = 8 warps, each warp owns 16 query rows.
// KV block = 64. Q/K/V/P staged in dynamic smem (stride 68 floats).
// qkv layout: [B][S][3][NH][HD] fp32.
// ---------------------------------------------------------------------------
#define ASTRIDE 68
__global__ __launch_bounds__(256) void attn_kernel(
    const float* __restrict__ qkv, float* __restrict__ outp)
{
    extern __shared__ float sm[];
    float (*Qs)[ASTRIDE] = (float(*)[ASTRIDE])(sm);                 // 128 rows
    float (*Ks)[ASTRIDE] = (float(*)[ASTRIDE])(sm + 128 * ASTRIDE); //  64 rows
    float (*Vs)[ASTRIDE] = (float(*)[ASTRIDE])(sm + 192 * ASTRIDE); //  64 rows
    float (*Ps)[ASTRIDE] = (float(*)[ASTRIDE])(sm + 256 * ASTRIDE); // 128 rows

    const int qb = blockIdx.x, h = blockIdx.y, b = blockIdx.z;
    const int tid = threadIdx.x, warp = tid >> 5, lane = tid & 31;
    const int q0 = qb << 7;

    // Load Q block (128 x 64) — already tf32
    const float* qbase = qkv + (size_t)(b * SEQ + q0) * (3 * DIM) + h * HD;
    #pragma unroll
    for (int i = 0; i < 8; i++) {
        int idx = tid + (i << 8);
        int r = idx >> 4, c = (idx & 15) << 2;
        *(float4*)&Qs[r][c] = *(const float4*)(qbase + (size_t)r * (3 * DIM) + c);
    }

    float o[8][4];
    #pragma unroll
    for (int i = 0; i < 8; i++)
        #pragma unroll
        for (int j = 0; j < 4; j++) o[i][j] = 0.f;
    float m0 = -1e30f, m1 = -1e30f, l0 = 0.f, l1 = 0.f;

    const int ar = (warp << 4) + (lane >> 2);   // local query row (c0/c1); +8 for c2/c3
    const int nkb = (q0 >> 6) + 2;              // causal KV-block count

    for (int kb = 0; kb < nkb; kb++) {
        __syncthreads();   // previous iteration's K/V fully consumed
        const float* kptr = qkv + (size_t)(b * SEQ + (kb << 6)) * (3 * DIM) + DIM + h * HD;
        #pragma unroll
        for (int i = 0; i < 4; i++) {
            int idx = tid + (i << 8);
            int r = idx >> 4, c = (idx & 15) << 2;
            *(float4*)&Ks[r][c] = *(const float4*)(kptr + (size_t)r * (3 * DIM) + c);
            *(float4*)&Vs[r][c] = *(const float4*)(kptr + (size_t)r * (3 * DIM) + DIM + c);
        }
        __syncthreads();

        // S = Q @ K^T  (warp: 16 rows x 64 kv cols)
        float s[8][4];
        #pragma unroll
        for (int i = 0; i < 8; i++)
            #pragma unroll
            for (int j = 0; j < 4; j++) s[i][j] = 0.f;

        #pragma unroll
        for (int kk = 0; kk < 64; kk += 8) {
            uint32_t a[4];
            a[0] = __float_as_uint(Qs[ar    ][kk + (lane & 3)    ]);
            a[1] = __float_as_uint(Qs[ar + 8][kk + (lane & 3)    ]);
            a[2] = __float_as_uint(Qs[ar    ][kk + (lane & 3) + 4]);
            a[3] = __float_as_uint(Qs[ar + 8][kk + (lane & 3) + 4]);
            #pragma unroll
            for (int nt = 0; nt < 8; nt++) {
                uint32_t bfr[2];
                int n = (nt << 3) + (lane >> 2);
                bfr[0] = __float_as_uint(Ks[n][kk + (lane & 3)    ]);
                bfr[1] = __float_as_uint(Ks[n][kk + (lane & 3) + 4]);
                mma8(s[nt], a, bfr);
            }
        }

        // scale + causal mask + online softmax
        const int grow0 = q0 + ar;
        const int grow1 = grow0 + 8;
        const int cbase = (kb << 6) + ((lane & 3) << 1);
        float mn0 = m0, mn1 = m1;
        #pragma unroll
        for (int nt = 0; nt < 8; nt++) {
            int c0 = cbase + (nt << 3);
            s[nt][0] = (c0     <= grow0) ? s[nt][0] * 0.125f : -1e30f;
            s[nt][1] = (c0 + 1 <= grow0) ? s[nt][1] * 0.125f : -1e30f;
            s[nt][2] = (c0     <= grow1) ? s[nt][2] * 0.125f : -1e30f;
            s[nt][3] = (c0 + 1 <= grow1) ? s[nt][3] * 0.125f : -1e30f;
            mn0 = fmaxf(mn0, fmaxf(s[nt][0], s[nt][1]));
            mn1 = fmaxf(mn1, fmaxf(s[nt][2], s[nt][3]));
        }
        mn0 = fmaxf(mn0, __shfl_xor_sync(0xffffffffu, mn0, 1));
        mn0 = fmaxf(mn0, __shfl_xor_sync(0xffffffffu, mn0, 2));
        mn1 = fmaxf(mn1, __shfl_xor_sync(0xffffffffu, mn1, 1));
        mn1 = fmaxf(mn1, __shfl_xor_sync(0xffffffffu, mn1, 2));

        const float corr0 = __expf(m0 - mn0);
        const float corr1 = __expf(m1 - mn1);
        m0 = mn0; m1 = mn1;

        float rs0 = 0.f, rs1 = 0.f;
        #pragma unroll
        for (int nt = 0; nt < 8; nt++) {
            float p0 = __expf(s[nt][0] - m0);
            float p1 = __expf(s[nt][1] - m0);
            float p2 = __expf(s[nt][2] - m1);
            float p3 = __expf(s[nt][3] - m1);
            rs0 += p0 + p1; rs1 += p2 + p3;
            int pc = (nt << 3) + ((lane & 3) << 1);
            Ps[ar    ][pc]     = f2tff(p0);
            Ps[ar    ][pc + 1] = f2tff(p1);
            Ps[ar + 8][pc]     = f2tff(p2);
            Ps[ar + 8][pc + 1] = f2tff(p3);
        }
        rs0 += __shfl_xor_sync(0xffffffffu, rs0, 1);
        rs0 += __shfl_xor_sync(0xffffffffu, rs0, 2);
        rs1 += __shfl_xor_sync(0xffffffffu, rs1, 1);
        rs1 += __shfl_xor_sync(0xffffffffu, rs1, 2);
        l0 = l0 * corr0 + rs0;
        l1 = l1 * corr1 + rs1;
        #pragma unroll
        for (int nt = 0; nt < 8; nt++) {
            o[nt][0] *= corr0; o[nt][1] *= corr0;
            o[nt][2] *= corr1; o[nt][3] *= corr1;
        }
        __syncwarp();   // Ps visible to whole warp (P region is warp-private)

        // O += P @ V  (warp: 16 rows x 64 d cols, k = 64 kv)
        #pragma unroll
        for (int kk = 0; kk < 64; kk += 8) {
            uint32_t a[4];
            a[0] = __float_as_uint(Ps[ar    ][kk + (lane & 3)    ]);
            a[1] = __float_as_uint(Ps[ar + 8][kk + (lane & 3)    ]);
            a[2] = __float_as_uint(Ps[ar    ][kk + (lane & 3) + 4]);
            a[3] = __float_as_uint(Ps[ar + 8][kk + (lane & 3) + 4]);
            #pragma unroll
            for (int nt = 0; nt < 8; nt++) {
                uint32_t bfr[2];
                int n = (nt << 3) + (lane >> 2);
                bfr[0] = __float_as_uint(Vs[kk + (lane & 3)    ][n]);
                bfr[1] = __float_as_uint(Vs[kk + (lane & 3) + 4][n]);
                mma8(o[nt], a, bfr);
            }
        }
    }

    // Write (tf32-rounded; consumed only by proj GEMM): out[b, q0+row, h*64+col]
    const float inv0 = 1.0f / l0;
    const float inv1 = 1.0f / l1;
    #pragma unroll
    for (int nt = 0; nt < 8; nt++) {
        int col = h * HD + (nt << 3) + ((lane & 3) << 1);
        size_t base0 = (size_t)(b * SEQ + q0 + ar) * DIM + col;
        size_t base1 = base0 + (size_t)8 * DIM;
        outp[base0]     = f2tff(o[nt][0] * inv0);
        outp[base0 + 1] = f2tff(o[nt][1] * inv0);
        outp[base1]     = f2tff(o[nt][2] * inv1);
        outp[base1 + 1] = f2tff(o[nt][3] * inv1);
    }
}

// ---------------------------------------------------------------------------
// Launch
// ---------------------------------------------------------------------------
extern "C" void kernel_launch(void* const* d_in, const int* in_sizes, int n_in,
                              void* d_out, int out_size)
{
    const float* x      = (const float*)d_in[0];
    const float* w_qkv  = (const float*)d_in[1];
    const float* b_qkv  = (const float*)d_in[2];
    const float* w_proj = (const float*)d_in[3];
    const float* b_proj = (const float*)d_in[4];
    const float* g1     = (const float*)d_in[5];
    const float* beta1  = (const float*)d_in[6];
    const float* g2     = (const float*)d_in[7];
    const float* beta2  = (const float*)d_in[8];
    const float* w_fc1  = (const float*)d_in[9];
    const float* b_fc1  = (const float*)d_in[10];
    const float* w_fc2  = (const float*)d_in[11];
    const float* b_fc2  = (const float*)d_in[12];
    float* out = (float*)d_out;

    float *h, *qkv, *attn, *x1, *mid, *wqkv, *wproj, *wfc1, *wfc2;
    cudaGetSymbolAddress((void**)&h,     g_h);
    cudaGetSymbolAddress((void**)&qkv,   g_qkv);
    cudaGetSymbolAddress((void**)&attn,  g_attn);
    cudaGetSymbolAddress((void**)&x1,    g_x1);
    cudaGetSymbolAddress((void**)&mid,   g_mid);
    cudaGetSymbolAddress((void**)&wqkv,  g_wqkv);
    cudaGetSymbolAddress((void**)&wproj, g_wproj);
    cudaGetSymbolAddress((void**)&wfc1,  g_wfc1);
    cudaGetSymbolAddress((void**)&wfc2,  g_wfc2);

    const int ATTN_SMEM = 384 * ASTRIDE * (int)sizeof(float);  // ~102 KB
    cudaFuncSetAttribute(attn_kernel, cudaFuncAttributeMaxDynamicSharedMemorySize, ATTN_SMEM);
    cudaFuncSetAttribute(gemm_kernel<false, false, true>,
                         cudaFuncAttributeMaxDynamicSharedMemorySize, GEMM_SMEM);
    cudaFuncSetAttribute(gemm_kernel<false, true, false>,
                         cudaFuncAttributeMaxDynamicSharedMemorySize, GEMM_SMEM);
    cudaFuncSetAttribute(gemm_kernel<true, false, true>,
                         cudaFuncAttributeMaxDynamicSharedMemorySize, GEMM_SMEM);

    // 0) Pre-round weights to tf32 (once per call; ~12 us)
    round_copy<<<(DIM * 3 * DIM) / 1024, 256>>>(w_qkv,  wqkv);
    round_copy<<<(DIM * DIM)     / 1024, 256>>>(w_proj, wproj);
    round_copy<<<(DIM * HIDDEN)  / 1024, 256>>>(w_fc1,  wfc1);
    round_copy<<<(HIDDEN * DIM)  / 1024, 256>>>(w_fc2,  wfc2);

    // 1) LN1 (rounded output)
    ln_kernel<<<NTOK, 256>>>(x, g1, beta1, h);
    // 2) QKV = h @ w_qkv + b_qkv        [4096,1024]x[1024,3072], rounded out
    gemm_kernel<false, false, true><<<dim3(3 * DIM / 128, NTOK / 128), 256, GEMM_SMEM>>>(
        h, wqkv, b_qkv, nullptr, qkv, NTOK, 3 * DIM, DIM);
    // 3) Causal MHA (rounded output)
    attn_kernel<<<dim3(SEQ / 128, NH, 2), 256, ATTN_SMEM>>>(qkv, attn);
    // 4) x1 = x + attn @ w_proj + b_proj (full fp32 residual)
    gemm_kernel<false, true, false><<<dim3(DIM / 128, NTOK / 128), 256, GEMM_SMEM>>>(
        attn, wproj, b_proj, x, x1, NTOK, DIM, DIM);
    // 5) LN2 (rounded output)
    ln_kernel<<<NTOK, 256>>>(x1, g2, beta2, h);
    // 6) mid = gelu(h @ w_fc1 + b_fc1)   [4096,1024]x[1024,4096], rounded out
    gemm_kernel<true, false, true><<<dim3(HIDDEN / 128, NTOK / 128), 256, GEMM_SMEM>>>(
        h, wfc1, b_fc1, nullptr, mid, NTOK, HIDDEN, DIM);
    // 7) out = x1 + mid @ w_fc2 + b_fc2  [4096,4096]x[4096,1024], full fp32
    gemm_kernel<false, true, false><<<dim3(DIM / 128, NTOK / 128), 256, GEMM_SMEM>>>(
        mid, wfc2, b_fc2, x1, out, NTOK, DIM, HIDDEN);
}

// round 10
// speedup vs baseline: 1.1430x; 1.0960x over previous
#include <cuda_runtime.h>
#include <cuda_bf16.h>
#include <cstdint>
#include <math.h>

// ---------------------------------------------------------------------------
// Transformer block: LN1 -> QKV -> causal MHA -> proj(+res) -> LN2 -> FC1+GELU
//                    -> FC2(+res).  B=2, S=2048, D=1024, H=16, hd=64, FF=4096.
// TF32 mma.sync (m16n8k8) everywhere, fp32 accumulation.
// R10: GEMM warp tile 32x64 -> 64x64 (4 warps / 128 threads per CTA), raising
// MMA:LDS density from 16:24 to 32:32 per k-step. 2-stage cp.async kept.
// ---------------------------------------------------------------------------

#define DIM    1024
#define HIDDEN 4096
#define SEQ    2048
#define NTOK   4096   // B * S
#define NH     16
#define HD     64

// Scratch (allocation-free rule: device globals)
__device__ float g_h    [NTOK * DIM];       // LN output (tf32-rounded)
__device__ float g_qkv  [NTOK * 3 * DIM];   // tf32-rounded
__device__ float g_attn [NTOK * DIM];       // tf32-rounded
__device__ float g_x1   [NTOK * DIM];       // full fp32 (residual stream)
__device__ float g_mid  [NTOK * HIDDEN];    // tf32-rounded
// tf32-rounded weight copies
__device__ float g_wqkv [DIM * 3 * DIM];
__device__ float g_wproj[DIM * DIM];
__device__ float g_wfc1 [DIM * HIDDEN];
__device__ float g_wfc2 [HIDDEN * DIM];

// ---------------------------------------------------------------------------
// TF32 helpers
// ---------------------------------------------------------------------------
__device__ __forceinline__ uint32_t f2tf(float x) {
    uint32_t u;
    asm("cvt.rna.tf32.f32 %0, %1;" : "=r"(u) : "f"(x));
    return u;
}
__device__ __forceinline__ float f2tff(float x) { return __uint_as_float(f2tf(x)); }

__device__ __forceinline__ void mma8(float c[4], const uint32_t a[4], const uint32_t b[2]) {
    asm volatile(
        "mma.sync.aligned.m16n8k8.row.col.f32.tf32.tf32.f32 "
        "{%0,%1,%2,%3}, {%4,%5,%6,%7}, {%8,%9}, {%0,%1,%2,%3};"
        : "+f"(c[0]), "+f"(c[1]), "+f"(c[2]), "+f"(c[3])
        : "r"(a[0]), "r"(a[1]), "r"(a[2]), "r"(a[3]), "r"(b[0]), "r"(b[1]));
}

__device__ __forceinline__ void cpa16(uint32_t dst, const void* src) {
    asm volatile("cp.async.cg.shared.global [%0], [%1], 16;" :: "r"(dst), "l"(src) : "memory");
}
#define CP_COMMIT() asm volatile("cp.async.commit_group;" ::: "memory")
#define CP_WAIT1()  asm volatile("cp.async.wait_group 1;" ::: "memory")
#define CP_WAIT0()  asm volatile("cp.async.wait_group 0;" ::: "memory")

__device__ __forceinline__ float gelu_f(float v) {
    return 0.5f * v * (1.0f + erff(v * 0.70710678118654752440f));
}

// ---------------------------------------------------------------------------
// Elementwise tf32 round-copy (for weights), float4 per thread
// ---------------------------------------------------------------------------
__global__ __launch_bounds__(256) void round_copy(
    const float* __restrict__ s, float* __restrict__ d)
{
    int i = (blockIdx.x * 256 + threadIdx.x) << 2;
    float4 v = *(const float4*)(s + i);
    v.x = f2tff(v.x); v.y = f2tff(v.y); v.z = f2tff(v.z); v.w = f2tff(v.w);
    *(float4*)(d + i) = v;
}

// ---------------------------------------------------------------------------
// LayerNorm: one 256-thread block per row of 1024.  Output tf32-rounded
// (it is consumed only as a GEMM A operand).
// ---------------------------------------------------------------------------
__global__ __launch_bounds__(256) void ln_kernel(
    const float* __restrict__ x, const float* __restrict__ g,
    const float* __restrict__ be, float* __restrict__ out)
{
    const int row = blockIdx.x;
    const int tid = threadIdx.x;
    const float4 v = *(const float4*)(x + (size_t)row * DIM + (tid << 2));
    float s = v.x + v.y + v.z + v.w;
    float q = v.x * v.x + v.y * v.y + v.z * v.z + v.w * v.w;
    #pragma unroll
    for (int off = 16; off; off >>= 1) {
        s += __shfl_xor_sync(0xffffffffu, s, off);
        q += __shfl_xor_sync(0xffffffffu, q, off);
    }
    __shared__ float ss[8], sq[8];
    if ((tid & 31) == 0) { ss[tid >> 5] = s; sq[tid >> 5] = q; }
    __syncthreads();
    float ts = 0.f, tq = 0.f;
    #pragma unroll
    for (int i = 0; i < 8; i++) { ts += ss[i]; tq += sq[i]; }
    const float mu  = ts * (1.0f / DIM);
    const float var = tq * (1.0f / DIM) - mu * mu;
    const float inv = rsqrtf(var + 1e-5f);
    const float4 gg = *(const float4*)(g  + (tid << 2));
    const float4 bb = *(const float4*)(be + (tid << 2));
    float4 r;
    r.x = f2tff((v.x - mu) * inv * gg.x + bb.x);
    r.y = f2tff((v.y - mu) * inv * gg.y + bb.y);
    r.z = f2tff((v.z - mu) * inv * gg.z + bb.z);
    r.w = f2tff((v.w - mu) * inv * gg.w + bb.w);
    *(float4*)(out + (size_t)row * DIM + (tid << 2)) = r;
}

// ---------------------------------------------------------------------------
// GEMM: C[M,N] = A[M,K] @ W[K,N] + bias  (opt GELU, opt +residual, opt tf32-
// round of output).  A and W must already be tf32-rounded in gmem.
// CTA tile 128x128, k-tile 32, cp.async 2-stage double buffer (dynamic smem).
// 4 warps (128 threads) in 2x2; warp tile 64x64 (4x8 m16n8).
// ---------------------------------------------------------------------------
#define AS_ELEMS (128 * 36)   // per stage, +4 pad
#define BS_ELEMS (32 * 132)   // per stage, +4 pad
#define GEMM_SMEM ((2 * AS_ELEMS + 2 * BS_ELEMS) * 4)

template <bool GELU_, bool RESID_, bool ROUND_>
__global__ __launch_bounds__(128, 1) void gemm_kernel(
    const float* __restrict__ A, const float* __restrict__ W,
    const float* __restrict__ bias, const float* __restrict__ R,
    float* __restrict__ C, int M, int N, int K)
{
    extern __shared__ float gsm[];
    float* Asm = gsm;                      // 2 stages of [128][36]
    float* Bsm = gsm + 2 * AS_ELEMS;       // 2 stages of [32][132]

    const int tid  = threadIdx.x;
    const int warp = tid >> 5, lane = tid & 31;
    const int wm = warp >> 1, wn = warp & 1;   // 2x2 warp grid, warp tile 64x64
    const int bm = blockIdx.y << 7, bn = blockIdx.x << 7;

    const uint32_t As_u = (uint32_t)__cvta_generic_to_shared(Asm);
    const uint32_t Bs_u = (uint32_t)__cvta_generic_to_shared(Bsm);

    float acc[4][8][4];
    #pragma unroll
    for (int i = 0; i < 4; i++)
        #pragma unroll
        for (int j = 0; j < 8; j++)
            #pragma unroll
            for (int k = 0; k < 4; k++) acc[i][j][k] = 0.f;

    const int KT = K >> 5;   // number of 32-wide k-tiles

    // Async stage loader: stage s <- k-tile starting at k0 (commits one group)
    auto load_stage = [&](int s, int k0) {
        // A tile 128x32 : 1024 16B chunks, 8 per thread
        #pragma unroll
        for (int i = 0; i < 8; i++) {
            int c  = tid + (i << 7);
            int r  = c >> 3, off = (c & 7) << 2;
            cpa16(As_u + (uint32_t)((s * AS_ELEMS + r * 36 + off) << 2),
                  A + (size_t)(bm + r) * K + k0 + off);
        }
        // B tile 32x128 : 1024 16B chunks, 8 per thread
        #pragma unroll
        for (int i = 0; i < 8; i++) {
            int c  = tid + (i << 7);
            int r  = c >> 5, off = (c & 31) << 2;
            cpa16(Bs_u + (uint32_t)((s * BS_ELEMS + r * 132 + off) << 2),
                  W + (size_t)(k0 + r) * N + bn + off);
        }
        CP_COMMIT();
    };

    load_stage(0, 0);

    for (int kt = 0; kt < KT; kt++) {
        if (kt + 1 < KT) {
            load_stage((kt + 1) & 1, (kt + 1) << 5);
            CP_WAIT1();      // stage kt landed; stage kt+1 still in flight
        } else {
            CP_WAIT0();      // last tile: drain everything
        }
        __syncthreads();

        const float* As_ = Asm + (kt & 1) * AS_ELEMS;
        const float* Bs_ = Bsm + (kt & 1) * BS_ELEMS;

        #pragma unroll
        for (int kk = 0; kk < 32; kk += 8) {
            uint32_t af[4][4], bf[8][2];
            #pragma unroll
            for (int mt = 0; mt < 4; mt++) {
                int r  = (wm << 6) + (mt << 4) + (lane >> 2);
                int cA = kk + (lane & 3);
                af[mt][0] = __float_as_uint(As_[ r      * 36 + cA    ]);
                af[mt][1] = __float_as_uint(As_[(r + 8) * 36 + cA    ]);
                af[mt][2] = __float_as_uint(As_[ r      * 36 + cA + 4]);
                af[mt][3] = __float_as_uint(As_[(r + 8) * 36 + cA + 4]);
            }
            #pragma unroll
            for (int nt = 0; nt < 8; nt++) {
                int cB = (wn << 6) + (nt << 3) + (lane >> 2);
                int rB = kk + (lane & 3);
                bf[nt][0] = __float_as_uint(Bs_[ rB      * 132 + cB]);
                bf[nt][1] = __float_as_uint(Bs_[(rB + 4) * 132 + cB]);
            }
            #pragma unroll
            for (int mt = 0; mt < 4; mt++)
                #pragma unroll
                for (int nt = 0; nt < 8; nt++)
                    mma8(acc[mt][nt], af[mt], bf[nt]);
        }
        __syncthreads();     // stage kt fully consumed before it is overwritten
    }

    // Epilogue
    #pragma unroll
    for (int mt = 0; mt < 4; mt++) {
        #pragma unroll
        for (int nt = 0; nt < 8; nt++) {
            int row0 = bm + (wm << 6) + (mt << 4) + (lane >> 2);
            int col  = bn + (wn << 6) + (nt << 3) + ((lane & 3) << 1);
            const float b0 = __ldg(bias + col);
            const float b1 = __ldg(bias + col + 1);
            #pragma unroll
            for (int half = 0; half < 2; half++) {
                int row = row0 + half * 8;
                float v0 = acc[mt][nt][half * 2 + 0] + b0;
                float v1 = acc[mt][nt][half * 2 + 1] + b1;
                if (GELU_) { v0 = gelu_f(v0); v1 = gelu_f(v1); }
                if (RESID_) {
                    v0 += __ldg(R + (size_t)row * N + col);
                    v1 += __ldg(R + (size_t)row * N + col + 1);
                }
                if (ROUND_) { v0 = f2tff(v0); v1 = f2tff(v1); }
                C[(size_t)row * N + col]     = v0;
                C[(size_t)row * N + col + 1] = v1;
            }
        }
    }
}

// ---------------------------------------------------------------------------
// Causal flash attention.  Inputs (qkv) already tf32-rounded; output rounded.
// grid = (S/128, NH, B); 256 threads = 8 warps, each warp owns 16 query rows.
// KV block = 64. Q/K/V/P staged in dynamic smem (stride 68 floats).
// qkv layout: [B][S][3][NH][HD] fp32.
// ---------------------------------------------------------------------------
#define ASTRIDE 68
__global__ __launch_bounds__(256) void attn_kernel(
    const float* __restrict__ qkv, float* __restrict__ outp)
{
    extern __shared__ float sm[];
    float (*Qs)[ASTRIDE] = (float(*)[ASTRIDE])(sm);                 // 128 rows
    float (*Ks)[ASTRIDE] = (float(*)[ASTRIDE])(sm + 128 * ASTRIDE); //  64 rows
    float (*Vs)[ASTRIDE] = (float(*)[ASTRIDE])(sm + 192 * ASTRIDE); //  64 rows
    float (*Ps)[ASTRIDE] = (float(*)[ASTRIDE])(sm + 256 * ASTRIDE); // 128 rows

    const int qb = blockIdx.x, h = blockIdx.y, b = blockIdx.z;
    const int tid = threadIdx.x, warp = tid >> 5, lane = tid & 31;
    const int q0 = qb << 7;

    // Load Q block (128 x 64) — already tf32
    const float* qbase = qkv + (size_t)(b * SEQ + q0) * (3 * DIM) + h * HD;
    #pragma unroll
    for (int i = 0; i < 8; i++) {
        int idx = tid + (i << 8);
        int r = idx >> 4, c = (idx & 15) << 2;
        *(float4*)&Qs[r][c] = *(const float4*)(qbase + (size_t)r * (3 * DIM) + c);
    }

    float o[8][4];
    #pragma unroll
    for (int i = 0; i < 8; i++)
        #pragma unroll
        for (int j = 0; j < 4; j++) o[i][j] = 0.f;
    float m0 = -1e30f, m1 = -1e30f, l0 = 0.f, l1 = 0.f;

    const int ar = (warp << 4) + (lane >> 2);   // local query row (c0/c1); +8 for c2/c3
    const int nkb = (q0 >> 6) + 2;              // causal KV-block count

    for (int kb = 0; kb < nkb; kb++) {
        __syncthreads();   // previous iteration's K/V fully consumed
        const float* kptr = qkv + (size_t)(b * SEQ + (kb << 6)) * (3 * DIM) + DIM + h * HD;
        #pragma unroll
        for (int i = 0; i < 4; i++) {
            int idx = tid + (i << 8);
            int r = idx >> 4, c = (idx & 15) << 2;
            *(float4*)&Ks[r][c] = *(const float4*)(kptr + (size_t)r * (3 * DIM) + c);
            *(float4*)&Vs[r][c] = *(const float4*)(kptr + (size_t)r * (3 * DIM) + DIM + c);
        }
        __syncthreads();

        // S = Q @ K^T  (warp: 16 rows x 64 kv cols)
        float s[8][4];
        #pragma unroll
        for (int i = 0; i < 8; i++)
            #pragma unroll
            for (int j = 0; j < 4; j++) s[i][j] = 0.f;

        #pragma unroll
        for (int kk = 0; kk < 64; kk += 8) {
            uint32_t a[4];
            a[0] = __float_as_uint(Qs[ar    ][kk + (lane & 3)    ]);
            a[1] = __float_as_uint(Qs[ar + 8][kk + (lane & 3)    ]);
            a[2] = __float_as_uint(Qs[ar    ][kk + (lane & 3) + 4]);
            a[3] = __float_as_uint(Qs[ar + 8][kk + (lane & 3) + 4]);
            #pragma unroll
            for (int nt = 0; nt < 8; nt++) {
                uint32_t bfr[2];
                int n = (nt << 3) + (lane >> 2);
                bfr[0] = __float_as_uint(Ks[n][kk + (lane & 3)    ]);
                bfr[1] = __float_as_uint(Ks[n][kk + (lane & 3) + 4]);
                mma8(s[nt], a, bfr);
            }
        }

        // scale + causal mask + online softmax
        const int grow0 = q0 + ar;
        const int grow1 = grow0 + 8;
        const int cbase = (kb << 6) + ((lane & 3) << 1);
        float mn0 = m0, mn1 = m1;
        #pragma unroll
        for (int nt = 0; nt < 8; nt++) {
            int c0 = cbase + (nt << 3);
            s[nt][0] = (c0     <= grow0) ? s[nt][0] * 0.125f : -1e30f;
            s[nt][1] = (c0 + 1 <= grow0) ? s[nt][1] * 0.125f : -1e30f;
            s[nt][2] = (c0     <= grow1) ? s[nt][2] * 0.125f : -1e30f;
            s[nt][3] = (c0 + 1 <= grow1) ? s[nt][3] * 0.125f : -1e30f;
            mn0 = fmaxf(mn0, fmaxf(s[nt][0], s[nt][1]));
            mn1 = fmaxf(mn1, fmaxf(s[nt][2], s[nt][3]));
        }
        mn0 = fmaxf(mn0, __shfl_xor_sync(0xffffffffu, mn0, 1));
        mn0 = fmaxf(mn0, __shfl_xor_sync(0xffffffffu, mn0, 2));
        mn1 = fmaxf(mn1, __shfl_xor_sync(0xffffffffu, mn1, 1));
        mn1 = fmaxf(mn1, __shfl_xor_sync(0xffffffffu, mn1, 2));

        const float corr0 = __expf(m0 - mn0);
        const float corr1 = __expf(m1 - mn1);
        m0 = mn0; m1 = mn1;

        float rs0 = 0.f, rs1 = 0.f;
        #pragma unroll
        for (int nt = 0; nt < 8; nt++) {
            float p0 = __expf(s[nt][0] - m0);
            float p1 = __expf(s[nt][1] - m0);
            float p2 = __expf(s[nt][2] - m1);
            float p3 = __expf(s[nt][3] - m1);
            rs0 += p0 + p1; rs1 += p2 + p3;
            int pc = (nt << 3) + ((lane & 3) << 1);
            Ps[ar    ][pc]     = f2tff(p0);
            Ps[ar    ][pc + 1] = f2tff(p1);
            Ps[ar + 8][pc]     = f2tff(p2);
            Ps[ar + 8][pc + 1] = f2tff(p3);
        }
        rs0 += __shfl_xor_sync(0xffffffffu, rs0, 1);
        rs0 += __shfl_xor_sync(0xffffffffu, rs0, 2);
        rs1 += __shfl_xor_sync(0xffffffffu, rs1, 1);
        rs1 += __shfl_xor_sync(0xffffffffu, rs1, 2);
        l0 = l0 * corr0 + rs0;
        l1 = l1 * corr1 + rs1;
        #pragma unroll
        for (int nt = 0; nt < 8; nt++) {
            o[nt][0] *= corr0; o[nt][1] *= corr0;
            o[nt][2] *= corr1; o[nt][3] *= corr1;
        }
        __syncwarp();   // Ps visible to whole warp (P region is warp-private)

        // O += P @ V  (warp: 16 rows x 64 d cols, k = 64 kv)
        #pragma unroll
        for (int kk = 0; kk < 64; kk += 8) {
            uint32_t a[4];
            a[0] = __float_as_uint(Ps[ar    ][kk + (lane & 3)    ]);
            a[1] = __float_as_uint(Ps[ar + 8][kk + (lane & 3)    ]);
            a[2] = __float_as_uint(Ps[ar    ][kk + (lane & 3) + 4]);
            a[3] = __float_as_uint(Ps[ar + 8][kk + (lane & 3) + 4]);
            #pragma unroll
            for (int nt = 0; nt < 8; nt++) {
                uint32_t bfr[2];
                int n = (nt << 3) + (lane >> 2);
                bfr[0] = __float_as_uint(Vs[kk + (lane & 3)    ][n]);
                bfr[1] = __float_as_uint(Vs[kk + (lane & 3) + 4][n]);
                mma8(o[nt], a, bfr);
            }
        }
    }

    // Write (tf32-rounded; consumed only by proj GEMM): out[b, q0+row, h*64+col]
    const float inv0 = 1.0f / l0;
    const float inv1 = 1.0f / l1;
    #pragma unroll
    for (int nt = 0; nt < 8; nt++) {
        int col = h * HD + (nt << 3) + ((lane & 3) << 1);
        size_t base0 = (size_t)(b * SEQ + q0 + ar) * DIM + col;
        size_t base1 = base0 + (size_t)8 * DIM;
        outp[base0]     = f2tff(o[nt][0] * inv0);
        outp[base0 + 1] = f2tff(o[nt][1] * inv0);
        outp[base1]     = f2tff(o[nt][2] * inv1);
        outp[base1 + 1] = f2tff(o[nt][3] * inv1);
    }
}

// ---------------------------------------------------------------------------
// Launch
// ---------------------------------------------------------------------------
extern "C" void kernel_launch(void* const* d_in, const int* in_sizes, int n_in,
                              void* d_out, int out_size)
{
    const float* x      = (const float*)d_in[0];
    const float* w_qkv  = (const float*)d_in[1];
    const float* b_qkv  = (const float*)d_in[2];
    const float* w_proj = (const float*)d_in[3];
    const float* b_proj = (const float*)d_in[4];
    const float* g1     = (const float*)d_in[5];
    const float* beta1  = (const float*)d_in[6];
    const float* g2     = (const float*)d_in[7];
    const float* beta2  = (const float*)d_in[8];
    const float* w_fc1  = (const float*)d_in[9];
    const float* b_fc1  = (const float*)d_in[10];
    const float* w_fc2  = (const float*)d_in[11];
    const float* b_fc2  = (const float*)d_in[12];
    float* out = (float*)d_out;

    float *h, *qkv, *attn, *x1, *mid, *wqkv, *wproj, *wfc1, *wfc2;
    cudaGetSymbolAddress((void**)&h,     g_h);
    cudaGetSymbolAddress((void**)&qkv,   g_qkv);
    cudaGetSymbolAddress((void**)&attn,  g_attn);
    cudaGetSymbolAddress((void**)&x1,    g_x1);
    cudaGetSymbolAddress((void**)&mid,   g_mid);
    cudaGetSymbolAddress((void**)&wqkv,  g_wqkv);
    cudaGetSymbolAddress((void**)&wproj, g_wproj);
    cudaGetSymbolAddress((void**)&wfc1,  g_wfc1);
    cudaGetSymbolAddress((void**)&wfc2,  g_wfc2);

    const int ATTN_SMEM = 384 * ASTRIDE * (int)sizeof(float);  // ~102 KB
    cudaFuncSetAttribute(attn_kernel, cudaFuncAttributeMaxDynamicSharedMemorySize, ATTN_SMEM);
    cudaFuncSetAttribute(gemm_kernel<false, false, true>,
                         cudaFuncAttributeMaxDynamicSharedMemorySize, GEMM_SMEM);
    cudaFuncSetAttribute(gemm_kernel<false, true, false>,
                         cudaFuncAttributeMaxDynamicSharedMemorySize, GEMM_SMEM);
    cudaFuncSetAttribute(gemm_kernel<true, false, true>,
                         cudaFuncAttributeMaxDynamicSharedMemorySize, GEMM_SMEM);

    // 0) Pre-round weights to tf32 (once per call; ~25 us)
    round_copy<<<(DIM * 3 * DIM) / 1024, 256>>>(w_qkv,  wqkv);
    round_copy<<<(DIM * DIM)     / 1024, 256>>>(w_proj, wproj);
    round_copy<<<(DIM * HIDDEN)  / 1024, 256>>>(w_fc1,  wfc1);
    round_copy<<<(HIDDEN * DIM)  / 1024, 256>>>(w_fc2,  wfc2);

    // 1) LN1 (rounded output)
    ln_kernel<<<NTOK, 256>>>(x, g1, beta1, h);
    // 2) QKV = h @ w_qkv + b_qkv        [4096,1024]x[1024,3072], rounded out
    gemm_kernel<false, false, true><<<dim3(3 * DIM / 128, NTOK / 128), 128, GEMM_SMEM>>>(
        h, wqkv, b_qkv, nullptr, qkv, NTOK, 3 * DIM, DIM);
    // 3) Causal MHA (rounded output)
    attn_kernel<<<dim3(SEQ / 128, NH, 2), 256, ATTN_SMEM>>>(qkv, attn);
    // 4) x1 = x + attn @ w_proj + b_proj (full fp32 residual)
    gemm_kernel<false, true, false><<<dim3(DIM / 128, NTOK / 128), 128, GEMM_SMEM>>>(
        attn, wproj, b_proj, x, x1, NTOK, DIM, DIM);
    // 5) LN2 (rounded output)
    ln_kernel<<<NTOK, 256>>>(x1, g2, beta2, h);
    // 6) mid = gelu(h @ w_fc1 + b_fc1)   [4096,1024]x[1024,4096], rounded out
    gemm_kernel<true, false, true><<<dim3(HIDDEN / 128, NTOK / 128), 128, GEMM_SMEM>>>(
        h, wfc1, b_fc1, nullptr, mid, NTOK, HIDDEN, DIM);
    // 7) out = x1 + mid @ w_fc2 + b_fc2  [4096,4096]x[4096,1024], full fp32
    gemm_kernel<false, true, false><<<dim3(DIM / 128, NTOK / 128), 128, GEMM_SMEM>>>(
        mid, wfc2, b_fc2, x1, out, NTOK, DIM, HIDDEN);
}

// round 11
// speedup vs baseline: 1.2376x; 1.0828x over previous
#include <cuda_runtime.h>
#include <cuda_bf16.h>
#include <cstdint>
#include <math.h>

// ---------------------------------------------------------------------------
// Transformer block: LN1 -> QKV -> causal MHA -> proj(+res) -> LN2 -> FC1+GELU
//                    -> FC2(+res).  B=2, S=2048, D=1024, H=16, hd=64, FF=4096.
// TF32 mma.sync (m16n8k8), fp32 accumulation.
// R11: weights pre-relayouted into fragment-major tiles (B loads = 4 LDS.128
// per k-step), 3-stage cp.async pipeline with a single barrier per k-tile.
// ---------------------------------------------------------------------------

#define DIM    1024
#define HIDDEN 4096
#define SEQ    2048
#define NTOK   4096   // B * S
#define NH     16
#define HD     64

// Scratch (allocation-free rule: device globals)
__device__ float g_h    [NTOK * DIM];       // LN output (tf32-rounded)
__device__ float g_qkv  [NTOK * 3 * DIM];   // tf32-rounded
__device__ float g_attn [NTOK * DIM];       // tf32-rounded
__device__ float g_x1   [NTOK * DIM];       // full fp32 (residual stream)
__device__ float g_mid  [NTOK * HIDDEN];    // tf32-rounded
// tf32-rounded + fragment-major re-tiled weights
__device__ float g_wqkv [DIM * 3 * DIM];
__device__ float g_wproj[DIM * DIM];
__device__ float g_wfc1 [DIM * HIDDEN];
__device__ float g_wfc2 [HIDDEN * DIM];

// ---------------------------------------------------------------------------
// TF32 helpers
// ---------------------------------------------------------------------------
__device__ __forceinline__ uint32_t f2tf(float x) {
    uint32_t u;
    asm("cvt.rna.tf32.f32 %0, %1;" : "=r"(u) : "f"(x));
    return u;
}
__device__ __forceinline__ float f2tff(float x) { return __uint_as_float(f2tf(x)); }

__device__ __forceinline__ void mma8(float c[4], const uint32_t a[4], const uint32_t b[2]) {
    asm volatile(
        "mma.sync.aligned.m16n8k8.row.col.f32.tf32.tf32.f32 "
        "{%0,%1,%2,%3}, {%4,%5,%6,%7}, {%8,%9}, {%0,%1,%2,%3};"
        : "+f"(c[0]), "+f"(c[1]), "+f"(c[2]), "+f"(c[3])
        : "r"(a[0]), "r"(a[1]), "r"(a[2]), "r"(a[3]), "r"(b[0]), "r"(b[1]));
}

__device__ __forceinline__ void cpa16(uint32_t dst, const void* src) {
    asm volatile("cp.async.cg.shared.global [%0], [%1], 16;" :: "r"(dst), "l"(src) : "memory");
}
#define CP_COMMIT() asm volatile("cp.async.commit_group;" ::: "memory")
#define CP_WAIT1()  asm volatile("cp.async.wait_group 1;" ::: "memory")

__device__ __forceinline__ float gelu_f(float v) {
    return 0.5f * v * (1.0f + erff(v * 0.70710678118654752440f));
}

// ---------------------------------------------------------------------------
// Weight relayout: W[K][N] row-major -> fragment-major tiles.
// Tile (nb, kt) = 32x128 block, stored as 4096 contiguous floats indexed
// [kk(4)][wn(2)][j(4)][lane(32)][e(4)], where for warp-half wn, k-step kk:
//   e=0: (k = kt*32+kk*8+(lane&3)   , n = nb*128+wn*64+(2j  )*8+(lane>>2))
//   e=1: (k+4, n), e=2: (k, n+8), e=3: (k+4, n+8)
// One thread produces one float4 (gathers 4 strided floats, tf32-rounds).
// ---------------------------------------------------------------------------
__global__ __launch_bounds__(256) void relayout_w(
    const float* __restrict__ W, float* __restrict__ Wt, int N, int K)
{
    int t    = blockIdx.x * 256 + threadIdx.x;   // one float4 per thread
    int lane = t & 31;
    int j    = (t >> 5) & 3;
    int wn   = (t >> 7) & 1;
    int kk   = (t >> 8) & 3;
    int tile = t >> 10;
    int KT   = K >> 5;
    int kt   = tile % KT;
    int nb   = tile / KT;
    int k0   = kt * 32 + kk * 8 + (lane & 3);
    int n0   = nb * 128 + wn * 64 + (j << 4) + (lane >> 2);
    float4 v;
    v.x = f2tff(W[(size_t)(k0    ) * N + n0    ]);
    v.y = f2tff(W[(size_t)(k0 + 4) * N + n0    ]);
    v.z = f2tff(W[(size_t)(k0    ) * N + n0 + 8]);
    v.w = f2tff(W[(size_t)(k0 + 4) * N + n0 + 8]);
    *(float4*)(Wt + ((size_t)t << 2)) = v;
}

// ---------------------------------------------------------------------------
// LayerNorm: one 256-thread block per row of 1024.  Output tf32-rounded.
// ---------------------------------------------------------------------------
__global__ __launch_bounds__(256) void ln_kernel(
    const float* __restrict__ x, const float* __restrict__ g,
    const float* __restrict__ be, float* __restrict__ out)
{
    const int row = blockIdx.x;
    const int tid = threadIdx.x;
    const float4 v = *(const float4*)(x + (size_t)row * DIM + (tid << 2));
    float s = v.x + v.y + v.z + v.w;
    float q = v.x * v.x + v.y * v.y + v.z * v.z + v.w * v.w;
    #pragma unroll
    for (int off = 16; off; off >>= 1) {
        s += __shfl_xor_sync(0xffffffffu, s, off);
        q += __shfl_xor_sync(0xffffffffu, q, off);
    }
    __shared__ float ss[8], sq[8];
    if ((tid & 31) == 0) { ss[tid >> 5] = s; sq[tid >> 5] = q; }
    __syncthreads();
    float ts = 0.f, tq = 0.f;
    #pragma unroll
    for (int i = 0; i < 8; i++) { ts += ss[i]; tq += sq[i]; }
    const float mu  = ts * (1.0f / DIM);
    const float var = tq * (1.0f / DIM) - mu * mu;
    const float inv = rsqrtf(var + 1e-5f);
    const float4 gg = *(const float4*)(g  + (tid << 2));
    const float4 bb = *(const float4*)(be + (tid << 2));
    float4 r;
    r.x = f2tff((v.x - mu) * inv * gg.x + bb.x);
    r.y = f2tff((v.y - mu) * inv * gg.y + bb.y);
    r.z = f2tff((v.z - mu) * inv * gg.z + bb.z);
    r.w = f2tff((v.w - mu) * inv * gg.w + bb.w);
    *(float4*)(out + (size_t)row * DIM + (tid << 2)) = r;
}

// ---------------------------------------------------------------------------
// GEMM: C[M,N] = A[M,K] @ W[K,N] + bias  (opt GELU / +residual / tf32-round).
// A row-major tf32-rounded; W in fragment-major tile layout (relayout_w).
// CTA tile 128x128, k-tile 32, 3-stage cp.async pipeline, ONE barrier/k-tile.
// 4 warps (2x2), warp tile 64x64 (4x8 m16n8).
// ---------------------------------------------------------------------------
#define AS_ELEMS (128 * 36)   // A stage: +4 pad per row
#define BS_ELEMS 4096         // B stage: exact fragment-major tile
#define GEMM_SMEM (3 * (AS_ELEMS + BS_ELEMS) * 4)   // 104448 B

template <bool GELU_, bool RESID_, bool ROUND_>
__global__ __launch_bounds__(128, 1) void gemm_kernel(
    const float* __restrict__ A, const float* __restrict__ W,
    const float* __restrict__ bias, const float* __restrict__ R,
    float* __restrict__ C, int M, int N, int K)
{
    extern __shared__ float gsm[];
    float* Asm = gsm;                      // 3 stages of [128][36]
    float* Bsm = gsm + 3 * AS_ELEMS;       // 3 stages of 4096

    const int tid  = threadIdx.x;
    const int warp = tid >> 5, lane = tid & 31;
    const int wm = warp >> 1, wn = warp & 1;   // 2x2 warp grid, 64x64 tiles
    const int bm = blockIdx.y << 7;
    const int KT = K >> 5;

    const uint32_t As_u = (uint32_t)__cvta_generic_to_shared(Asm);
    const uint32_t Bs_u = (uint32_t)__cvta_generic_to_shared(Bsm);

    float acc[4][8][4];
    #pragma unroll
    for (int i = 0; i < 4; i++)
        #pragma unroll
        for (int j = 0; j < 8; j++)
            #pragma unroll
            for (int k = 0; k < 4; k++) acc[i][j][k] = 0.f;

    // Stage loader (no commit): stage s <- k-tile kt_
    auto load_stage = [&](int s, int kt_) {
        // A tile 128x32 : 1024 16B chunks, 8 per thread
        #pragma unroll
        for (int i = 0; i < 8; i++) {
            int c  = tid + (i << 7);
            int r  = c >> 3, off = (c & 7) << 2;
            cpa16(As_u + (uint32_t)((s * AS_ELEMS + r * 36 + off) << 2),
                  A + (size_t)(bm + r) * K + (kt_ << 5) + off);
        }
        // B tile: contiguous 16KB fragment-major block
        const float* src = W + ((size_t)blockIdx.x * KT + kt_) * 4096;
        #pragma unroll
        for (int i = 0; i < 8; i++) {
            int c = tid + (i << 7);
            cpa16(Bs_u + (uint32_t)((s * BS_ELEMS + (c << 2)) << 2),
                  src + (c << 2));
        }
    };

    load_stage(0, 0); CP_COMMIT();
    load_stage(1, 1); CP_COMMIT();

    for (int kt = 0; kt < KT; kt++) {
        CP_WAIT1();          // stage kt resident (<=1 newer group in flight)
        __syncthreads();     // all warps: stage kt visible, stage kt-1 consumed
        if (kt + 2 < KT) load_stage((kt + 2) % 3, kt + 2);
        CP_COMMIT();         // may be an empty group near the tail

        const float* As_ = Asm + (kt % 3) * AS_ELEMS;
        const float* Bs_ = Bsm + (kt % 3) * BS_ELEMS;

        #pragma unroll
        for (int kki = 0; kki < 4; kki++) {
            uint32_t af[4][4], bf[8][2];
            #pragma unroll
            for (int mt = 0; mt < 4; mt++) {
                int r  = (wm << 6) + (mt << 4) + (lane >> 2);
                int cA = (kki << 3) + (lane & 3);
                af[mt][0] = __float_as_uint(As_[ r      * 36 + cA    ]);
                af[mt][1] = __float_as_uint(As_[(r + 8) * 36 + cA    ]);
                af[mt][2] = __float_as_uint(As_[ r      * 36 + cA + 4]);
                af[mt][3] = __float_as_uint(As_[(r + 8) * 36 + cA + 4]);
            }
            #pragma unroll
            for (int j = 0; j < 4; j++) {
                float4 q = *(const float4*)(Bs_ +
                    (size_t)((((kki << 1) + wn) * 4 + j) * 32 + lane) * 4);
                bf[2 * j    ][0] = __float_as_uint(q.x);
                bf[2 * j    ][1] = __float_as_uint(q.y);
                bf[2 * j + 1][0] = __float_as_uint(q.z);
                bf[2 * j + 1][1] = __float_as_uint(q.w);
            }
            #pragma unroll
            for (int mt = 0; mt < 4; mt++)
                #pragma unroll
                for (int nt = 0; nt < 8; nt++)
                    mma8(acc[mt][nt], af[mt], bf[nt]);
        }
    }

    // Epilogue
    const int bn = blockIdx.x << 7;
    #pragma unroll
    for (int mt = 0; mt < 4; mt++) {
        #pragma unroll
        for (int nt = 0; nt < 8; nt++) {
            int row0 = bm + (wm << 6) + (mt << 4) + (lane >> 2);
            int col  = bn + (wn << 6) + (nt << 3) + ((lane & 3) << 1);
            const float b0 = __ldg(bias + col);
            const float b1 = __ldg(bias + col + 1);
            #pragma unroll
            for (int half = 0; half < 2; half++) {
                int row = row0 + half * 8;
                float v0 = acc[mt][nt][half * 2 + 0] + b0;
                float v1 = acc[mt][nt][half * 2 + 1] + b1;
                if (GELU_) { v0 = gelu_f(v0); v1 = gelu_f(v1); }
                if (RESID_) {
                    v0 += __ldg(R + (size_t)row * N + col);
                    v1 += __ldg(R + (size_t)row * N + col + 1);
                }
                if (ROUND_) { v0 = f2tff(v0); v1 = f2tff(v1); }
                C[(size_t)row * N + col]     = v0;
                C[(size_t)row * N + col + 1] = v1;
            }
        }
    }
}

// ---------------------------------------------------------------------------
// Causal flash attention.  Inputs (qkv) already tf32-rounded; output rounded.
// grid = (S/128, NH, B); 256 threads = 8 warps, each warp owns 16 query rows.
// KV block = 64. Q/K/V/P staged in dynamic smem (stride 68 floats).
// qkv layout: [B][S][3][NH][HD] fp32.
// ---------------------------------------------------------------------------
#define ASTRIDE 68
__global__ __launch_bounds__(256) void attn_kernel(
    const float* __restrict__ qkv, float* __restrict__ outp)
{
    extern __shared__ float sm[];
    float (*Qs)[ASTRIDE] = (float(*)[ASTRIDE])(sm);                 // 128 rows
    float (*Ks)[ASTRIDE] = (float(*)[ASTRIDE])(sm + 128 * ASTRIDE); //  64 rows
    float (*Vs)[ASTRIDE] = (float(*)[ASTRIDE])(sm + 192 * ASTRIDE); //  64 rows
    float (*Ps)[ASTRIDE] = (float(*)[ASTRIDE])(sm + 256 * ASTRIDE); // 128 rows

    const int qb = blockIdx.x, h = blockIdx.y, b = blockIdx.z;
    const int tid = threadIdx.x, warp = tid >> 5, lane = tid & 31;
    const int q0 = qb << 7;

    // Load Q block (128 x 64) — already tf32
    const float* qbase = qkv + (size_t)(b * SEQ + q0) * (3 * DIM) + h * HD;
    #pragma unroll
    for (int i = 0; i < 8; i++) {
        int idx = tid + (i << 8);
        int r = idx >> 4, c = (idx & 15) << 2;
        *(float4*)&Qs[r][c] = *(const float4*)(qbase + (size_t)r * (3 * DIM) + c);
    }

    float o[8][4];
    #pragma unroll
    for (int i = 0; i < 8; i++)
        #pragma unroll
        for (int j = 0; j < 4; j++) o[i][j] = 0.f;
    float m0 = -1e30f, m1 = -1e30f, l0 = 0.f, l1 = 0.f;

    const int ar = (warp << 4) + (lane >> 2);   // local query row (c0/c1); +8 for c2/c3
    const int nkb = (q0 >> 6) + 2;              // causal KV-block count

    for (int kb = 0; kb < nkb; kb++) {
        __syncthreads();   // previous iteration's K/V fully consumed
        const float* kptr = qkv + (size_t)(b * SEQ + (kb << 6)) * (3 * DIM) + DIM + h * HD;
        #pragma unroll
        for (int i = 0; i < 4; i++) {
            int idx = tid + (i << 8);
            int r = idx >> 4, c = (idx & 15) << 2;
            *(float4*)&Ks[r][c] = *(const float4*)(kptr + (size_t)r * (3 * DIM) + c);
            *(float4*)&Vs[r][c] = *(const float4*)(kptr + (size_t)r * (3 * DIM) + DIM + c);
        }
        __syncthreads();

        // S = Q @ K^T  (warp: 16 rows x 64 kv cols)
        float s[8][4];
        #pragma unroll
        for (int i = 0; i < 8; i++)
            #pragma unroll
            for (int j = 0; j < 4; j++) s[i][j] = 0.f;

        #pragma unroll
        for (int kk = 0; kk < 64; kk += 8) {
            uint32_t a[4];
            a[0] = __float_as_uint(Qs[ar    ][kk + (lane & 3)    ]);
            a[1] = __float_as_uint(Qs[ar + 8][kk + (lane & 3)    ]);
            a[2] = __float_as_uint(Qs[ar    ][kk + (lane & 3) + 4]);
            a[3] = __float_as_uint(Qs[ar + 8][kk + (lane & 3) + 4]);
            #pragma unroll
            for (int nt = 0; nt < 8; nt++) {
                uint32_t bfr[2];
                int n = (nt << 3) + (lane >> 2);
                bfr[0] = __float_as_uint(Ks[n][kk + (lane & 3)    ]);
                bfr[1] = __float_as_uint(Ks[n][kk + (lane & 3) + 4]);
                mma8(s[nt], a, bfr);
            }
        }

        // scale + causal mask + online softmax
        const int grow0 = q0 + ar;
        const int grow1 = grow0 + 8;
        const int cbase = (kb << 6) + ((lane & 3) << 1);
        float mn0 = m0, mn1 = m1;
        #pragma unroll
        for (int nt = 0; nt < 8; nt++) {
            int c0 = cbase + (nt << 3);
            s[nt][0] = (c0     <= grow0) ? s[nt][0] * 0.125f : -1e30f;
            s[nt][1] = (c0 + 1 <= grow0) ? s[nt][1] * 0.125f : -1e30f;
            s[nt][2] = (c0     <= grow1) ? s[nt][2] * 0.125f : -1e30f;
            s[nt][3] = (c0 + 1 <= grow1) ? s[nt][3] * 0.125f : -1e30f;
            mn0 = fmaxf(mn0, fmaxf(s[nt][0], s[nt][1]));
            mn1 = fmaxf(mn1, fmaxf(s[nt][2], s[nt][3]));
        }
        mn0 = fmaxf(mn0, __shfl_xor_sync(0xffffffffu, mn0, 1));
        mn0 = fmaxf(mn0, __shfl_xor_sync(0xffffffffu, mn0, 2));
        mn1 = fmaxf(mn1, __shfl_xor_sync(0xffffffffu, mn1, 1));
        mn1 = fmaxf(mn1, __shfl_xor_sync(0xffffffffu, mn1, 2));

        const float corr0 = __expf(m0 - mn0);
        const float corr1 = __expf(m1 - mn1);
        m0 = mn0; m1 = mn1;

        float rs0 = 0.f, rs1 = 0.f;
        #pragma unroll
        for (int nt = 0; nt < 8; nt++) {
            float p0 = __expf(s[nt][0] - m0);
            float p1 = __expf(s[nt][1] - m0);
            float p2 = __expf(s[nt][2] - m1);
            float p3 = __expf(s[nt][3] - m1);
            rs0 += p0 + p1; rs1 += p2 + p3;
            int pc = (nt << 3) + ((lane & 3) << 1);
            Ps[ar    ][pc]     = f2tff(p0);
            Ps[ar    ][pc + 1] = f2tff(p1);
            Ps[ar + 8][pc]     = f2tff(p2);
            Ps[ar + 8][pc + 1] = f2tff(p3);
        }
        rs0 += __shfl_xor_sync(0xffffffffu, rs0, 1);
        rs0 += __shfl_xor_sync(0xffffffffu, rs0, 2);
        rs1 += __shfl_xor_sync(0xffffffffu, rs1, 1);
        rs1 += __shfl_xor_sync(0xffffffffu, rs1, 2);
        l0 = l0 * corr0 + rs0;
        l1 = l1 * corr1 + rs1;
        #pragma unroll
        for (int nt = 0; nt < 8; nt++) {
            o[nt][0] *= corr0; o[nt][1] *= corr0;
            o[nt][2] *= corr1; o[nt][3] *= corr1;
        }
        __syncwarp();   // Ps visible to whole warp (P region is warp-private)

        // O += P @ V  (warp: 16 rows x 64 d cols, k = 64 kv)
        #pragma unroll
        for (int kk = 0; kk < 64; kk += 8) {
            uint32_t a[4];
            a[0] = __float_as_uint(Ps[ar    ][kk + (lane & 3)    ]);
            a[1] = __float_as_uint(Ps[ar + 8][kk + (lane & 3)    ]);
            a[2] = __float_as_uint(Ps[ar    ][kk + (lane & 3) + 4]);
            a[3] = __float_as_uint(Ps[ar + 8][kk + (lane & 3) + 4]);
            #pragma unroll
            for (int nt = 0; nt < 8; nt++) {
                uint32_t bfr[2];
                int n = (nt << 3) + (lane >> 2);
                bfr[0] = __float_as_uint(Vs[kk + (lane & 3)    ][n]);
                bfr[1] = __float_as_uint(Vs[kk + (lane & 3) + 4][n]);
                mma8(o[nt], a, bfr);
            }
        }
    }

    // Write (tf32-rounded; consumed only by proj GEMM): out[b, q0+row, h*64+col]
    const float inv0 = 1.0f / l0;
    const float inv1 = 1.0f / l1;
    #pragma unroll
    for (int nt = 0; nt < 8; nt++) {
        int col = h * HD + (nt << 3) + ((lane & 3) << 1);
        size_t base0 = (size_t)(b * SEQ + q0 + ar) * DIM + col;
        size_t base1 = base0 + (size_t)8 * DIM;
        outp[base0]     = f2tff(o[nt][0] * inv0);
        outp[base0 + 1] = f2tff(o[nt][1] * inv0);
        outp[base1]     = f2tff(o[nt][2] * inv1);
        outp[base1 + 1] = f2tff(o[nt][3] * inv1);
    }
}

// ---------------------------------------------------------------------------
// Launch
// ---------------------------------------------------------------------------
extern "C" void kernel_launch(void* const* d_in, const int* in_sizes, int n_in,
                              void* d_out, int out_size)
{
    const float* x      = (const float*)d_in[0];
    const float* w_qkv  = (const float*)d_in[1];
    const float* b_qkv  = (const float*)d_in[2];
    const float* w_proj = (const float*)d_in[3];
    const float* b_proj = (const float*)d_in[4];
    const float* g1     = (const float*)d_in[5];
    const float* beta1  = (const float*)d_in[6];
    const float* g2     = (const float*)d_in[7];
    const float* beta2  = (const float*)d_in[8];
    const float* w_fc1  = (const float*)d_in[9];
    const float* b_fc1  = (const float*)d_in[10];
    const float* w_fc2  = (const float*)d_in[11];
    const float* b_fc2  = (const float*)d_in[12];
    float* out = (float*)d_out;

    float *h, *qkv, *attn, *x1, *mid, *wqkv, *wproj, *wfc1, *wfc2;
    cudaGetSymbolAddress((void**)&h,     g_h);
    cudaGetSymbolAddress((void**)&qkv,   g_qkv);
    cudaGetSymbolAddress((void**)&attn,  g_attn);
    cudaGetSymbolAddress((void**)&x1,    g_x1);
    cudaGetSymbolAddress((void**)&mid,   g_mid);
    cudaGetSymbolAddress((void**)&wqkv,  g_wqkv);
    cudaGetSymbolAddress((void**)&wproj, g_wproj);
    cudaGetSymbolAddress((void**)&wfc1,  g_wfc1);
    cudaGetSymbolAddress((void**)&wfc2,  g_wfc2);

    const int ATTN_SMEM = 384 * ASTRIDE * (int)sizeof(float);  // ~102 KB
    cudaFuncSetAttribute(attn_kernel, cudaFuncAttributeMaxDynamicSharedMemorySize, ATTN_SMEM);
    cudaFuncSetAttribute(gemm_kernel<false, false, true>,
                         cudaFuncAttributeMaxDynamicSharedMemorySize, GEMM_SMEM);
    cudaFuncSetAttribute(gemm_kernel<false, true, false>,
                         cudaFuncAttributeMaxDynamicSharedMemorySize, GEMM_SMEM);
    cudaFuncSetAttribute(gemm_kernel<true, false, true>,
                         cudaFuncAttributeMaxDynamicSharedMemorySize, GEMM_SMEM);

    // 0) Pre-round + fragment-major relayout of weights (once per call)
    relayout_w<<<(DIM * 3 * DIM) / 1024, 256>>>(w_qkv,  wqkv,  3 * DIM, DIM);
    relayout_w<<<(DIM * DIM)     / 1024, 256>>>(w_proj, wproj, DIM,     DIM);
    relayout_w<<<(DIM * HIDDEN)  / 1024, 256>>>(w_fc1,  wfc1,  HIDDEN,  DIM);
    relayout_w<<<(HIDDEN * DIM)  / 1024, 256>>>(w_fc2,  wfc2,  DIM,     HIDDEN);

    // 1) LN1 (rounded output)
    ln_kernel<<<NTOK, 256>>>(x, g1, beta1, h);
    // 2) QKV = h @ w_qkv + b_qkv        [4096,1024]x[1024,3072], rounded out
    gemm_kernel<false, false, true><<<dim3(3 * DIM / 128, NTOK / 128), 128, GEMM_SMEM>>>(
        h, wqkv, b_qkv, nullptr, qkv, NTOK, 3 * DIM, DIM);
    // 3) Causal MHA (rounded output)
    attn_kernel<<<dim3(SEQ / 128, NH, 2), 256, ATTN_SMEM>>>(qkv, attn);
    // 4) x1 = x + attn @ w_proj + b_proj (full fp32 residual)
    gemm_kernel<false, true, false><<<dim3(DIM / 128, NTOK / 128), 128, GEMM_SMEM>>>(
        attn, wproj, b_proj, x, x1, NTOK, DIM, DIM);
    // 5) LN2 (rounded output)
    ln_kernel<<<NTOK, 256>>>(x1, g2, beta2, h);
    // 6) mid = gelu(h @ w_fc1 + b_fc1)   [4096,1024]x[1024,4096], rounded out
    gemm_kernel<true, false, true><<<dim3(HIDDEN / 128, NTOK / 128), 128, GEMM_SMEM>>>(
        h, wfc1, b_fc1, nullptr, mid, NTOK, HIDDEN, DIM);
    // 7) out = x1 + mid @ w_fc2 + b_fc2  [4096,4096]x[4096,1024], full fp32
    gemm_kernel<false, true, false><<<dim3(DIM / 128, NTOK / 128), 128, GEMM_SMEM>>>(
        mid, wfc2, b_fc2, x1, out, NTOK, DIM, HIDDEN);
}

// round 12
// speedup vs baseline: 1.3314x; 1.0758x over previous
#include <cuda_runtime.h>
#include <cuda_bf16.h>
#include <cstdint>
#include <math.h>

// ---------------------------------------------------------------------------
// Transformer block: LN1 -> QKV -> causal MHA -> proj(+res) -> LN2 -> FC1+GELU
//                    -> FC2(+res).  B=2, S=2048, D=1024, H=16, hd=64, FF=4096.
// TF32 mma.sync (m16n8k8), fp32 accumulation.
// R12: BOTH GEMM operands fragment-major. Weights re-tiled once (relayout_w);
// activations written fragment-major directly by their producers (LN, attn,
// fc1 epilogue). GEMM mainloop: 4 A-LDS.128 + 4 B-LDS.128 + 32 MMA per k-step.
// ---------------------------------------------------------------------------

#define DIM    1024
#define HIDDEN 4096
#define SEQ    2048
#define NTOK   4096   // B * S
#define NH     16
#define HD     64

// Scratch (allocation-free rule: device globals)
__device__ float g_h    [NTOK * DIM];       // LN output (tf32, A-frag layout)
__device__ float g_qkv  [NTOK * 3 * DIM];   // tf32, row-major (attn consumes)
__device__ float g_attn [NTOK * DIM];       // tf32, A-frag layout
__device__ float g_x1   [NTOK * DIM];       // full fp32 row-major (residual)
__device__ float g_mid  [NTOK * HIDDEN];    // tf32, A-frag layout (K=HIDDEN)
// tf32-rounded + fragment-major re-tiled weights
__device__ float g_wqkv [DIM * 3 * DIM];
__device__ float g_wproj[DIM * DIM];
__device__ float g_wfc1 [DIM * HIDDEN];
__device__ float g_wfc2 [HIDDEN * DIM];

// ---------------------------------------------------------------------------
// TF32 helpers
// ---------------------------------------------------------------------------
__device__ __forceinline__ uint32_t f2tf(float x) {
    uint32_t u;
    asm("cvt.rna.tf32.f32 %0, %1;" : "=r"(u) : "f"(x));
    return u;
}
__device__ __forceinline__ float f2tff(float x) { return __uint_as_float(f2tf(x)); }

__device__ __forceinline__ void mma8(float c[4], const uint32_t a[4], const uint32_t b[2]) {
    asm volatile(
        "mma.sync.aligned.m16n8k8.row.col.f32.tf32.tf32.f32 "
        "{%0,%1,%2,%3}, {%4,%5,%6,%7}, {%8,%9}, {%0,%1,%2,%3};"
        : "+f"(c[0]), "+f"(c[1]), "+f"(c[2]), "+f"(c[3])
        : "r"(a[0]), "r"(a[1]), "r"(a[2]), "r"(a[3]), "r"(b[0]), "r"(b[1]));
}

__device__ __forceinline__ void cpa16(uint32_t dst, const void* src) {
    asm volatile("cp.async.cg.shared.global [%0], [%1], 16;" :: "r"(dst), "l"(src) : "memory");
}
#define CP_COMMIT() asm volatile("cp.async.commit_group;" ::: "memory")
#define CP_WAIT1()  asm volatile("cp.async.wait_group 1;" ::: "memory")

__device__ __forceinline__ float gelu_f(float v) {
    return 0.5f * v * (1.0f + erff(v * 0.70710678118654752440f));
}

// ---------------------------------------------------------------------------
// A-fragment-major addressing.  M x K matrix, tiles 128(M) x 32(K), each tile
// 4096 contiguous floats: [kk(4)][wm(2)][mt(4)][lane(32)][e(4)] where for the
// m16n8k8 A fragment of warp-row wm, sub-tile mt, k-step kk:
//   lane = (rr&7)*4 + (cc&3),  e = (rr>>3) + 2*(cc>>2)
//   (rr = row%16 within the 16-row tile, cc = col%8 within the 8-col k-step)
// GEMM loads one float4 per (kk, mt): af[0..3] = e0..e3
//   = A[r][c], A[r+8][c], A[r][c+4], A[r+8][c+4].
// ---------------------------------------------------------------------------
__device__ __forceinline__ size_t fragA_addr(int row, int col, int K) {
    int KT   = K >> 5;
    int tile = (row >> 7) * KT + (col >> 5);
    int r = row & 127, c = col & 31;
    int wm = r >> 6, mt = (r >> 4) & 3, rr = r & 15;
    int kk = c >> 3, cc = c & 7;
    int lane = ((rr & 7) << 2) + (cc & 3);
    int e    = (rr >> 3) + ((cc >> 2) << 1);
    return ((size_t)tile << 12) +
           (size_t)(((((kk << 1) + wm) << 2) + mt) << 7) + (lane << 2) + e;
}

// ---------------------------------------------------------------------------
// Weight relayout: W[K][N] row-major -> B-fragment-major tiles (as R11).
// ---------------------------------------------------------------------------
__global__ __launch_bounds__(256) void relayout_w(
    const float* __restrict__ W, float* __restrict__ Wt, int N, int K)
{
    int t    = blockIdx.x * 256 + threadIdx.x;   // one float4 per thread
    int lane = t & 31;
    int j    = (t >> 5) & 3;
    int wn   = (t >> 7) & 1;
    int kk   = (t >> 8) & 3;
    int tile = t >> 10;
    int KT   = K >> 5;
    int kt   = tile % KT;
    int nb   = tile / KT;
    int k0   = kt * 32 + kk * 8 + (lane & 3);
    int n0   = nb * 128 + wn * 64 + (j << 4) + (lane >> 2);
    float4 v;
    v.x = f2tff(W[(size_t)(k0    ) * N + n0    ]);
    v.y = f2tff(W[(size_t)(k0 + 4) * N + n0    ]);
    v.z = f2tff(W[(size_t)(k0    ) * N + n0 + 8]);
    v.w = f2tff(W[(size_t)(k0 + 4) * N + n0 + 8]);
    *(float4*)(Wt + ((size_t)t << 2)) = v;
}

// ---------------------------------------------------------------------------
// LayerNorm: one 256-thread block per row of 1024.  Output tf32-rounded,
// written in A-fragment-major layout (K = DIM).
// ---------------------------------------------------------------------------
__global__ __launch_bounds__(256) void ln_kernel(
    const float* __restrict__ x, const float* __restrict__ g,
    const float* __restrict__ be, float* __restrict__ out)
{
    const int row = blockIdx.x;
    const int tid = threadIdx.x;
    const float4 v = *(const float4*)(x + (size_t)row * DIM + (tid << 2));
    float s = v.x + v.y + v.z + v.w;
    float q = v.x * v.x + v.y * v.y + v.z * v.z + v.w * v.w;
    #pragma unroll
    for (int off = 16; off; off >>= 1) {
        s += __shfl_xor_sync(0xffffffffu, s, off);
        q += __shfl_xor_sync(0xffffffffu, q, off);
    }
    __shared__ float ss[8], sq[8];
    if ((tid & 31) == 0) { ss[tid >> 5] = s; sq[tid >> 5] = q; }
    __syncthreads();
    float ts = 0.f, tq = 0.f;
    #pragma unroll
    for (int i = 0; i < 8; i++) { ts += ss[i]; tq += sq[i]; }
    const float mu  = ts * (1.0f / DIM);
    const float var = tq * (1.0f / DIM) - mu * mu;
    const float inv = rsqrtf(var + 1e-5f);
    const float4 gg = *(const float4*)(g  + (tid << 2));
    const float4 bb = *(const float4*)(be + (tid << 2));
    const int col = tid << 2;
    out[fragA_addr(row, col    , DIM)] = f2tff((v.x - mu) * inv * gg.x + bb.x);
    out[fragA_addr(row, col + 1, DIM)] = f2tff((v.y - mu) * inv * gg.y + bb.y);
    out[fragA_addr(row, col + 2, DIM)] = f2tff((v.z - mu) * inv * gg.z + bb.z);
    out[fragA_addr(row, col + 3, DIM)] = f2tff((v.w - mu) * inv * gg.w + bb.w);
}

// ---------------------------------------------------------------------------
// GEMM: C[M,N] = A @ W + bias (opt GELU / +residual / tf32-round / frag-out).
// A in A-fragment-major tiles; W in B-fragment-major tiles.  Both stages are
// contiguous 16KB blocks -> fully coalesced cp.async, conflict-free LDS.128.
// CTA tile 128x128, k-tile 32, 3-stage pipeline, ONE barrier per k-tile.
// 4 warps (2x2), warp tile 64x64 (4x8 m16n8).
// ---------------------------------------------------------------------------
#define STG_ELEMS 4096
#define GEMM_SMEM (6 * STG_ELEMS * 4)   // 98304 B

template <bool GELU_, bool RESID_, bool ROUND_, bool FRAG_>
__global__ __launch_bounds__(128, 1) void gemm_kernel(
    const float* __restrict__ A, const float* __restrict__ W,
    const float* __restrict__ bias, const float* __restrict__ R,
    float* __restrict__ C, int M, int N, int K)
{
    extern __shared__ float gsm[];
    float* Asm = gsm;                      // 3 stages of 4096
    float* Bsm = gsm + 3 * STG_ELEMS;      // 3 stages of 4096

    const int tid  = threadIdx.x;
    const int warp = tid >> 5, lane = tid & 31;
    const int wm = warp >> 1, wn = warp & 1;   // 2x2 warp grid, 64x64 tiles
    const int KT = K >> 5;

    const uint32_t As_u = (uint32_t)__cvta_generic_to_shared(Asm);
    const uint32_t Bs_u = (uint32_t)__cvta_generic_to_shared(Bsm);

    float acc[4][8][4];
    #pragma unroll
    for (int i = 0; i < 4; i++)
        #pragma unroll
        for (int j = 0; j < 8; j++)
            #pragma unroll
            for (int k = 0; k < 4; k++) acc[i][j][k] = 0.f;

    // Stage loader (no commit): stage s <- k-tile kt_  (both tiles contiguous)
    auto load_stage = [&](int s, int kt_) {
        const float* asrc = A + ((size_t)blockIdx.y * KT + kt_) * STG_ELEMS;
        const float* bsrc = W + ((size_t)blockIdx.x * KT + kt_) * STG_ELEMS;
        #pragma unroll
        for (int i = 0; i < 8; i++) {
            int c = tid + (i << 7);
            cpa16(As_u + (uint32_t)((s * STG_ELEMS + (c << 2)) << 2), asrc + (c << 2));
            cpa16(Bs_u + (uint32_t)((s * STG_ELEMS + (c << 2)) << 2), bsrc + (c << 2));
        }
    };

    load_stage(0, 0); CP_COMMIT();
    load_stage(1, 1); CP_COMMIT();

    for (int kt = 0; kt < KT; kt++) {
        CP_WAIT1();          // stage kt resident (<=1 newer group in flight)
        __syncthreads();     // all warps: stage kt visible, stage kt-1 consumed
        if (kt + 2 < KT) load_stage((kt + 2) % 3, kt + 2);
        CP_COMMIT();         // may be an empty group near the tail

        const float* As_ = Asm + (kt % 3) * STG_ELEMS;
        const float* Bs_ = Bsm + (kt % 3) * STG_ELEMS;

        #pragma unroll
        for (int kki = 0; kki < 4; kki++) {
            uint32_t af[4][4], bf[8][2];
            #pragma unroll
            for (int mt = 0; mt < 4; mt++) {
                float4 qa = *(const float4*)(As_ +
                    (size_t)(((((kki << 1) + wm) << 2) + mt) << 7) + (lane << 2));
                af[mt][0] = __float_as_uint(qa.x);
                af[mt][1] = __float_as_uint(qa.y);
                af[mt][2] = __float_as_uint(qa.z);
                af[mt][3] = __float_as_uint(qa.w);
            }
            #pragma unroll
            for (int j = 0; j < 4; j++) {
                float4 q = *(const float4*)(Bs_ +
                    (size_t)((((kki << 1) + wn) * 4 + j) * 32 + lane) * 4);
                bf[2 * j    ][0] = __float_as_uint(q.x);
                bf[2 * j    ][1] = __float_as_uint(q.y);
                bf[2 * j + 1][0] = __float_as_uint(q.z);
                bf[2 * j + 1][1] = __float_as_uint(q.w);
            }
            #pragma unroll
            for (int mt = 0; mt < 4; mt++)
                #pragma unroll
                for (int nt = 0; nt < 8; nt++)
                    mma8(acc[mt][nt], af[mt], bf[nt]);
        }
    }

    // Epilogue
    const int bm = blockIdx.y << 7;
    const int bn = blockIdx.x << 7;
    #pragma unroll
    for (int mt = 0; mt < 4; mt++) {
        #pragma unroll
        for (int nt = 0; nt < 8; nt++) {
            int row0 = bm + (wm << 6) + (mt << 4) + (lane >> 2);
            int col  = bn + (wn << 6) + (nt << 3) + ((lane & 3) << 1);
            const float b0 = __ldg(bias + col);
            const float b1 = __ldg(bias + col + 1);
            #pragma unroll
            for (int half = 0; half < 2; half++) {
                int row = row0 + half * 8;
                float v0 = acc[mt][nt][half * 2 + 0] + b0;
                float v1 = acc[mt][nt][half * 2 + 1] + b1;
                if (GELU_) { v0 = gelu_f(v0); v1 = gelu_f(v1); }
                if (RESID_) {
                    v0 += __ldg(R + (size_t)row * N + col);
                    v1 += __ldg(R + (size_t)row * N + col + 1);
                }
                if (ROUND_) { v0 = f2tff(v0); v1 = f2tff(v1); }
                if (FRAG_) {
                    C[fragA_addr(row, col    , N)] = v0;
                    C[fragA_addr(row, col + 1, N)] = v1;
                } else {
                    C[(size_t)row * N + col]     = v0;
                    C[(size_t)row * N + col + 1] = v1;
                }
            }
        }
    }
}

// ---------------------------------------------------------------------------
// Causal flash attention.  Inputs (qkv) tf32-rounded row-major; output is
// tf32-rounded, written A-fragment-major (K = DIM) for the proj GEMM.
// grid = (S/128, NH, B); 256 threads = 8 warps, each warp owns 16 query rows.
// ---------------------------------------------------------------------------
#define ASTRIDE 68
__global__ __launch_bounds__(256) void attn_kernel(
    const float* __restrict__ qkv, float* __restrict__ outp)
{
    extern __shared__ float sm[];
    float (*Qs)[ASTRIDE] = (float(*)[ASTRIDE])(sm);                 // 128 rows
    float (*Ks)[ASTRIDE] = (float(*)[ASTRIDE])(sm + 128 * ASTRIDE); //  64 rows
    float (*Vs)[ASTRIDE] = (float(*)[ASTRIDE])(sm + 192 * ASTRIDE); //  64 rows
    float (*Ps)[ASTRIDE] = (float(*)[ASTRIDE])(sm + 256 * ASTRIDE); // 128 rows

    const int qb = blockIdx.x, h = blockIdx.y, b = blockIdx.z;
    const int tid = threadIdx.x, warp = tid >> 5, lane = tid & 31;
    const int q0 = qb << 7;

    // Load Q block (128 x 64) — already tf32
    const float* qbase = qkv + (size_t)(b * SEQ + q0) * (3 * DIM) + h * HD;
    #pragma unroll
    for (int i = 0; i < 8; i++) {
        int idx = tid + (i << 8);
        int r = idx >> 4, c = (idx & 15) << 2;
        *(float4*)&Qs[r][c] = *(const float4*)(qbase + (size_t)r * (3 * DIM) + c);
    }

    float o[8][4];
    #pragma unroll
    for (int i = 0; i < 8; i++)
        #pragma unroll
        for (int j = 0; j < 4; j++) o[i][j] = 0.f;
    float m0 = -1e30f, m1 = -1e30f, l0 = 0.f, l1 = 0.f;

    const int ar = (warp << 4) + (lane >> 2);   // local query row (c0/c1); +8 for c2/c3
    const int nkb = (q0 >> 6) + 2;              // causal KV-block count

    for (int kb = 0; kb < nkb; kb++) {
        __syncthreads();   // previous iteration's K/V fully consumed
        const float* kptr = qkv + (size_t)(b * SEQ + (kb << 6)) * (3 * DIM) + DIM + h * HD;
        #pragma unroll
        for (int i = 0; i < 4; i++) {
            int idx = tid + (i << 8);
            int r = idx >> 4, c = (idx & 15) << 2;
            *(float4*)&Ks[r][c] = *(const float4*)(kptr + (size_t)r * (3 * DIM) + c);
            *(float4*)&Vs[r][c] = *(const float4*)(kptr + (size_t)r * (3 * DIM) + DIM + c);
        }
        __syncthreads();

        // S = Q @ K^T  (warp: 16 rows x 64 kv cols)
        float s[8][4];
        #pragma unroll
        for (int i = 0; i < 8; i++)
            #pragma unroll
            for (int j = 0; j < 4; j++) s[i][j] = 0.f;

        #pragma unroll
        for (int kk = 0; kk < 64; kk += 8) {
            uint32_t a[4];
            a[0] = __float_as_uint(Qs[ar    ][kk + (lane & 3)    ]);
            a[1] = __float_as_uint(Qs[ar + 8][kk + (lane & 3)    ]);
            a[2] = __float_as_uint(Qs[ar    ][kk + (lane & 3) + 4]);
            a[3] = __float_as_uint(Qs[ar + 8][kk + (lane & 3) + 4]);
            #pragma unroll
            for (int nt = 0; nt < 8; nt++) {
                uint32_t bfr[2];
                int n = (nt << 3) + (lane >> 2);
                bfr[0] = __float_as_uint(Ks[n][kk + (lane & 3)    ]);
                bfr[1] = __float_as_uint(Ks[n][kk + (lane & 3) + 4]);
                mma8(s[nt], a, bfr);
            }
        }

        // scale + causal mask + online softmax
        const int grow0 = q0 + ar;
        const int grow1 = grow0 + 8;
        const int cbase = (kb << 6) + ((lane & 3) << 1);
        float mn0 = m0, mn1 = m1;
        #pragma unroll
        for (int nt = 0; nt < 8; nt++) {
            int c0 = cbase + (nt << 3);
            s[nt][0] = (c0     <= grow0) ? s[nt][0] * 0.125f : -1e30f;
            s[nt][1] = (c0 + 1 <= grow0) ? s[nt][1] * 0.125f : -1e30f;
            s[nt][2] = (c0     <= grow1) ? s[nt][2] * 0.125f : -1e30f;
            s[nt][3] = (c0 + 1 <= grow1) ? s[nt][3] * 0.125f : -1e30f;
            mn0 = fmaxf(mn0, fmaxf(s[nt][0], s[nt][1]));
            mn1 = fmaxf(mn1, fmaxf(s[nt][2], s[nt][3]));
        }
        mn0 = fmaxf(mn0, __shfl_xor_sync(0xffffffffu, mn0, 1));
        mn0 = fmaxf(mn0, __shfl_xor_sync(0xffffffffu, mn0, 2));
        mn1 = fmaxf(mn1, __shfl_xor_sync(0xffffffffu, mn1, 1));
        mn1 = fmaxf(mn1, __shfl_xor_sync(0xffffffffu, mn1, 2));

        const float corr0 = __expf(m0 - mn0);
        const float corr1 = __expf(m1 - mn1);
        m0 = mn0; m1 = mn1;

        float rs0 = 0.f, rs1 = 0.f;
        #pragma unroll
        for (int nt = 0; nt < 8; nt++) {
            float p0 = __expf(s[nt][0] - m0);
            float p1 = __expf(s[nt][1] - m0);
            float p2 = __expf(s[nt][2] - m1);
            float p3 = __expf(s[nt][3] - m1);
            rs0 += p0 + p1; rs1 += p2 + p3;
            int pc = (nt << 3) + ((lane & 3) << 1);
            Ps[ar    ][pc]     = f2tff(p0);
            Ps[ar    ][pc + 1] = f2tff(p1);
            Ps[ar + 8][pc]     = f2tff(p2);
            Ps[ar + 8][pc + 1] = f2tff(p3);
        }
        rs0 += __shfl_xor_sync(0xffffffffu, rs0, 1);
        rs0 += __shfl_xor_sync(0xffffffffu, rs0, 2);
        rs1 += __shfl_xor_sync(0xffffffffu, rs1, 1);
        rs1 += __shfl_xor_sync(0xffffffffu, rs1, 2);
        l0 = l0 * corr0 + rs0;
        l1 = l1 * corr1 + rs1;
        #pragma unroll
        for (int nt = 0; nt < 8; nt++) {
            o[nt][0] *= corr0; o[nt][1] *= corr0;
            o[nt][2] *= corr1; o[nt][3] *= corr1;
        }
        __syncwarp();   // Ps visible to whole warp (P region is warp-private)

        // O += P @ V  (warp: 16 rows x 64 d cols, k = 64 kv)
        #pragma unroll
        for (int kk = 0; kk < 64; kk += 8) {
            uint32_t a[4];
            a[0] = __float_as_uint(Ps[ar    ][kk + (lane & 3)    ]);
            a[1] = __float_as_uint(Ps[ar + 8][kk + (lane & 3)    ]);
            a[2] = __float_as_uint(Ps[ar    ][kk + (lane & 3) + 4]);
            a[3] = __float_as_uint(Ps[ar + 8][kk + (lane & 3) + 4]);
            #pragma unroll
            for (int nt = 0; nt < 8; nt++) {
                uint32_t bfr[2];
                int n = (nt << 3) + (lane >> 2);
                bfr[0] = __float_as_uint(Vs[kk + (lane & 3)    ][n]);
                bfr[1] = __float_as_uint(Vs[kk + (lane & 3) + 4][n]);
                mma8(o[nt], a, bfr);
            }
        }
    }

    // Write (tf32-rounded), A-fragment-major for the proj GEMM (K = DIM).
    const float inv0 = 1.0f / l0;
    const float inv1 = 1.0f / l1;
    const int row0 = b * SEQ + q0 + ar;
    const int row1 = row0 + 8;
    #pragma unroll
    for (int nt = 0; nt < 8; nt++) {
        int col = h * HD + (nt << 3) + ((lane & 3) << 1);
        outp[fragA_addr(row0, col    , DIM)] = f2tff(o[nt][0] * inv0);
        outp[fragA_addr(row0, col + 1, DIM)] = f2tff(o[nt][1] * inv0);
        outp[fragA_addr(row1, col    , DIM)] = f2tff(o[nt][2] * inv1);
        outp[fragA_addr(row1, col + 1, DIM)] = f2tff(o[nt][3] * inv1);
    }
}

// ---------------------------------------------------------------------------
// Launch
// ---------------------------------------------------------------------------
extern "C" void kernel_launch(void* const* d_in, const int* in_sizes, int n_in,
                              void* d_out, int out_size)
{
    const float* x      = (const float*)d_in[0];
    const float* w_qkv  = (const float*)d_in[1];
    const float* b_qkv  = (const float*)d_in[2];
    const float* w_proj = (const float*)d_in[3];
    const float* b_proj = (const float*)d_in[4];
    const float* g1     = (const float*)d_in[5];
    const float* beta1  = (const float*)d_in[6];
    const float* g2     = (const float*)d_in[7];
    const float* beta2  = (const float*)d_in[8];
    const float* w_fc1  = (const float*)d_in[9];
    const float* b_fc1  = (const float*)d_in[10];
    const float* w_fc2  = (const float*)d_in[11];
    const float* b_fc2  = (const float*)d_in[12];
    float* out = (float*)d_out;

    float *h, *qkv, *attn, *x1, *mid, *wqkv, *wproj, *wfc1, *wfc2;
    cudaGetSymbolAddress((void**)&h,     g_h);
    cudaGetSymbolAddress((void**)&qkv,   g_qkv);
    cudaGetSymbolAddress((void**)&attn,  g_attn);
    cudaGetSymbolAddress((void**)&x1,    g_x1);
    cudaGetSymbolAddress((void**)&mid,   g_mid);
    cudaGetSymbolAddress((void**)&wqkv,  g_wqkv);
    cudaGetSymbolAddress((void**)&wproj, g_wproj);
    cudaGetSymbolAddress((void**)&wfc1,  g_wfc1);
    cudaGetSymbolAddress((void**)&wfc2,  g_wfc2);

    const int ATTN_SMEM = 384 * ASTRIDE * (int)sizeof(float);  // ~102 KB
    cudaFuncSetAttribute(attn_kernel, cudaFuncAttributeMaxDynamicSharedMemorySize, ATTN_SMEM);
    cudaFuncSetAttribute(gemm_kernel<false, false, true, false>,
                         cudaFuncAttributeMaxDynamicSharedMemorySize, GEMM_SMEM);
    cudaFuncSetAttribute(gemm_kernel<false, true, false, false>,
                         cudaFuncAttributeMaxDynamicSharedMemorySize, GEMM_SMEM);
    cudaFuncSetAttribute(gemm_kernel<true, false, true, true>,
                         cudaFuncAttributeMaxDynamicSharedMemorySize, GEMM_SMEM);

    // 0) Pre-round + fragment-major relayout of weights (once per call)
    relayout_w<<<(DIM * 3 * DIM) / 1024, 256>>>(w_qkv,  wqkv,  3 * DIM, DIM);
    relayout_w<<<(DIM * DIM)     / 1024, 256>>>(w_proj, wproj, DIM,     DIM);
    relayout_w<<<(DIM * HIDDEN)  / 1024, 256>>>(w_fc1,  wfc1,  HIDDEN,  DIM);
    relayout_w<<<(HIDDEN * DIM)  / 1024, 256>>>(w_fc2,  wfc2,  DIM,     HIDDEN);

    // 1) LN1 (A-frag output)
    ln_kernel<<<NTOK, 256>>>(x, g1, beta1, h);
    // 2) QKV = h @ w_qkv + b_qkv  [4096,1024]x[1024,3072], rounded row-major out
    gemm_kernel<false, false, true, false><<<dim3(3 * DIM / 128, NTOK / 128), 128, GEMM_SMEM>>>(
        h, wqkv, b_qkv, nullptr, qkv, NTOK, 3 * DIM, DIM);
    // 3) Causal MHA (A-frag output)
    attn_kernel<<<dim3(SEQ / 128, NH, 2), 256, ATTN_SMEM>>>(qkv, attn);
    // 4) x1 = x + attn @ w_proj + b_proj (full fp32 row-major residual)
    gemm_kernel<false, true, false, false><<<dim3(DIM / 128, NTOK / 128), 128, GEMM_SMEM>>>(
        attn, wproj, b_proj, x, x1, NTOK, DIM, DIM);
    // 5) LN2 (A-frag output)
    ln_kernel<<<NTOK, 256>>>(x1, g2, beta2, h);
    // 6) mid = gelu(h @ w_fc1 + b_fc1)  [4096,1024]x[1024,4096], A-frag out
    gemm_kernel<true, false, true, true><<<dim3(HIDDEN / 128, NTOK / 128), 128, GEMM_SMEM>>>(
        h, wfc1, b_fc1, nullptr, mid, NTOK, HIDDEN, DIM);
    // 7) out = x1 + mid @ w_fc2 + b_fc2  [4096,4096]x[4096,1024], row-major
    gemm_kernel<false, true, false, false><<<dim3(DIM / 128, NTOK / 128), 128, GEMM_SMEM>>>(
        mid, wfc2, b_fc2, x1, out, NTOK, DIM, HIDDEN);
}

// round 14
// speedup vs baseline: 1.8114x; 1.3605x over previous
#include <cuda_runtime.h>
#include <cuda_fp16.h>
#include <cstdint>
#include <math.h>

// ---------------------------------------------------------------------------
// Transformer block: LN1 -> QKV -> causal MHA -> proj(+res) -> LN2 -> FC1+GELU
//                    -> FC2(+res).  B=2, S=2048, D=1024, H=16, hd=64, FF=4096.
// R14: GEMMs on fp16 mma.sync m16n8k16 (same 10-bit mantissa as tf32 -> same
// rounding for in-range values), fragment-major BOTH operands, 3-stage
// cp.async, one barrier per k-tile.  Attention stays tf32 (proven).
// ---------------------------------------------------------------------------

#define DIM    1024
#define HIDDEN 4096
#define SEQ    2048
#define NTOK   4096   // B * S
#define NH     16
#define HD     64

// Scratch (allocation-free rule: device globals)
__device__ __half g_h   [NTOK * DIM];       // LN out, fp16 A-frag (K=DIM)
__device__ float  g_qkv [NTOK * 3 * DIM];   // tf32-rounded row-major (attn in)
__device__ __half g_attn[NTOK * DIM];       // attn out, fp16 A-frag (K=DIM)
__device__ float  g_x1  [NTOK * DIM];       // fp32 row-major residual
__device__ __half g_mid [NTOK * HIDDEN];    // fc1 out, fp16 A-frag (K=HIDDEN)
// fp16 B-frag weights
__device__ __half g_wqkv [DIM * 3 * DIM];
__device__ __half g_wproj[DIM * DIM];
__device__ __half g_wfc1 [DIM * HIDDEN];
__device__ __half g_wfc2 [HIDDEN * DIM];

// ---------------------------------------------------------------------------
// Helpers
// ---------------------------------------------------------------------------
__device__ __forceinline__ uint32_t f2tf(float x) {
    uint32_t u;
    asm("cvt.rna.tf32.f32 %0, %1;" : "=r"(u) : "f"(x));
    return u;
}
__device__ __forceinline__ float f2tff(float x) { return __uint_as_float(f2tf(x)); }

// tf32 m16n8k8 (attention)
__device__ __forceinline__ void mma8(float c[4], const uint32_t a[4], const uint32_t b[2]) {
    asm volatile(
        "mma.sync.aligned.m16n8k8.row.col.f32.tf32.tf32.f32 "
        "{%0,%1,%2,%3}, {%4,%5,%6,%7}, {%8,%9}, {%0,%1,%2,%3};"
        : "+f"(c[0]), "+f"(c[1]), "+f"(c[2]), "+f"(c[3])
        : "r"(a[0]), "r"(a[1]), "r"(a[2]), "r"(a[3]), "r"(b[0]), "r"(b[1]));
}
// fp16 m16n8k16 (GEMMs)
__device__ __forceinline__ void mma16(float c[4], const uint32_t a[4], const uint32_t b[2]) {
    asm volatile(
        "mma.sync.aligned.m16n8k16.row.col.f32.f16.f16.f32 "
        "{%0,%1,%2,%3}, {%4,%5,%6,%7}, {%8,%9}, {%0,%1,%2,%3};"
        : "+f"(c[0]), "+f"(c[1]), "+f"(c[2]), "+f"(c[3])
        : "r"(a[0]), "r"(a[1]), "r"(a[2]), "r"(a[3]), "r"(b[0]), "r"(b[1]));
}

__device__ __forceinline__ void cpa16(uint32_t dst, const void* src) {
    asm volatile("cp.async.cg.shared.global [%0], [%1], 16;" :: "r"(dst), "l"(src) : "memory");
}
#define CP_COMMIT() asm volatile("cp.async.commit_group;" ::: "memory")
#define CP_WAIT1()  asm volatile("cp.async.wait_group 1;" ::: "memory")

__device__ __forceinline__ float gelu_f(float v) {
    return 0.5f * v * (1.0f + erff(v * 0.70710678118654752440f));
}

// ---------------------------------------------------------------------------
// fp16 A-fragment-major addressing (m16n8k16).  M x K halfs, tiles 128(M) x
// 64(K) = 8192 halfs (4096 uint32) contiguous:
//   [kki(4)][wm(2)][mt(4)][lane(32)][reg(4)] uint32s, + low/high half (k&1).
// For A frag of warp-row wm, sub-tile mt, k16-step kki:
//   lane = (rr&7)*4 + ((cc>>1)&3), reg = (rr>>3) + 2*(cc>>3), half = cc&1
//   (rr = row%16, cc = col%16)
// Returns half index.
// ---------------------------------------------------------------------------
__device__ __forceinline__ size_t fragA_h(int row, int col, int K) {
    int KT = K >> 6;
    size_t tile = (size_t)(row >> 7) * KT + (col >> 6);
    int r = row & 127, c = col & 63;
    int wm = r >> 6, mt = (r >> 4) & 3, rr = r & 15;
    int kki = c >> 4, cc = c & 15;
    int lane = ((rr & 7) << 2) + ((cc >> 1) & 3);
    int reg  = (rr >> 3) + ((cc >> 3) << 1);
    return (((tile << 12) +
             (size_t)(((((kki << 1) + wm) << 2) + mt) << 7) + (lane << 2) + reg) << 1)
           + (cc & 1);
}

// ---------------------------------------------------------------------------
// Weight relayout: W[K][N] fp32 row-major -> fp16 B-frag tiles.
// Tile (nb, kt) = 64(K) x 128(N) halfs = 4096 uint32 contiguous:
//   [kki(4)][wn(2)][j(4)][lane(32)][e(4)] uint32, e: nt=2j+(e>>1), khi=(e&1).
//   n = nb*128 + wn*64 + nt*8 + (lane>>2)
//   k = kt*64 + kki*16 + 2*(lane&3) + 8*(e&1), halfs (k, k+1).
// One thread per uint32.
// ---------------------------------------------------------------------------
__global__ __launch_bounds__(256) void relayout_wh(
    const float* __restrict__ W, __half* __restrict__ Wt, int N, int K)
{
    int u    = blockIdx.x * 256 + threadIdx.x;
    int e    = u & 3;
    int lane = (u >> 2) & 31;
    int base = (u >> 7) & 31;
    int j = base & 3, wn = (base >> 2) & 1, kki = base >> 3;
    int tile = u >> 12;
    int KT = K >> 6;
    int kt = tile % KT, nb = tile / KT;
    int n = nb * 128 + wn * 64 + ((j << 1) + (e >> 1)) * 8 + (lane >> 2);
    int k = kt * 64 + kki * 16 + ((lane & 3) << 1) + ((e & 1) << 3);
    __half2 h2 = __floats2half2_rn(W[(size_t)k * N + n], W[(size_t)(k + 1) * N + n]);
    *(__half2*)(Wt + ((size_t)u << 1)) = h2;
}

// ---------------------------------------------------------------------------
// LayerNorm: one 256-thread block per row of 1024; fp16 A-frag output.
// ---------------------------------------------------------------------------
__global__ __launch_bounds__(256) void ln_kernel(
    const float* __restrict__ x, const float* __restrict__ g,
    const float* __restrict__ be, __half* __restrict__ out)
{
    const int row = blockIdx.x;
    const int tid = threadIdx.x;
    const float4 v = *(const float4*)(x + (size_t)row * DIM + (tid << 2));
    float s = v.x + v.y + v.z + v.w;
    float q = v.x * v.x + v.y * v.y + v.z * v.z + v.w * v.w;
    #pragma unroll
    for (int off = 16; off; off >>= 1) {
        s += __shfl_xor_sync(0xffffffffu, s, off);
        q += __shfl_xor_sync(0xffffffffu, q, off);
    }
    __shared__ float ss[8], sq[8];
    if ((tid & 31) == 0) { ss[tid >> 5] = s; sq[tid >> 5] = q; }
    __syncthreads();
    float ts = 0.f, tq = 0.f;
    #pragma unroll
    for (int i = 0; i < 8; i++) { ts += ss[i]; tq += sq[i]; }
    const float mu  = ts * (1.0f / DIM);
    const float var = tq * (1.0f / DIM) - mu * mu;
    const float inv = rsqrtf(var + 1e-5f);
    const float4 gg = *(const float4*)(g  + (tid << 2));
    const float4 bb = *(const float4*)(be + (tid << 2));
    const int col = tid << 2;
    *(__half2*)(out + fragA_h(row, col, DIM)) =
        __floats2half2_rn((v.x - mu) * inv * gg.x + bb.x,
                          (v.y - mu) * inv * gg.y + bb.y);
    *(__half2*)(out + fragA_h(row, col + 2, DIM)) =
        __floats2half2_rn((v.z - mu) * inv * gg.z + bb.z,
                          (v.w - mu) * inv * gg.w + bb.w);
}

// ---------------------------------------------------------------------------
// fp16 GEMM: C[M,N] = A @ W + bias (opt GELU / +residual / frag-half-out /
// rounded-fp32-row-out).  A in fp16 A-frag tiles, W in fp16 B-frag tiles.
// CTA 128x128, k-tile 64 halfs, 3-stage cp.async, one barrier per k-tile.
// 4 warps (2x2), warp tile 64x64 (4x8 m16n8k16).
// ---------------------------------------------------------------------------
#define STG_U32 4096                       // uint32 per operand stage (8 KB... = 16KB)
#define GEMM_SMEM (6 * STG_U32 * 4)        // 98304 B

template <bool GELU_, bool RESID_, bool ROUND_, bool FRAGOUT_>
__global__ __launch_bounds__(128, 1) void gemm_kernel(
    const __half* __restrict__ A, const __half* __restrict__ Wt,
    const float* __restrict__ bias, const float* __restrict__ R,
    float* __restrict__ Cf, __half* __restrict__ Ch, int M, int N, int K)
{
    extern __shared__ uint32_t gsm[];
    uint32_t* Asm = gsm;                   // 3 stages of 4096 uint32
    uint32_t* Bsm = gsm + 3 * STG_U32;     // 3 stages of 4096 uint32

    const int tid  = threadIdx.x;
    const int warp = tid >> 5, lane = tid & 31;
    const int wm = warp >> 1, wn = warp & 1;
    const int KT = K >> 6;

    const uint32_t As_u = (uint32_t)__cvta_generic_to_shared(Asm);
    const uint32_t Bs_u = (uint32_t)__cvta_generic_to_shared(Bsm);

    float acc[4][8][4];
    #pragma unroll
    for (int i = 0; i < 4; i++)
        #pragma unroll
        for (int j = 0; j < 8; j++)
            #pragma unroll
            for (int k = 0; k < 4; k++) acc[i][j][k] = 0.f;

    // stage s <- k-tile kt_: A and B tiles are contiguous 16KB blocks
    auto load_stage = [&](int s, int kt_) {
        const __half* asrc = A  + (((size_t)blockIdx.y * KT + kt_) << 13);
        const __half* bsrc = Wt + (((size_t)blockIdx.x * KT + kt_) << 13);
        #pragma unroll
        for (int i = 0; i < 8; i++) {
            int c = tid + (i << 7);        // 0..1023 chunks of 16B
            cpa16(As_u + (uint32_t)((s * STG_U32 + (c << 2)) << 2), asrc + (c << 3));
            cpa16(Bs_u + (uint32_t)((s * STG_U32 + (c << 2)) << 2), bsrc + (c << 3));
        }
    };

    load_stage(0, 0); CP_COMMIT();
    load_stage(1, 1); CP_COMMIT();

    for (int kt = 0; kt < KT; kt++) {
        CP_WAIT1();
        __syncthreads();
        if (kt + 2 < KT) load_stage((kt + 2) % 3, kt + 2);
        CP_COMMIT();

        const uint32_t* As_ = Asm + (kt % 3) * STG_U32;
        const uint32_t* Bs_ = Bsm + (kt % 3) * STG_U32;

        #pragma unroll
        for (int kki = 0; kki < 4; kki++) {
            uint32_t af[4][4], bf[8][2];
            #pragma unroll
            for (int mt = 0; mt < 4; mt++) {
                uint4 qa = *(const uint4*)(As_ +
                    (size_t)(((((kki << 1) + wm) << 2) + mt) << 7) + (lane << 2));
                af[mt][0] = qa.x; af[mt][1] = qa.y; af[mt][2] = qa.z; af[mt][3] = qa.w;
            }
            #pragma unroll
            for (int j = 0; j < 4; j++) {
                uint4 qb = *(const uint4*)(Bs_ +
                    (size_t)(((((kki << 1) + wn) << 2) + j) << 7) + (lane << 2));
                bf[2 * j    ][0] = qb.x; bf[2 * j    ][1] = qb.y;
                bf[2 * j + 1][0] = qb.z; bf[2 * j + 1][1] = qb.w;
            }
            #pragma unroll
            for (int mt = 0; mt < 4; mt++)
                #pragma unroll
                for (int nt = 0; nt < 8; nt++)
                    mma16(acc[mt][nt], af[mt], bf[nt]);
        }
    }

    // Epilogue
    const int bm = blockIdx.y << 7;
    const int bn = blockIdx.x << 7;
    #pragma unroll
    for (int mt = 0; mt < 4; mt++) {
        #pragma unroll
        for (int nt = 0; nt < 8; nt++) {
            int row0 = bm + (wm << 6) + (mt << 4) + (lane >> 2);
            int col  = bn + (wn << 6) + (nt << 3) + ((lane & 3) << 1);
            const float b0 = __ldg(bias + col);
            const float b1 = __ldg(bias + col + 1);
            #pragma unroll
            for (int half = 0; half < 2; half++) {
                int row = row0 + half * 8;
                float v0 = acc[mt][nt][half * 2 + 0] + b0;
                float v1 = acc[mt][nt][half * 2 + 1] + b1;
                if (GELU_) { v0 = gelu_f(v0); v1 = gelu_f(v1); }
                if (RESID_) {
                    v0 += __ldg(R + (size_t)row * N + col);
                    v1 += __ldg(R + (size_t)row * N + col + 1);
                }
                if (FRAGOUT_) {
                    *(__half2*)(Ch + fragA_h(row, col, N)) = __floats2half2_rn(v0, v1);
                } else if (ROUND_) {
                    Cf[(size_t)row * N + col]     = f2tff(v0);
                    Cf[(size_t)row * N + col + 1] = f2tff(v1);
                } else {
                    Cf[(size_t)row * N + col]     = v0;
                    Cf[(size_t)row * N + col + 1] = v1;
                }
            }
        }
    }
}

// ---------------------------------------------------------------------------
// Causal flash attention (proven tf32 version).  qkv fp32 row-major; output
// fp16 A-frag (K=DIM) for the proj GEMM.
// grid = (S/128, NH, B); 256 threads = 8 warps.
// ---------------------------------------------------------------------------
#define ASTRIDE 68
__global__ __launch_bounds__(256) void attn_kernel(
    const float* __restrict__ qkv, __half* __restrict__ outp)
{
    extern __shared__ float sm[];
    float (*Qs)[ASTRIDE] = (float(*)[ASTRIDE])(sm);                 // 128 rows
    float (*Ks)[ASTRIDE] = (float(*)[ASTRIDE])(sm + 128 * ASTRIDE); //  64 rows
    float (*Vs)[ASTRIDE] = (float(*)[ASTRIDE])(sm + 192 * ASTRIDE); //  64 rows
    float (*Ps)[ASTRIDE] = (float(*)[ASTRIDE])(sm + 256 * ASTRIDE); // 128 rows

    const int qb = blockIdx.x, h = blockIdx.y, b = blockIdx.z;
    const int tid = threadIdx.x, warp = tid >> 5, lane = tid & 31;
    const int q0 = qb << 7;

    const float* qbase = qkv + (size_t)(b * SEQ + q0) * (3 * DIM) + h * HD;
    #pragma unroll
    for (int i = 0; i < 8; i++) {
        int idx = tid + (i << 8);
        int r = idx >> 4, c = (idx & 15) << 2;
        *(float4*)&Qs[r][c] = *(const float4*)(qbase + (size_t)r * (3 * DIM) + c);
    }

    float o[8][4];
    #pragma unroll
    for (int i = 0; i < 8; i++)
        #pragma unroll
        for (int j = 0; j < 4; j++) o[i][j] = 0.f;
    float m0 = -1e30f, m1 = -1e30f, l0 = 0.f, l1 = 0.f;

    const int ar = (warp << 4) + (lane >> 2);
    const int nkb = (q0 >> 6) + 2;

    for (int kb = 0; kb < nkb; kb++) {
        __syncthreads();
        const float* kptr = qkv + (size_t)(b * SEQ + (kb << 6)) * (3 * DIM) + DIM + h * HD;
        #pragma unroll
        for (int i = 0; i < 4; i++) {
            int idx = tid + (i << 8);
            int r = idx >> 4, c = (idx & 15) << 2;
            *(float4*)&Ks[r][c] = *(const float4*)(kptr + (size_t)r * (3 * DIM) + c);
            *(float4*)&Vs[r][c] = *(const float4*)(kptr + (size_t)r * (3 * DIM) + DIM + c);
        }
        __syncthreads();

        float s[8][4];
        #pragma unroll
        for (int i = 0; i < 8; i++)
            #pragma unroll
            for (int j = 0; j < 4; j++) s[i][j] = 0.f;

        #pragma unroll
        for (int kk = 0; kk < 64; kk += 8) {
            uint32_t a[4];
            a[0] = __float_as_uint(Qs[ar    ][kk + (lane & 3)    ]);
            a[1] = __float_as_uint(Qs[ar + 8][kk + (lane & 3)    ]);
            a[2] = __float_as_uint(Qs[ar    ][kk + (lane & 3) + 4]);
            a[3] = __float_as_uint(Qs[ar + 8][kk + (lane & 3) + 4]);
            #pragma unroll
            for (int nt = 0; nt < 8; nt++) {
                uint32_t bfr[2];
                int n = (nt << 3) + (lane >> 2);
                bfr[0] = __float_as_uint(Ks[n][kk + (lane & 3)    ]);
                bfr[1] = __float_as_uint(Ks[n][kk + (lane & 3) + 4]);
                mma8(s[nt], a, bfr);
            }
        }

        const int grow0 = q0 + ar;
        const int grow1 = grow0 + 8;
        const int cbase = (kb << 6) + ((lane & 3) << 1);
        float mn0 = m0, mn1 = m1;
        #pragma unroll
        for (int nt = 0; nt < 8; nt++) {
            int c0 = cbase + (nt << 3);
            s[nt][0] = (c0     <= grow0) ? s[nt][0] * 0.125f : -1e30f;
            s[nt][1] = (c0 + 1 <= grow0) ? s[nt][1] * 0.125f : -1e30f;
            s[nt][2] = (c0     <= grow1) ? s[nt][2] * 0.125f : -1e30f;
            s[nt][3] = (c0 + 1 <= grow1) ? s[nt][3] * 0.125f : -1e30f;
            mn0 = fmaxf(mn0, fmaxf(s[nt][0], s[nt][1]));
            mn1 = fmaxf(mn1, fmaxf(s[nt][2], s[nt][3]));
        }
        mn0 = fmaxf(mn0, __shfl_xor_sync(0xffffffffu, mn0, 1));
        mn0 = fmaxf(mn0, __shfl_xor_sync(0xffffffffu, mn0, 2));
        mn1 = fmaxf(mn1, __shfl_xor_sync(0xffffffffu, mn1, 1));
        mn1 = fmaxf(mn1, __shfl_xor_sync(0xffffffffu, mn1, 2));

        const float corr0 = __expf(m0 - mn0);
        const float corr1 = __expf(m1 - mn1);
        m0 = mn0; m1 = mn1;

        float rs0 = 0.f, rs1 = 0.f;
        #pragma unroll
        for (int nt = 0; nt < 8; nt++) {
            float p0 = __expf(s[nt][0] - m0);
            float p1 = __expf(s[nt][1] - m0);
            float p2 = __expf(s[nt][2] - m1);
            float p3 = __expf(s[nt][3] - m1);
            rs0 += p0 + p1; rs1 += p2 + p3;
            int pc = (nt << 3) + ((lane & 3) << 1);
            Ps[ar    ][pc]     = f2tff(p0);
            Ps[ar    ][pc + 1] = f2tff(p1);
            Ps[ar + 8][pc]     = f2tff(p2);
            Ps[ar + 8][pc + 1] = f2tff(p3);
        }
        rs0 += __shfl_xor_sync(0xffffffffu, rs0, 1);
        rs0 += __shfl_xor_sync(0xffffffffu, rs0, 2);
        rs1 += __shfl_xor_sync(0xffffffffu, rs1, 1);
        rs1 += __shfl_xor_sync(0xffffffffu, rs1, 2);
        l0 = l0 * corr0 + rs0;
        l1 = l1 * corr1 + rs1;
        #pragma unroll
        for (int nt = 0; nt < 8; nt++) {
            o[nt][0] *= corr0; o[nt][1] *= corr0;
            o[nt][2] *= corr1; o[nt][3] *= corr1;
        }
        __syncwarp();

        #pragma unroll
        for (int kk = 0; kk < 64; kk += 8) {
            uint32_t a[4];
            a[0] = __float_as_uint(Ps[ar    ][kk + (lane & 3)    ]);
            a[1] = __float_as_uint(Ps[ar + 8][kk + (lane & 3)    ]);
            a[2] = __float_as_uint(Ps[ar    ][kk + (lane & 3) + 4]);
            a[3] = __float_as_uint(Ps[ar + 8][kk + (lane & 3) + 4]);
            #pragma unroll
            for (int nt = 0; nt < 8; nt++) {
                uint32_t bfr[2];
                int n = (nt << 3) + (lane >> 2);
                bfr[0] = __float_as_uint(Vs[kk + (lane & 3)    ][n]);
                bfr[1] = __float_as_uint(Vs[kk + (lane & 3) + 4][n]);
                mma8(o[nt], a, bfr);
            }
        }
    }

    // fp16 A-frag output for proj GEMM (K = DIM); cols are even pairs.
    const float inv0 = 1.0f / l0;
    const float inv1 = 1.0f / l1;
    const int row0 = b * SEQ + q0 + ar;
    const int row1 = row0 + 8;
    #pragma unroll
    for (int nt = 0; nt < 8; nt++) {
        int col = h * HD + (nt << 3) + ((lane & 3) << 1);
        *(__half2*)(outp + fragA_h(row0, col, DIM)) =
            __floats2half2_rn(o[nt][0] * inv0, o[nt][1] * inv0);
        *(__half2*)(outp + fragA_h(row1, col, DIM)) =
            __floats2half2_rn(o[nt][2] * inv1, o[nt][3] * inv1);
    }
}

// ---------------------------------------------------------------------------
// Launch
// ---------------------------------------------------------------------------
extern "C" void kernel_launch(void* const* d_in, const int* in_sizes, int n_in,
                              void* d_out, int out_size)
{
    const float* x      = (const float*)d_in[0];
    const float* w_qkv  = (const float*)d_in[1];
    const float* b_qkv  = (const float*)d_in[2];
    const float* w_proj = (const float*)d_in[3];
    const float* b_proj = (const float*)d_in[4];
    const float* g1     = (const float*)d_in[5];
    const float* beta1  = (const float*)d_in[6];
    const float* g2     = (const float*)d_in[7];
    const float* beta2  = (const float*)d_in[8];
    const float* w_fc1  = (const float*)d_in[9];
    const float* b_fc1  = (const float*)d_in[10];
    const float* w_fc2  = (const float*)d_in[11];
    const float* b_fc2  = (const float*)d_in[12];
    float* out = (float*)d_out;

    __half *h, *attn, *mid, *wqkv, *wproj, *wfc1, *wfc2;
    float *qkv, *x1;
    cudaGetSymbolAddress((void**)&h,     g_h);
    cudaGetSymbolAddress((void**)&qkv,   g_qkv);
    cudaGetSymbolAddress((void**)&attn,  g_attn);
    cudaGetSymbolAddress((void**)&x1,    g_x1);
    cudaGetSymbolAddress((void**)&mid,   g_mid);
    cudaGetSymbolAddress((void**)&wqkv,  g_wqkv);
    cudaGetSymbolAddress((void**)&wproj, g_wproj);
    cudaGetSymbolAddress((void**)&wfc1,  g_wfc1);
    cudaGetSymbolAddress((void**)&wfc2,  g_wfc2);

    const int ATTN_SMEM = 384 * ASTRIDE * (int)sizeof(float);  // ~102 KB
    cudaFuncSetAttribute(attn_kernel, cudaFuncAttributeMaxDynamicSharedMemorySize, ATTN_SMEM);
    cudaFuncSetAttribute(gemm_kernel<false, false, true, false>,
                         cudaFuncAttributeMaxDynamicSharedMemorySize, GEMM_SMEM);
    cudaFuncSetAttribute(gemm_kernel<false, true, false, false>,
                         cudaFuncAttributeMaxDynamicSharedMemorySize, GEMM_SMEM);
    cudaFuncSetAttribute(gemm_kernel<true, false, false, true>,
                         cudaFuncAttributeMaxDynamicSharedMemorySize, GEMM_SMEM);

    // 0) Weight relayout to fp16 B-frag (once per call)
    relayout_wh<<<(DIM * 3 * DIM / 2) / 256, 256>>>(w_qkv,  wqkv,  3 * DIM, DIM);
    relayout_wh<<<(DIM * DIM / 2)     / 256, 256>>>(w_proj, wproj, DIM,     DIM);
    relayout_wh<<<(DIM * HIDDEN / 2)  / 256, 256>>>(w_fc1,  wfc1,  HIDDEN,  DIM);
    relayout_wh<<<(HIDDEN * DIM / 2)  / 256, 256>>>(w_fc2,  wfc2,  DIM,     HIDDEN);

    // 1) LN1 (fp16 A-frag out)
    ln_kernel<<<NTOK, 256>>>(x, g1, beta1, h);
    // 2) QKV = h @ w_qkv + b_qkv  [4096,1024]x[1024,3072], tf32-rounded fp32 row-major
    gemm_kernel<false, false, true, false><<<dim3(3 * DIM / 128, NTOK / 128), 128, GEMM_SMEM>>>(
        h, wqkv, b_qkv, nullptr, qkv, nullptr, NTOK, 3 * DIM, DIM);
    // 3) Causal MHA (fp16 A-frag out)
    attn_kernel<<<dim3(SEQ / 128, NH, 2), 256, ATTN_SMEM>>>(qkv, attn);
    // 4) x1 = x + attn @ w_proj + b_proj (fp32 row-major residual)
    gemm_kernel<false, true, false, false><<<dim3(DIM / 128, NTOK / 128), 128, GEMM_SMEM>>>(
        attn, wproj, b_proj, x, x1, nullptr, NTOK, DIM, DIM);
    // 5) LN2 (fp16 A-frag out)
    ln_kernel<<<NTOK, 256>>>(x1, g2, beta2, h);
    // 6) mid = gelu(h @ w_fc1 + b_fc1)  [4096,1024]x[1024,4096], fp16 A-frag out
    gemm_kernel<true, false, false, true><<<dim3(HIDDEN / 128, NTOK / 128), 128, GEMM_SMEM>>>(
        h, wfc1, b_fc1, nullptr, nullptr, mid, NTOK, HIDDEN, DIM);
    // 7) out = x1 + mid @ w_fc2 + b_fc2  [4096,4096]x[4096,1024], fp32 row-major
    gemm_kernel<false, true, false, false><<<dim3(DIM / 128, NTOK / 128), 128, GEMM_SMEM>>>(
        mid, wfc2, b_fc2, x1, out, nullptr, NTOK, DIM, HIDDEN);
}

// round 15
// speedup vs baseline: 2.1763x; 1.2014x over previous
#include <cuda_runtime.h>
#include <cuda_fp16.h>
#include <cstdint>
#include <math.h>

// ---------------------------------------------------------------------------
// Transformer block: LN1 -> QKV -> causal MHA -> proj(+res) -> LN2 -> FC1+GELU
//                    -> FC2(+res).  B=2, S=2048, D=1024, H=16, hd=64, FF=4096.
// R15: everything tensor-side on fp16 mma.sync m16n8k16.  GEMMs: fragment-
// major operands, 3-stage cp.async (unchanged from R14).  NEW: attention on
// fp16 too (Q/K/P half smem, V transposed in smem), 54KB smem -> 2 CTAs/SM;
// qkv GEMM emits fp16 row-major directly.
// ---------------------------------------------------------------------------

#define DIM    1024
#define HIDDEN 4096
#define SEQ    2048
#define NTOK   4096   // B * S
#define NH     16
#define HD     64

// Scratch (allocation-free rule: device globals)
__device__ __half g_h   [NTOK * DIM];       // LN out, fp16 A-frag (K=DIM)
__device__ __half g_qkv [NTOK * 3 * DIM];   // fp16 row-major (attn input)
__device__ __half g_attn[NTOK * DIM];       // attn out, fp16 A-frag (K=DIM)
__device__ float  g_x1  [NTOK * DIM];       // fp32 row-major residual
__device__ __half g_mid [NTOK * HIDDEN];    // fc1 out, fp16 A-frag (K=HIDDEN)
// fp16 B-frag weights
__device__ __half g_wqkv [DIM * 3 * DIM];
__device__ __half g_wproj[DIM * DIM];
__device__ __half g_wfc1 [DIM * HIDDEN];
__device__ __half g_wfc2 [HIDDEN * DIM];

// ---------------------------------------------------------------------------
// Helpers
// ---------------------------------------------------------------------------
__device__ __forceinline__ void mma16(float c[4], const uint32_t a[4], const uint32_t b[2]) {
    asm volatile(
        "mma.sync.aligned.m16n8k16.row.col.f32.f16.f16.f32 "
        "{%0,%1,%2,%3}, {%4,%5,%6,%7}, {%8,%9}, {%0,%1,%2,%3};"
        : "+f"(c[0]), "+f"(c[1]), "+f"(c[2]), "+f"(c[3])
        : "r"(a[0]), "r"(a[1]), "r"(a[2]), "r"(a[3]), "r"(b[0]), "r"(b[1]));
}

__device__ __forceinline__ void cpa16(uint32_t dst, const void* src) {
    asm volatile("cp.async.cg.shared.global [%0], [%1], 16;" :: "r"(dst), "l"(src) : "memory");
}
#define CP_COMMIT() asm volatile("cp.async.commit_group;" ::: "memory")
#define CP_WAIT1()  asm volatile("cp.async.wait_group 1;" ::: "memory")

__device__ __forceinline__ float gelu_f(float v) {
    return 0.5f * v * (1.0f + erff(v * 0.70710678118654752440f));
}

// ---------------------------------------------------------------------------
// fp16 A-fragment-major addressing (m16n8k16).  M x K halfs, tiles 128(M) x
// 64(K) = 8192 halfs (4096 uint32) contiguous:
//   [kki(4)][wm(2)][mt(4)][lane(32)][reg(4)] uint32s, + low/high half (k&1).
// ---------------------------------------------------------------------------
__device__ __forceinline__ size_t fragA_h(int row, int col, int K) {
    int KT = K >> 6;
    size_t tile = (size_t)(row >> 7) * KT + (col >> 6);
    int r = row & 127, c = col & 63;
    int wm = r >> 6, mt = (r >> 4) & 3, rr = r & 15;
    int kki = c >> 4, cc = c & 15;
    int lane = ((rr & 7) << 2) + ((cc >> 1) & 3);
    int reg  = (rr >> 3) + ((cc >> 3) << 1);
    return (((tile << 12) +
             (size_t)(((((kki << 1) + wm) << 2) + mt) << 7) + (lane << 2) + reg) << 1)
           + (cc & 1);
}

// ---------------------------------------------------------------------------
// Weight relayout: W[K][N] fp32 row-major -> fp16 B-frag tiles (as R14).
// ---------------------------------------------------------------------------
__global__ __launch_bounds__(256) void relayout_wh(
    const float* __restrict__ W, __half* __restrict__ Wt, int N, int K)
{
    int u    = blockIdx.x * 256 + threadIdx.x;
    int e    = u & 3;
    int lane = (u >> 2) & 31;
    int base = (u >> 7) & 31;
    int j = base & 3, wn = (base >> 2) & 1, kki = base >> 3;
    int tile = u >> 12;
    int KT = K >> 6;
    int kt = tile % KT, nb = tile / KT;
    int n = nb * 128 + wn * 64 + ((j << 1) + (e >> 1)) * 8 + (lane >> 2);
    int k = kt * 64 + kki * 16 + ((lane & 3) << 1) + ((e & 1) << 3);
    __half2 h2 = __floats2half2_rn(W[(size_t)k * N + n], W[(size_t)(k + 1) * N + n]);
    *(__half2*)(Wt + ((size_t)u << 1)) = h2;
}

// ---------------------------------------------------------------------------
// LayerNorm: one 256-thread block per row of 1024; fp16 A-frag output.
// ---------------------------------------------------------------------------
__global__ __launch_bounds__(256) void ln_kernel(
    const float* __restrict__ x, const float* __restrict__ g,
    const float* __restrict__ be, __half* __restrict__ out)
{
    const int row = blockIdx.x;
    const int tid = threadIdx.x;
    const float4 v = *(const float4*)(x + (size_t)row * DIM + (tid << 2));
    float s = v.x + v.y + v.z + v.w;
    float q = v.x * v.x + v.y * v.y + v.z * v.z + v.w * v.w;
    #pragma unroll
    for (int off = 16; off; off >>= 1) {
        s += __shfl_xor_sync(0xffffffffu, s, off);
        q += __shfl_xor_sync(0xffffffffu, q, off);
    }
    __shared__ float ss[8], sq[8];
    if ((tid & 31) == 0) { ss[tid >> 5] = s; sq[tid >> 5] = q; }
    __syncthreads();
    float ts = 0.f, tq = 0.f;
    #pragma unroll
    for (int i = 0; i < 8; i++) { ts += ss[i]; tq += sq[i]; }
    const float mu  = ts * (1.0f / DIM);
    const float var = tq * (1.0f / DIM) - mu * mu;
    const float inv = rsqrtf(var + 1e-5f);
    const float4 gg = *(const float4*)(g  + (tid << 2));
    const float4 bb = *(const float4*)(be + (tid << 2));
    const int col = tid << 2;
    *(__half2*)(out + fragA_h(row, col, DIM)) =
        __floats2half2_rn((v.x - mu) * inv * gg.x + bb.x,
                          (v.y - mu) * inv * gg.y + bb.y);
    *(__half2*)(out + fragA_h(row, col + 2, DIM)) =
        __floats2half2_rn((v.z - mu) * inv * gg.z + bb.z,
                          (v.w - mu) * inv * gg.w + bb.w);
}

// ---------------------------------------------------------------------------
// fp16 GEMM: C[M,N] = A @ W + bias (opt GELU / +residual; output fp32-row /
// half-row / half A-frag).  A in fp16 A-frag tiles, W in fp16 B-frag tiles.
// CTA 128x128, k-tile 64 halfs, 3-stage cp.async, one barrier per k-tile.
// 4 warps (2x2), warp tile 64x64 (4x8 m16n8k16).
// ---------------------------------------------------------------------------
#define STG_U32 4096
#define GEMM_SMEM (6 * STG_U32 * 4)        // 98304 B

template <bool GELU_, bool RESID_, bool HROW_, bool FRAGOUT_>
__global__ __launch_bounds__(128, 1) void gemm_kernel(
    const __half* __restrict__ A, const __half* __restrict__ Wt,
    const float* __restrict__ bias, const float* __restrict__ R,
    float* __restrict__ Cf, __half* __restrict__ Ch, int M, int N, int K)
{
    extern __shared__ uint32_t gsm[];
    uint32_t* Asm = gsm;
    uint32_t* Bsm = gsm + 3 * STG_U32;

    const int tid  = threadIdx.x;
    const int warp = tid >> 5, lane = tid & 31;
    const int wm = warp >> 1, wn = warp & 1;
    const int KT = K >> 6;

    const uint32_t As_u = (uint32_t)__cvta_generic_to_shared(Asm);
    const uint32_t Bs_u = (uint32_t)__cvta_generic_to_shared(Bsm);

    float acc[4][8][4];
    #pragma unroll
    for (int i = 0; i < 4; i++)
        #pragma unroll
        for (int j = 0; j < 8; j++)
            #pragma unroll
            for (int k = 0; k < 4; k++) acc[i][j][k] = 0.f;

    auto load_stage = [&](int s, int kt_) {
        const __half* asrc = A  + (((size_t)blockIdx.y * KT + kt_) << 13);
        const __half* bsrc = Wt + (((size_t)blockIdx.x * KT + kt_) << 13);
        #pragma unroll
        for (int i = 0; i < 8; i++) {
            int c = tid + (i << 7);
            cpa16(As_u + (uint32_t)((s * STG_U32 + (c << 2)) << 2), asrc + (c << 3));
            cpa16(Bs_u + (uint32_t)((s * STG_U32 + (c << 2)) << 2), bsrc + (c << 3));
        }
    };

    load_stage(0, 0); CP_COMMIT();
    load_stage(1, 1); CP_COMMIT();

    for (int kt = 0; kt < KT; kt++) {
        CP_WAIT1();
        __syncthreads();
        if (kt + 2 < KT) load_stage((kt + 2) % 3, kt + 2);
        CP_COMMIT();

        const uint32_t* As_ = Asm + (kt % 3) * STG_U32;
        const uint32_t* Bs_ = Bsm + (kt % 3) * STG_U32;

        #pragma unroll
        for (int kki = 0; kki < 4; kki++) {
            uint32_t af[4][4], bf[8][2];
            #pragma unroll
            for (int mt = 0; mt < 4; mt++) {
                uint4 qa = *(const uint4*)(As_ +
                    (size_t)(((((kki << 1) + wm) << 2) + mt) << 7) + (lane << 2));
                af[mt][0] = qa.x; af[mt][1] = qa.y; af[mt][2] = qa.z; af[mt][3] = qa.w;
            }
            #pragma unroll
            for (int j = 0; j < 4; j++) {
                uint4 qb = *(const uint4*)(Bs_ +
                    (size_t)(((((kki << 1) + wn) << 2) + j) << 7) + (lane << 2));
                bf[2 * j    ][0] = qb.x; bf[2 * j    ][1] = qb.y;
                bf[2 * j + 1][0] = qb.z; bf[2 * j + 1][1] = qb.w;
            }
            #pragma unroll
            for (int mt = 0; mt < 4; mt++)
                #pragma unroll
                for (int nt = 0; nt < 8; nt++)
                    mma16(acc[mt][nt], af[mt], bf[nt]);
        }
    }

    // Epilogue
    const int bm = blockIdx.y << 7;
    const int bn = blockIdx.x << 7;
    #pragma unroll
    for (int mt = 0; mt < 4; mt++) {
        #pragma unroll
        for (int nt = 0; nt < 8; nt++) {
            int row0 = bm + (wm << 6) + (mt << 4) + (lane >> 2);
            int col  = bn + (wn << 6) + (nt << 3) + ((lane & 3) << 1);
            const float b0 = __ldg(bias + col);
            const float b1 = __ldg(bias + col + 1);
            #pragma unroll
            for (int half = 0; half < 2; half++) {
                int row = row0 + half * 8;
                float v0 = acc[mt][nt][half * 2 + 0] + b0;
                float v1 = acc[mt][nt][half * 2 + 1] + b1;
                if (GELU_) { v0 = gelu_f(v0); v1 = gelu_f(v1); }
                if (RESID_) {
                    v0 += __ldg(R + (size_t)row * N + col);
                    v1 += __ldg(R + (size_t)row * N + col + 1);
                }
                if (FRAGOUT_) {
                    *(__half2*)(Ch + fragA_h(row, col, N)) = __floats2half2_rn(v0, v1);
                } else if (HROW_) {
                    *(__half2*)(Ch + (size_t)row * N + col) = __floats2half2_rn(v0, v1);
                } else {
                    Cf[(size_t)row * N + col]     = v0;
                    Cf[(size_t)row * N + col + 1] = v1;
                }
            }
        }
    }
}

// ---------------------------------------------------------------------------
// Causal flash attention, fp16 m16n8k16.  qkv fp16 row-major; output fp16
// A-frag (K=DIM).  grid = (S/128, NH, B); 256 threads = 8 warps, each warp
// owns 16 query rows.  KV block 64.  Smem: Q/K/P half [.][72]; V transposed
// Vt[d][kv] so PV B-frags are contiguous half2.  54KB -> 2 CTAs/SM.
// ---------------------------------------------------------------------------
#define ASTR 72
#define ATTN_SMEM (384 * ASTR * 2)   // 55296 B

__global__ __launch_bounds__(256, 2) void attn_kernel(
    const __half* __restrict__ qkv, __half* __restrict__ outp)
{
    extern __shared__ __half smh[];
    __half (*Qs)[ASTR] = (__half(*)[ASTR])(smh);               // 128 q rows
    __half (*Ks)[ASTR] = (__half(*)[ASTR])(smh + 128 * ASTR);  //  64 kv rows
    __half (*Vt)[ASTR] = (__half(*)[ASTR])(smh + 192 * ASTR);  //  64 d rows (transposed)
    __half (*Ps)[ASTR] = (__half(*)[ASTR])(smh + 256 * ASTR);  // 128 q rows

    const int qb = blockIdx.x, h = blockIdx.y, b = blockIdx.z;
    const int tid = threadIdx.x, warp = tid >> 5, lane = tid & 31;
    const int q0 = qb << 7;

    // Load Q block (128 x 64 halfs) as 16B chunks
    const __half* qbase = qkv + (size_t)(b * SEQ + q0) * (3 * DIM) + h * HD;
    #pragma unroll
    for (int i = 0; i < 4; i++) {
        int idx = tid + (i << 8);
        int r = idx >> 3, c = (idx & 7) << 3;
        *(uint4*)&Qs[r][c] = *(const uint4*)(qbase + (size_t)r * (3 * DIM) + c);
    }

    float o[8][4];
    #pragma unroll
    for (int i = 0; i < 8; i++)
        #pragma unroll
        for (int j = 0; j < 4; j++) o[i][j] = 0.f;
    float m0 = -1e30f, m1 = -1e30f, l0 = 0.f, l1 = 0.f;

    const int ar = (warp << 4) + (lane >> 2);   // local q row; +8 for c2/c3
    const int nkb = (q0 >> 6) + 2;              // causal KV-block count

    for (int kb = 0; kb < nkb; kb++) {
        __syncthreads();   // previous K/V fully consumed
        const __half* kptr = qkv + (size_t)(b * SEQ + (kb << 6)) * (3 * DIM) + DIM + h * HD;
        const __half* vptr = kptr + DIM;
        #pragma unroll
        for (int i = 0; i < 2; i++) {
            int idx = tid + (i << 8);
            int r = idx >> 3, c = (idx & 7) << 3;
            *(uint4*)&Ks[r][c] = *(const uint4*)(kptr + (size_t)r * (3 * DIM) + c);
            // V transposed scatter: Vt[d][kv]
            uint4 raw = *(const uint4*)(vptr + (size_t)r * (3 * DIM) + c);
            const __half* vh = (const __half*)&raw;
            #pragma unroll
            for (int j = 0; j < 8; j++) Vt[c + j][r] = vh[j];
        }
        __syncthreads();

        // S = Q @ K^T  (warp: 16 q rows x 64 kv cols, K=64 head dim)
        float s[8][4];
        #pragma unroll
        for (int i = 0; i < 8; i++)
            #pragma unroll
            for (int j = 0; j < 4; j++) s[i][j] = 0.f;

        #pragma unroll
        for (int kki = 0; kki < 4; kki++) {
            const int ck = (kki << 4) + ((lane & 3) << 1);
            uint32_t a[4];
            a[0] = *(const uint32_t*)&Qs[ar    ][ck    ];
            a[1] = *(const uint32_t*)&Qs[ar + 8][ck    ];
            a[2] = *(const uint32_t*)&Qs[ar    ][ck + 8];
            a[3] = *(const uint32_t*)&Qs[ar + 8][ck + 8];
            #pragma unroll
            for (int nt = 0; nt < 8; nt++) {
                int n = (nt << 3) + (lane >> 2);
                uint32_t bfr[2];
                bfr[0] = *(const uint32_t*)&Ks[n][ck    ];
                bfr[1] = *(const uint32_t*)&Ks[n][ck + 8];
                mma16(s[nt], a, bfr);
            }
        }

        // scale + causal mask + online softmax (C-frag layout same as m16n8k8)
        const int grow0 = q0 + ar;
        const int grow1 = grow0 + 8;
        const int cbase = (kb << 6) + ((lane & 3) << 1);
        float mn0 = m0, mn1 = m1;
        #pragma unroll
        for (int nt = 0; nt < 8; nt++) {
            int c0 = cbase + (nt << 3);
            s[nt][0] = (c0     <= grow0) ? s[nt][0] * 0.125f : -1e30f;
            s[nt][1] = (c0 + 1 <= grow0) ? s[nt][1] * 0.125f : -1e30f;
            s[nt][2] = (c0     <= grow1) ? s[nt][2] * 0.125f : -1e30f;
            s[nt][3] = (c0 + 1 <= grow1) ? s[nt][3] * 0.125f : -1e30f;
            mn0 = fmaxf(mn0, fmaxf(s[nt][0], s[nt][1]));
            mn1 = fmaxf(mn1, fmaxf(s[nt][2], s[nt][3]));
        }
        mn0 = fmaxf(mn0, __shfl_xor_sync(0xffffffffu, mn0, 1));
        mn0 = fmaxf(mn0, __shfl_xor_sync(0xffffffffu, mn0, 2));
        mn1 = fmaxf(mn1, __shfl_xor_sync(0xffffffffu, mn1, 1));
        mn1 = fmaxf(mn1, __shfl_xor_sync(0xffffffffu, mn1, 2));

        const float corr0 = __expf(m0 - mn0);
        const float corr1 = __expf(m1 - mn1);
        m0 = mn0; m1 = mn1;

        float rs0 = 0.f, rs1 = 0.f;
        #pragma unroll
        for (int nt = 0; nt < 8; nt++) {
            float p0 = __expf(s[nt][0] - m0);
            float p1 = __expf(s[nt][1] - m0);
            float p2 = __expf(s[nt][2] - m1);
            float p3 = __expf(s[nt][3] - m1);
            rs0 += p0 + p1; rs1 += p2 + p3;
            int pc = (nt << 3) + ((lane & 3) << 1);
            *(__half2*)&Ps[ar    ][pc] = __floats2half2_rn(p0, p1);
            *(__half2*)&Ps[ar + 8][pc] = __floats2half2_rn(p2, p3);
        }
        rs0 += __shfl_xor_sync(0xffffffffu, rs0, 1);
        rs0 += __shfl_xor_sync(0xffffffffu, rs0, 2);
        rs1 += __shfl_xor_sync(0xffffffffu, rs1, 1);
        rs1 += __shfl_xor_sync(0xffffffffu, rs1, 2);
        l0 = l0 * corr0 + rs0;
        l1 = l1 * corr1 + rs1;
        #pragma unroll
        for (int nt = 0; nt < 8; nt++) {
            o[nt][0] *= corr0; o[nt][1] *= corr0;
            o[nt][2] *= corr1; o[nt][3] *= corr1;
        }
        __syncwarp();   // Ps rows are warp-private

        // O += P @ V  (warp: 16 rows x 64 d cols, k = 64 kv)
        #pragma unroll
        for (int kki = 0; kki < 4; kki++) {
            const int ck = (kki << 4) + ((lane & 3) << 1);
            uint32_t a[4];
            a[0] = *(const uint32_t*)&Ps[ar    ][ck    ];
            a[1] = *(const uint32_t*)&Ps[ar + 8][ck    ];
            a[2] = *(const uint32_t*)&Ps[ar    ][ck + 8];
            a[3] = *(const uint32_t*)&Ps[ar + 8][ck + 8];
            #pragma unroll
            for (int nt = 0; nt < 8; nt++) {
                int n = (nt << 3) + (lane >> 2);
                uint32_t bfr[2];
                bfr[0] = *(const uint32_t*)&Vt[n][ck    ];
                bfr[1] = *(const uint32_t*)&Vt[n][ck + 8];
                mma16(o[nt], a, bfr);
            }
        }
    }

    // fp16 A-frag output for proj GEMM (K = DIM)
    const float inv0 = 1.0f / l0;
    const float inv1 = 1.0f / l1;
    const int row0 = b * SEQ + q0 + ar;
    const int row1 = row0 + 8;
    #pragma unroll
    for (int nt = 0; nt < 8; nt++) {
        int col = h * HD + (nt << 3) + ((lane & 3) << 1);
        *(__half2*)(outp + fragA_h(row0, col, DIM)) =
            __floats2half2_rn(o[nt][0] * inv0, o[nt][1] * inv0);
        *(__half2*)(outp + fragA_h(row1, col, DIM)) =
            __floats2half2_rn(o[nt][2] * inv1, o[nt][3] * inv1);
    }
}

// ---------------------------------------------------------------------------
// Launch
// ---------------------------------------------------------------------------
extern "C" void kernel_launch(void* const* d_in, const int* in_sizes, int n_in,
                              void* d_out, int out_size)
{
    const float* x      = (const float*)d_in[0];
    const float* w_qkv  = (const float*)d_in[1];
    const float* b_qkv  = (const float*)d_in[2];
    const float* w_proj = (const float*)d_in[3];
    const float* b_proj = (const float*)d_in[4];
    const float* g1     = (const float*)d_in[5];
    const float* beta1  = (const float*)d_in[6];
    const float* g2     = (const float*)d_in[7];
    const float* beta2  = (const float*)d_in[8];
    const float* w_fc1  = (const float*)d_in[9];
    const float* b_fc1  = (const float*)d_in[10];
    const float* w_fc2  = (const float*)d_in[11];
    const float* b_fc2  = (const float*)d_in[12];
    float* out = (float*)d_out;

    __half *h, *qkv, *attn, *mid, *wqkv, *wproj, *wfc1, *wfc2;
    float *x1;
    cudaGetSymbolAddress((void**)&h,     g_h);
    cudaGetSymbolAddress((void**)&qkv,   g_qkv);
    cudaGetSymbolAddress((void**)&attn,  g_attn);
    cudaGetSymbolAddress((void**)&x1,    g_x1);
    cudaGetSymbolAddress((void**)&mid,   g_mid);
    cudaGetSymbolAddress((void**)&wqkv,  g_wqkv);
    cudaGetSymbolAddress((void**)&wproj, g_wproj);
    cudaGetSymbolAddress((void**)&wfc1,  g_wfc1);
    cudaGetSymbolAddress((void**)&wfc2,  g_wfc2);

    cudaFuncSetAttribute(attn_kernel, cudaFuncAttributeMaxDynamicSharedMemorySize, ATTN_SMEM);
    cudaFuncSetAttribute(gemm_kernel<false, false, true, false>,
                         cudaFuncAttributeMaxDynamicSharedMemorySize, GEMM_SMEM);
    cudaFuncSetAttribute(gemm_kernel<false, true, false, false>,
                         cudaFuncAttributeMaxDynamicSharedMemorySize, GEMM_SMEM);
    cudaFuncSetAttribute(gemm_kernel<true, false, false, true>,
                         cudaFuncAttributeMaxDynamicSharedMemorySize, GEMM_SMEM);

    // 0) Weight relayout to fp16 B-frag (once per call)
    relayout_wh<<<(DIM * 3 * DIM / 2) / 256, 256>>>(w_qkv,  wqkv,  3 * DIM, DIM);
    relayout_wh<<<(DIM * DIM / 2)     / 256, 256>>>(w_proj, wproj, DIM,     DIM);
    relayout_wh<<<(DIM * HIDDEN / 2)  / 256, 256>>>(w_fc1,  wfc1,  HIDDEN,  DIM);
    relayout_wh<<<(HIDDEN * DIM / 2)  / 256, 256>>>(w_fc2,  wfc2,  DIM,     HIDDEN);

    // 1) LN1 (fp16 A-frag out)
    ln_kernel<<<NTOK, 256>>>(x, g1, beta1, h);
    // 2) QKV = h @ w_qkv + b_qkv  [4096,1024]x[1024,3072], fp16 row-major out
    gemm_kernel<false, false, true, false><<<dim3(3 * DIM / 128, NTOK / 128), 128, GEMM_SMEM>>>(
        h, wqkv, b_qkv, nullptr, nullptr, qkv, NTOK, 3 * DIM, DIM);
    // 3) Causal MHA (fp16 in, fp16 A-frag out)
    attn_kernel<<<dim3(SEQ / 128, NH, 2), 256, ATTN_SMEM>>>(qkv, attn);
    // 4) x1 = x + attn @ w_proj + b_proj (fp32 row-major residual)
    gemm_kernel<false, true, false, false><<<dim3(DIM / 128, NTOK / 128), 128, GEMM_SMEM>>>(
        attn, wproj, b_proj, x, x1, nullptr, NTOK, DIM, DIM);
    // 5) LN2 (fp16 A-frag out)
    ln_kernel<<<NTOK, 256>>>(x1, g2, beta2, h);
    // 6) mid = gelu(h @ w_fc1 + b_fc1)  [4096,1024]x[1024,4096], fp16 A-frag out
    gemm_kernel<true, false, false, true><<<dim3(HIDDEN / 128, NTOK / 128), 128, GEMM_SMEM>>>(
        h, wfc1, b_fc1, nullptr, nullptr, mid, NTOK, HIDDEN, DIM);
    // 7) out = x1 + mid @ w_fc2 + b_fc2  [4096,4096]x[4096,1024], fp32 row-major
    gemm_kernel<false, true, false, false><<<dim3(DIM / 128, NTOK / 128), 128, GEMM_SMEM>>>(
        mid, wfc2, b_fc2, x1, out, nullptr, NTOK, DIM, HIDDEN);
}

// round 16
// speedup vs baseline: 2.2819x; 1.0485x over previous
#include <cuda_runtime.h>
#include <cuda_fp16.h>
#include <cstdint>
#include <math.h>

// ---------------------------------------------------------------------------
// Transformer block: LN1 -> QKV -> causal MHA -> proj(+res) -> LN2 -> FC1+GELU
//                    -> FC2(+res).  B=2, S=2048, D=1024, H=16, hd=64, FF=4096.
// R16: fp16 m16n8k16 everywhere (R15 structure).  NEW: (a) weight relayout
// split into smem-tiled transpose + coalesced fragpack (was a 4x-amplified
// gather); (b) attention keeps V row-major in smem (conflict-free fill) and
// gathers PV B-fragments via LDS.U16, removing the 8-way-conflict Vt scatter.
// ---------------------------------------------------------------------------

#define DIM    1024
#define HIDDEN 4096
#define SEQ    2048
#define NTOK   4096   // B * S
#define NH     16
#define HD     64

// Scratch (allocation-free rule: device globals)
__device__ __half g_h   [NTOK * DIM];       // LN out, fp16 A-frag (K=DIM)
__device__ __half g_qkv [NTOK * 3 * DIM];   // fp16 row-major (attn input)
__device__ __half g_attn[NTOK * DIM];       // attn out, fp16 A-frag (K=DIM)
__device__ float  g_x1  [NTOK * DIM];       // fp32 row-major residual
__device__ __half g_mid [NTOK * HIDDEN];    // fc1 out A-frag; ALSO temp for W^T
// fp16 B-frag weights
__device__ __half g_wqkv [DIM * 3 * DIM];
__device__ __half g_wproj[DIM * DIM];
__device__ __half g_wfc1 [DIM * HIDDEN];
__device__ __half g_wfc2 [HIDDEN * DIM];

// ---------------------------------------------------------------------------
// Helpers
// ---------------------------------------------------------------------------
__device__ __forceinline__ void mma16(float c[4], const uint32_t a[4], const uint32_t b[2]) {
    asm volatile(
        "mma.sync.aligned.m16n8k16.row.col.f32.f16.f16.f32 "
        "{%0,%1,%2,%3}, {%4,%5,%6,%7}, {%8,%9}, {%0,%1,%2,%3};"
        : "+f"(c[0]), "+f"(c[1]), "+f"(c[2]), "+f"(c[3])
        : "r"(a[0]), "r"(a[1]), "r"(a[2]), "r"(a[3]), "r"(b[0]), "r"(b[1]));
}

__device__ __forceinline__ void cpa16(uint32_t dst, const void* src) {
    asm volatile("cp.async.cg.shared.global [%0], [%1], 16;" :: "r"(dst), "l"(src) : "memory");
}
#define CP_COMMIT() asm volatile("cp.async.commit_group;" ::: "memory")
#define CP_WAIT1()  asm volatile("cp.async.wait_group 1;" ::: "memory")

__device__ __forceinline__ float gelu_f(float v) {
    return 0.5f * v * (1.0f + erff(v * 0.70710678118654752440f));
}

// ---------------------------------------------------------------------------
// fp16 A-fragment-major addressing (m16n8k16): tiles 128(M) x 64(K) = 8192
// halfs contiguous: [kki(4)][wm(2)][mt(4)][lane(32)][reg(4)] u32 + (k&1).
// ---------------------------------------------------------------------------
__device__ __forceinline__ size_t fragA_h(int row, int col, int K) {
    int KT = K >> 6;
    size_t tile = (size_t)(row >> 7) * KT + (col >> 6);
    int r = row & 127, c = col & 63;
    int wm = r >> 6, mt = (r >> 4) & 3, rr = r & 15;
    int kki = c >> 4, cc = c & 15;
    int lane = ((rr & 7) << 2) + ((cc >> 1) & 3);
    int reg  = (rr >> 3) + ((cc >> 3) << 1);
    return (((tile << 12) +
             (size_t)(((((kki << 1) + wm) << 2) + mt) << 7) + (lane << 2) + reg) << 1)
           + (cc & 1);
}

// ---------------------------------------------------------------------------
// Phase 1: smem-tiled transpose + fp16 round.  W[K][N] fp32 -> T[N][K] half.
// Block 256 threads, 32x32 tile, pad 34 halfs -> conflict-free.
// ---------------------------------------------------------------------------
__global__ __launch_bounds__(256) void transpose_h(
    const float* __restrict__ W, __half* __restrict__ T, int K, int N)
{
    __shared__ __half t[32][34];
    const int k0 = blockIdx.x << 5, n0 = blockIdx.y << 5;
    const int tx = threadIdx.x & 31, ty = threadIdx.x >> 5;  // 32 x 8
    #pragma unroll
    for (int j = 0; j < 32; j += 8)
        t[ty + j][tx] = __float2half_rn(W[(size_t)(k0 + ty + j) * N + n0 + tx]);
    __syncthreads();
    #pragma unroll
    for (int j = 0; j < 32; j += 8)
        T[(size_t)(n0 + ty + j) * K + k0 + tx] = t[tx][ty + j];
}

// ---------------------------------------------------------------------------
// Phase 2: fragpack.  T[N][K] half row-major -> B-frag tiles (same layout as
// R15's relayout_wh).  One block per 64K x 128N tile (4096 u32); reads are
// contiguous 32B runs per n-row, writes fully coalesced.  Merged 4 weights.
// ---------------------------------------------------------------------------
__global__ __launch_bounds__(256) void fragpack(
    const __half* __restrict__ t0, __half* __restrict__ d0, int K0,
    const __half* __restrict__ t1, __half* __restrict__ d1, int K1,
    const __half* __restrict__ t2, __half* __restrict__ d2, int K2,
    const __half* __restrict__ t3, __half* __restrict__ d3, int K3,
    int c0, int c1, int c2)   // prefix tile counts (end of weights 0,1,2)
{
    int gt = blockIdx.x;
    const __half* T; __half* D; int K, lt;
    if      (gt < c0) { T = t0; D = d0; K = K0; lt = gt; }
    else if (gt < c1) { T = t1; D = d1; K = K1; lt = gt - c0; }
    else if (gt < c2) { T = t2; D = d2; K = K2; lt = gt - c1; }
    else              { T = t3; D = d3; K = K3; lt = gt - c2; }
    const int KT = K >> 6;
    const int kt = lt % KT, nb = lt / KT;
    const int tid = threadIdx.x;
    uint32_t* __restrict__ Du = (uint32_t*)D;
    #pragma unroll
    for (int s = 0; s < 16; s++) {
        int u = (s << 8) + tid;                  // u32 index within tile
        int e    = u & 3;
        int ln   = (u >> 2) & 31;
        int j    = (u >> 7) & 3;
        int wn   = (u >> 9) & 1;
        int kki  = (u >> 10) & 3;
        int n = nb * 128 + wn * 64 + (((j << 1) + (e >> 1)) << 3) + (ln >> 2);
        int k = kt * 64 + (kki << 4) + ((ln & 3) << 1) + ((e & 1) << 3);
        uint32_t v = *(const uint32_t*)(T + (size_t)n * K + k);
        Du[((size_t)lt << 12) + u] = v;
    }
}

// ---------------------------------------------------------------------------
// LayerNorm: one 256-thread block per row of 1024; fp16 A-frag output.
// ---------------------------------------------------------------------------
__global__ __launch_bounds__(256) void ln_kernel(
    const float* __restrict__ x, const float* __restrict__ g,
    const float* __restrict__ be, __half* __restrict__ out)
{
    const int row = blockIdx.x;
    const int tid = threadIdx.x;
    const float4 v = *(const float4*)(x + (size_t)row * DIM + (tid << 2));
    float s = v.x + v.y + v.z + v.w;
    float q = v.x * v.x + v.y * v.y + v.z * v.z + v.w * v.w;
    #pragma unroll
    for (int off = 16; off; off >>= 1) {
        s += __shfl_xor_sync(0xffffffffu, s, off);
        q += __shfl_xor_sync(0xffffffffu, q, off);
    }
    __shared__ float ss[8], sq[8];
    if ((tid & 31) == 0) { ss[tid >> 5] = s; sq[tid >> 5] = q; }
    __syncthreads();
    float ts = 0.f, tq = 0.f;
    #pragma unroll
    for (int i = 0; i < 8; i++) { ts += ss[i]; tq += sq[i]; }
    const float mu  = ts * (1.0f / DIM);
    const float var = tq * (1.0f / DIM) - mu * mu;
    const float inv = rsqrtf(var + 1e-5f);
    const float4 gg = *(const float4*)(g  + (tid << 2));
    const float4 bb = *(const float4*)(be + (tid << 2));
    const int col = tid << 2;
    *(__half2*)(out + fragA_h(row, col, DIM)) =
        __floats2half2_rn((v.x - mu) * inv * gg.x + bb.x,
                          (v.y - mu) * inv * gg.y + bb.y);
    *(__half2*)(out + fragA_h(row, col + 2, DIM)) =
        __floats2half2_rn((v.z - mu) * inv * gg.z + bb.z,
                          (v.w - mu) * inv * gg.w + bb.w);
}

// ---------------------------------------------------------------------------
// fp16 GEMM: C[M,N] = A @ W + bias (opt GELU / +residual; output fp32-row /
// half-row / half A-frag).  A in fp16 A-frag tiles, W in fp16 B-frag tiles.
// CTA 128x128, k-tile 64 halfs, 3-stage cp.async, one barrier per k-tile.
// 4 warps (2x2), warp tile 64x64 (4x8 m16n8k16).
// ---------------------------------------------------------------------------
#define STG_U32 4096
#define GEMM_SMEM (6 * STG_U32 * 4)        // 98304 B

template <bool GELU_, bool RESID_, bool HROW_, bool FRAGOUT_>
__global__ __launch_bounds__(128, 1) void gemm_kernel(
    const __half* __restrict__ A, const __half* __restrict__ Wt,
    const float* __restrict__ bias, const float* __restrict__ R,
    float* __restrict__ Cf, __half* __restrict__ Ch, int M, int N, int K)
{
    extern __shared__ uint32_t gsm[];
    uint32_t* Asm = gsm;
    uint32_t* Bsm = gsm + 3 * STG_U32;

    const int tid  = threadIdx.x;
    const int warp = tid >> 5, lane = tid & 31;
    const int wm = warp >> 1, wn = warp & 1;
    const int KT = K >> 6;

    const uint32_t As_u = (uint32_t)__cvta_generic_to_shared(Asm);
    const uint32_t Bs_u = (uint32_t)__cvta_generic_to_shared(Bsm);

    float acc[4][8][4];
    #pragma unroll
    for (int i = 0; i < 4; i++)
        #pragma unroll
        for (int j = 0; j < 8; j++)
            #pragma unroll
            for (int k = 0; k < 4; k++) acc[i][j][k] = 0.f;

    auto load_stage = [&](int s, int kt_) {
        const __half* asrc = A  + (((size_t)blockIdx.y * KT + kt_) << 13);
        const __half* bsrc = Wt + (((size_t)blockIdx.x * KT + kt_) << 13);
        #pragma unroll
        for (int i = 0; i < 8; i++) {
            int c = tid + (i << 7);
            cpa16(As_u + (uint32_t)((s * STG_U32 + (c << 2)) << 2), asrc + (c << 3));
            cpa16(Bs_u + (uint32_t)((s * STG_U32 + (c << 2)) << 2), bsrc + (c << 3));
        }
    };

    load_stage(0, 0); CP_COMMIT();
    load_stage(1, 1); CP_COMMIT();

    for (int kt = 0; kt < KT; kt++) {
        CP_WAIT1();
        __syncthreads();
        if (kt + 2 < KT) load_stage((kt + 2) % 3, kt + 2);
        CP_COMMIT();

        const uint32_t* As_ = Asm + (kt % 3) * STG_U32;
        const uint32_t* Bs_ = Bsm + (kt % 3) * STG_U32;

        #pragma unroll
        for (int kki = 0; kki < 4; kki++) {
            uint32_t af[4][4], bf[8][2];
            #pragma unroll
            for (int mt = 0; mt < 4; mt++) {
                uint4 qa = *(const uint4*)(As_ +
                    (size_t)(((((kki << 1) + wm) << 2) + mt) << 7) + (lane << 2));
                af[mt][0] = qa.x; af[mt][1] = qa.y; af[mt][2] = qa.z; af[mt][3] = qa.w;
            }
            #pragma unroll
            for (int j = 0; j < 4; j++) {
                uint4 qb = *(const uint4*)(Bs_ +
                    (size_t)(((((kki << 1) + wn) << 2) + j) << 7) + (lane << 2));
                bf[2 * j    ][0] = qb.x; bf[2 * j    ][1] = qb.y;
                bf[2 * j + 1][0] = qb.z; bf[2 * j + 1][1] = qb.w;
            }
            #pragma unroll
            for (int mt = 0; mt < 4; mt++)
                #pragma unroll
                for (int nt = 0; nt < 8; nt++)
                    mma16(acc[mt][nt], af[mt], bf[nt]);
        }
    }

    // Epilogue
    const int bm = blockIdx.y << 7;
    const int bn = blockIdx.x << 7;
    #pragma unroll
    for (int mt = 0; mt < 4; mt++) {
        #pragma unroll
        for (int nt = 0; nt < 8; nt++) {
            int row0 = bm + (wm << 6) + (mt << 4) + (lane >> 2);
            int col  = bn + (wn << 6) + (nt << 3) + ((lane & 3) << 1);
            const float b0 = __ldg(bias + col);
            const float b1 = __ldg(bias + col + 1);
            #pragma unroll
            for (int half = 0; half < 2; half++) {
                int row = row0 + half * 8;
                float v0 = acc[mt][nt][half * 2 + 0] + b0;
                float v1 = acc[mt][nt][half * 2 + 1] + b1;
                if (GELU_) { v0 = gelu_f(v0); v1 = gelu_f(v1); }
                if (RESID_) {
                    v0 += __ldg(R + (size_t)row * N + col);
                    v1 += __ldg(R + (size_t)row * N + col + 1);
                }
                if (FRAGOUT_) {
                    *(__half2*)(Ch + fragA_h(row, col, N)) = __floats2half2_rn(v0, v1);
                } else if (HROW_) {
                    *(__half2*)(Ch + (size_t)row * N + col) = __floats2half2_rn(v0, v1);
                } else {
                    Cf[(size_t)row * N + col]     = v0;
                    Cf[(size_t)row * N + col + 1] = v1;
                }
            }
        }
    }
}

// ---------------------------------------------------------------------------
// Causal flash attention, fp16 m16n8k16.  qkv fp16 row-major; output fp16
// A-frag (K=DIM).  grid = (S/128, NH, B); 256 threads = 8 warps.  KV blk 64.
// Smem: Q/K/V/P half [.][72]; V kept ROW-MAJOR (conflict-free uint4 fill);
// PV B-frags gathered via LDS.U16 (broadcast/subword reads, conflict-free).
// ---------------------------------------------------------------------------
#define ASTR 72
#define ATTN_SMEM (384 * ASTR * 2)   // 55296 B

__global__ __launch_bounds__(256, 2) void attn_kernel(
    const __half* __restrict__ qkv, __half* __restrict__ outp)
{
    extern __shared__ __half smh[];
    __half (*Qs)[ASTR] = (__half(*)[ASTR])(smh);               // 128 q rows
    __half (*Ks)[ASTR] = (__half(*)[ASTR])(smh + 128 * ASTR);  //  64 kv rows
    __half (*Vs)[ASTR] = (__half(*)[ASTR])(smh + 192 * ASTR);  //  64 kv rows (row-major)
    __half (*Ps)[ASTR] = (__half(*)[ASTR])(smh + 256 * ASTR);  // 128 q rows

    const int qb = blockIdx.x, h = blockIdx.y, b = blockIdx.z;
    const int tid = threadIdx.x, warp = tid >> 5, lane = tid & 31;
    const int q0 = qb << 7;

    // Load Q block (128 x 64 halfs) as 16B chunks
    const __half* qbase = qkv + (size_t)(b * SEQ + q0) * (3 * DIM) + h * HD;
    #pragma unroll
    for (int i = 0; i < 4; i++) {
        int idx = tid + (i << 8);
        int r = idx >> 3, c = (idx & 7) << 3;
        *(uint4*)&Qs[r][c] = *(const uint4*)(qbase + (size_t)r * (3 * DIM) + c);
    }

    float o[8][4];
    #pragma unroll
    for (int i = 0; i < 8; i++)
        #pragma unroll
        for (int j = 0; j < 4; j++) o[i][j] = 0.f;
    float m0 = -1e30f, m1 = -1e30f, l0 = 0.f, l1 = 0.f;

    const int ar = (warp << 4) + (lane >> 2);   // local q row; +8 for c2/c3
    const int nkb = (q0 >> 6) + 2;              // causal KV-block count

    for (int kb = 0; kb < nkb; kb++) {
        __syncthreads();   // previous K/V fully consumed
        const __half* kptr = qkv + (size_t)(b * SEQ + (kb << 6)) * (3 * DIM) + DIM + h * HD;
        const __half* vptr = kptr + DIM;
        #pragma unroll
        for (int i = 0; i < 2; i++) {
            int idx = tid + (i << 8);
            int r = idx >> 3, c = (idx & 7) << 3;
            *(uint4*)&Ks[r][c] = *(const uint4*)(kptr + (size_t)r * (3 * DIM) + c);
            *(uint4*)&Vs[r][c] = *(const uint4*)(vptr + (size_t)r * (3 * DIM) + c);
        }
        __syncthreads();

        // S = Q @ K^T  (warp: 16 q rows x 64 kv cols, K=64 head dim)
        float s[8][4];
        #pragma unroll
        for (int i = 0; i < 8; i++)
            #pragma unroll
            for (int j = 0; j < 4; j++) s[i][j] = 0.f;

        #pragma unroll
        for (int kki = 0; kki < 4; kki++) {
            const int ck = (kki << 4) + ((lane & 3) << 1);
            uint32_t a[4];
            a[0] = *(const uint32_t*)&Qs[ar    ][ck    ];
            a[1] = *(const uint32_t*)&Qs[ar + 8][ck    ];
            a[2] = *(const uint32_t*)&Qs[ar    ][ck + 8];
            a[3] = *(const uint32_t*)&Qs[ar + 8][ck + 8];
            #pragma unroll
            for (int nt = 0; nt < 8; nt++) {
                int n = (nt << 3) + (lane >> 2);
                uint32_t bfr[2];
                bfr[0] = *(const uint32_t*)&Ks[n][ck    ];
                bfr[1] = *(const uint32_t*)&Ks[n][ck + 8];
                mma16(s[nt], a, bfr);
            }
        }

        // scale + causal mask + online softmax
        const int grow0 = q0 + ar;
        const int grow1 = grow0 + 8;
        const int cbase = (kb << 6) + ((lane & 3) << 1);
        float mn0 = m0, mn1 = m1;
        #pragma unroll
        for (int nt = 0; nt < 8; nt++) {
            int c0 = cbase + (nt << 3);
            s[nt][0] = (c0     <= grow0) ? s[nt][0] * 0.125f : -1e30f;
            s[nt][1] = (c0 + 1 <= grow0) ? s[nt][1] * 0.125f : -1e30f;
            s[nt][2] = (c0     <= grow1) ? s[nt][2] * 0.125f : -1e30f;
            s[nt][3] = (c0 + 1 <= grow1) ? s[nt][3] * 0.125f : -1e30f;
            mn0 = fmaxf(mn0, fmaxf(s[nt][0], s[nt][1]));
            mn1 = fmaxf(mn1, fmaxf(s[nt][2], s[nt][3]));
        }
        mn0 = fmaxf(mn0, __shfl_xor_sync(0xffffffffu, mn0, 1));
        mn0 = fmaxf(mn0, __shfl_xor_sync(0xffffffffu, mn0, 2));
        mn1 = fmaxf(mn1, __shfl_xor_sync(0xffffffffu, mn1, 1));
        mn1 = fmaxf(mn1, __shfl_xor_sync(0xffffffffu, mn1, 2));

        const float corr0 = __expf(m0 - mn0);
        const float corr1 = __expf(m1 - mn1);
        m0 = mn0; m1 = mn1;

        float rs0 = 0.f, rs1 = 0.f;
        #pragma unroll
        for (int nt = 0; nt < 8; nt++) {
            float p0 = __expf(s[nt][0] - m0);
            float p1 = __expf(s[nt][1] - m0);
            float p2 = __expf(s[nt][2] - m1);
            float p3 = __expf(s[nt][3] - m1);
            rs0 += p0 + p1; rs1 += p2 + p3;
            int pc = (nt << 3) + ((lane & 3) << 1);
            *(__half2*)&Ps[ar    ][pc] = __floats2half2_rn(p0, p1);
            *(__half2*)&Ps[ar + 8][pc] = __floats2half2_rn(p2, p3);
        }
        rs0 += __shfl_xor_sync(0xffffffffu, rs0, 1);
        rs0 += __shfl_xor_sync(0xffffffffu, rs0, 2);
        rs1 += __shfl_xor_sync(0xffffffffu, rs1, 1);
        rs1 += __shfl_xor_sync(0xffffffffu, rs1, 2);
        l0 = l0 * corr0 + rs0;
        l1 = l1 * corr1 + rs1;
        #pragma unroll
        for (int nt = 0; nt < 8; nt++) {
            o[nt][0] *= corr0; o[nt][1] *= corr0;
            o[nt][2] *= corr1; o[nt][3] *= corr1;
        }
        __syncwarp();   // Ps rows are warp-private

        // O += P @ V  (B-frag gathered from row-major Vs: B[k=kv][n=d])
        #pragma unroll
        for (int kki = 0; kki < 4; kki++) {
            const int ck = (kki << 4) + ((lane & 3) << 1);
            uint32_t a[4];
            a[0] = *(const uint32_t*)&Ps[ar    ][ck    ];
            a[1] = *(const uint32_t*)&Ps[ar + 8][ck    ];
            a[2] = *(const uint32_t*)&Ps[ar    ][ck + 8];
            a[3] = *(const uint32_t*)&Ps[ar + 8][ck + 8];
            #pragma unroll
            for (int nt = 0; nt < 8; nt++) {
                int n = (nt << 3) + (lane >> 2);
                __half2 b0 = __halves2half2(Vs[ck    ][n], Vs[ck + 1][n]);
                __half2 b1 = __halves2half2(Vs[ck + 8][n], Vs[ck + 9][n]);
                uint32_t bfr[2];
                bfr[0] = *(const uint32_t*)&b0;
                bfr[1] = *(const uint32_t*)&b1;
                mma16(o[nt], a, bfr);
            }
        }
    }

    // fp16 A-frag output for proj GEMM (K = DIM)
    const float inv0 = 1.0f / l0;
    const float inv1 = 1.0f / l1;
    const int row0 = b * SEQ + q0 + ar;
    const int row1 = row0 + 8;
    #pragma unroll
    for (int nt = 0; nt < 8; nt++) {
        int col = h * HD + (nt << 3) + ((lane & 3) << 1);
        *(__half2*)(outp + fragA_h(row0, col, DIM)) =
            __floats2half2_rn(o[nt][0] * inv0, o[nt][1] * inv0);
        *(__half2*)(outp + fragA_h(row1, col, DIM)) =
            __floats2half2_rn(o[nt][2] * inv1, o[nt][3] * inv1);
    }
}

// ---------------------------------------------------------------------------
// Launch
// ---------------------------------------------------------------------------
extern "C" void kernel_launch(void* const* d_in, const int* in_sizes, int n_in,
                              void* d_out, int out_size)
{
    const float* x      = (const float*)d_in[0];
    const float* w_qkv  = (const float*)d_in[1];
    const float* b_qkv  = (const float*)d_in[2];
    const float* w_proj = (const float*)d_in[3];
    const float* b_proj = (const float*)d_in[4];
    const float* g1     = (const float*)d_in[5];
    const float* beta1  = (const float*)d_in[6];
    const float* g2     = (const float*)d_in[7];
    const float* beta2  = (const float*)d_in[8];
    const float* w_fc1  = (const float*)d_in[9];
    const float* b_fc1  = (const float*)d_in[10];
    const float* w_fc2  = (const float*)d_in[11];
    const float* b_fc2  = (const float*)d_in[12];
    float* out = (float*)d_out;

    __half *h, *qkv, *attn, *mid, *wqkv, *wproj, *wfc1, *wfc2;
    float *x1;
    cudaGetSymbolAddress((void**)&h,     g_h);
    cudaGetSymbolAddress((void**)&qkv,   g_qkv);
    cudaGetSymbolAddress((void**)&attn,  g_attn);
    cudaGetSymbolAddress((void**)&x1,    g_x1);
    cudaGetSymbolAddress((void**)&mid,   g_mid);
    cudaGetSymbolAddress((void**)&wqkv,  g_wqkv);
    cudaGetSymbolAddress((void**)&wproj, g_wproj);
    cudaGetSymbolAddress((void**)&wfc1,  g_wfc1);
    cudaGetSymbolAddress((void**)&wfc2,  g_wfc2);

    cudaFuncSetAttribute(attn_kernel, cudaFuncAttributeMaxDynamicSharedMemorySize, ATTN_SMEM);
    cudaFuncSetAttribute(gemm_kernel<false, false, true, false>,
                         cudaFuncAttributeMaxDynamicSharedMemorySize, GEMM_SMEM);
    cudaFuncSetAttribute(gemm_kernel<false, true, false, false>,
                         cudaFuncAttributeMaxDynamicSharedMemorySize, GEMM_SMEM);
    cudaFuncSetAttribute(gemm_kernel<true, false, false, true>,
                         cudaFuncAttributeMaxDynamicSharedMemorySize, GEMM_SMEM);

    // 0) Weight prep: transpose to half [N][K] in g_mid temp, then fragpack.
    //    (g_mid is free until fc1; sizes: 3.1M+1M+4.2M+4.2M = 12.6M halfs < 16.8M)
    __half* tq = mid;
    __half* tp = tq + (size_t)3 * DIM * DIM;
    __half* t1 = tp + (size_t)DIM * DIM;
    __half* t2 = t1 + (size_t)DIM * HIDDEN;
    transpose_h<<<dim3(DIM / 32, 3 * DIM / 32), 256>>>(w_qkv,  tq, DIM,    3 * DIM);
    transpose_h<<<dim3(DIM / 32, DIM / 32),     256>>>(w_proj, tp, DIM,    DIM);
    transpose_h<<<dim3(DIM / 32, HIDDEN / 32),  256>>>(w_fc1,  t1, DIM,    HIDDEN);
    transpose_h<<<dim3(HIDDEN / 32, DIM / 32),  256>>>(w_fc2,  t2, HIDDEN, DIM);
    // tiles: qkv 384, proj 128, fc1 512, fc2 512 -> 1536 total
    fragpack<<<1536, 256>>>(tq, wqkv, DIM,  tp, wproj, DIM,
                            t1, wfc1, DIM,  t2, wfc2, HIDDEN,
                            384, 512, 1024);

    // 1) LN1 (fp16 A-frag out)
    ln_kernel<<<NTOK, 256>>>(x, g1, beta1, h);
    // 2) QKV = h @ w_qkv + b_qkv  [4096,1024]x[1024,3072], fp16 row-major out
    gemm_kernel<false, false, true, false><<<dim3(3 * DIM / 128, NTOK / 128), 128, GEMM_SMEM>>>(
        h, wqkv, b_qkv, nullptr, nullptr, qkv, NTOK, 3 * DIM, DIM);
    // 3) Causal MHA (fp16 in, fp16 A-frag out)
    attn_kernel<<<dim3(SEQ / 128, NH, 2), 256, ATTN_SMEM>>>(qkv, attn);
    // 4) x1 = x + attn @ w_proj + b_proj (fp32 row-major residual)
    gemm_kernel<false, true, false, false><<<dim3(DIM / 128, NTOK / 128), 128, GEMM_SMEM>>>(
        attn, wproj, b_proj, x, x1, nullptr, NTOK, DIM, DIM);
    // 5) LN2 (fp16 A-frag out)
    ln_kernel<<<NTOK, 256>>>(x1, g2, beta2, h);
    // 6) mid = gelu(h @ w_fc1 + b_fc1)  [4096,1024]x[1024,4096], fp16 A-frag out
    gemm_kernel<true, false, false, true><<<dim3(HIDDEN / 128, NTOK / 128), 128, GEMM_SMEM>>>(
        h, wfc1, b_fc1, nullptr, nullptr, mid, NTOK, HIDDEN, DIM);
    // 7) out = x1 + mid @ w_fc2 + b_fc2  [4096,4096]x[4096,1024], fp32 row-major
    gemm_kernel<false, true, false, false><<<dim3(DIM / 128, NTOK / 128), 128, GEMM_SMEM>>>(
        mid, wfc2, b_fc2, x1, out, nullptr, NTOK, DIM, HIDDEN);
}

// round 17
// speedup vs baseline: 2.5596x; 1.1217x over previous
#include <cuda_runtime.h>
#include <cuda_fp16.h>
#include <cstdint>
#include <math.h>

// ---------------------------------------------------------------------------
// Transformer block: LN1 -> QKV -> causal MHA -> proj(+res) -> LN2 -> FC1+GELU
//                    -> FC2(+res).  B=2, S=2048, D=1024, H=16, hd=64, FF=4096.
// R17: fp16 m16n8k16 everywhere.  NEW vs R16:
//  (a) attention keeps P in registers (S C-frag == P A-frag layout), no Ps
//      smem, no __syncwarp; Q/K/V fragments via ldmatrix (V with .trans from
//      row-major smem);  smem 54KB -> 36.9KB.
//  (b) weight prep fused into ONE kernel (gmem->smem transpose->fragpack).
// ---------------------------------------------------------------------------

#define DIM    1024
#define HIDDEN 4096
#define SEQ    2048
#define NTOK   4096   // B * S
#define NH     16
#define HD     64

// Scratch (allocation-free rule: device globals)
__device__ __half g_h   [NTOK * DIM];       // LN out, fp16 A-frag (K=DIM)
__device__ __half g_qkv [NTOK * 3 * DIM];   // fp16 row-major (attn input)
__device__ __half g_attn[NTOK * DIM];       // attn out, fp16 A-frag (K=DIM)
__device__ float  g_x1  [NTOK * DIM];       // fp32 row-major residual
__device__ __half g_mid [NTOK * HIDDEN];    // fc1 out, fp16 A-frag (K=HIDDEN)
// fp16 B-frag weights
__device__ __half g_wqkv [DIM * 3 * DIM];
__device__ __half g_wproj[DIM * DIM];
__device__ __half g_wfc1 [DIM * HIDDEN];
__device__ __half g_wfc2 [HIDDEN * DIM];

// ---------------------------------------------------------------------------
// Helpers
// ---------------------------------------------------------------------------
__device__ __forceinline__ void mma16(float c[4], const uint32_t a[4], const uint32_t b[2]) {
    asm volatile(
        "mma.sync.aligned.m16n8k16.row.col.f32.f16.f16.f32 "
        "{%0,%1,%2,%3}, {%4,%5,%6,%7}, {%8,%9}, {%0,%1,%2,%3};"
        : "+f"(c[0]), "+f"(c[1]), "+f"(c[2]), "+f"(c[3])
        : "r"(a[0]), "r"(a[1]), "r"(a[2]), "r"(a[3]), "r"(b[0]), "r"(b[1]));
}

__device__ __forceinline__ void cpa16(uint32_t dst, const void* src) {
    asm volatile("cp.async.cg.shared.global [%0], [%1], 16;" :: "r"(dst), "l"(src) : "memory");
}
#define CP_COMMIT() asm volatile("cp.async.commit_group;" ::: "memory")
#define CP_WAIT1()  asm volatile("cp.async.wait_group 1;" ::: "memory")

__device__ __forceinline__ float gelu_f(float v) {
    return 0.5f * v * (1.0f + erff(v * 0.70710678118654752440f));
}

__device__ __forceinline__ uint32_t s2u(const void* p) {
    return (uint32_t)__cvta_generic_to_shared(p);
}
__device__ __forceinline__ void ldsm4(uint32_t& r0, uint32_t& r1, uint32_t& r2,
                                      uint32_t& r3, uint32_t addr) {
    asm volatile("ldmatrix.sync.aligned.m8n8.x4.shared.b16 {%0,%1,%2,%3}, [%4];"
                 : "=r"(r0), "=r"(r1), "=r"(r2), "=r"(r3) : "r"(addr));
}
__device__ __forceinline__ void ldsm4t(uint32_t& r0, uint32_t& r1, uint32_t& r2,
                                       uint32_t& r3, uint32_t addr) {
    asm volatile("ldmatrix.sync.aligned.m8n8.x4.trans.shared.b16 {%0,%1,%2,%3}, [%4];"
                 : "=r"(r0), "=r"(r1), "=r"(r2), "=r"(r3) : "r"(addr));
}

// ---------------------------------------------------------------------------
// fp16 A-fragment-major addressing (m16n8k16): tiles 128(M) x 64(K) = 8192
// halfs contiguous: [kki(4)][wm(2)][mt(4)][lane(32)][reg(4)] u32 + (k&1).
// ---------------------------------------------------------------------------
__device__ __forceinline__ size_t fragA_h(int row, int col, int K) {
    int KT = K >> 6;
    size_t tile = (size_t)(row >> 7) * KT + (col >> 6);
    int r = row & 127, c = col & 63;
    int wm = r >> 6, mt = (r >> 4) & 3, rr = r & 15;
    int kki = c >> 4, cc = c & 15;
    int lane = ((rr & 7) << 2) + ((cc >> 1) & 3);
    int reg  = (rr >> 3) + ((cc >> 3) << 1);
    return (((tile << 12) +
             (size_t)(((((kki << 1) + wm) << 2) + mt) << 7) + (lane << 2) + reg) << 1)
           + (cc & 1);
}

// ---------------------------------------------------------------------------
// Fused weight prep: W[K][N] fp32 row-major -> fp16 B-frag tiles, one pass.
// One block per output tile (K-range 64, N-range 128).  Load coalesced into
// smem as sm[n][k] halfs, then write frag-packed u32s coalesced.
// ---------------------------------------------------------------------------
__global__ __launch_bounds__(256) void wprep(
    const float* __restrict__ w0, __half* __restrict__ d0, int N0_, int K0_,
    const float* __restrict__ w1, __half* __restrict__ d1, int N1_, int K1_,
    const float* __restrict__ w2, __half* __restrict__ d2, int N2_, int K2_,
    const float* __restrict__ w3, __half* __restrict__ d3, int N3_, int K3_,
    int c0, int c1, int c2)
{
    __shared__ __half sm[128][66];   // [n][k], pad 66
    int gt = blockIdx.x;
    const float* W; __half* D; int N, K, lt;
    if      (gt < c0) { W = w0; D = d0; N = N0_; K = K0_; lt = gt; }
    else if (gt < c1) { W = w1; D = d1; N = N1_; K = K1_; lt = gt - c0; }
    else if (gt < c2) { W = w2; D = d2; N = N2_; K = K2_; lt = gt - c1; }
    else              { W = w3; D = d3; N = N3_; K = K3_; lt = gt - c2; }
    const int KT = K >> 6;
    const int kt = lt % KT, nb = lt / KT;
    const int k0 = kt << 6, n0 = nb << 7;
    const int tid = threadIdx.x;

    // Load 64(k) x 128(n) fp32, coalesced; store sm[n][k] halfs
    #pragma unroll
    for (int i = 0; i < 8; i++) {
        int idx = tid + (i << 8);
        int kr = idx >> 5, nc = (idx & 31) << 2;
        float4 v = *(const float4*)(W + (size_t)(k0 + kr) * N + n0 + nc);
        sm[nc + 0][kr] = __float2half_rn(v.x);
        sm[nc + 1][kr] = __float2half_rn(v.y);
        sm[nc + 2][kr] = __float2half_rn(v.z);
        sm[nc + 3][kr] = __float2half_rn(v.w);
    }
    __syncthreads();

    // Frag-pack: same layout as before, coalesced u32 writes
    uint32_t* __restrict__ Du = (uint32_t*)D;
    #pragma unroll
    for (int s = 0; s < 16; s++) {
        int u = (s << 8) + tid;
        int e   = u & 3;
        int ln  = (u >> 2) & 31;
        int j   = (u >> 7) & 3;
        int wn  = (u >> 9) & 1;
        int kki = (u >> 10) & 3;
        int nl = (wn << 6) + (((j << 1) + (e >> 1)) << 3) + (ln >> 2);
        int kl = (kki << 4) + ((ln & 3) << 1) + ((e & 1) << 3);
        Du[((size_t)lt << 12) + u] = *(const uint32_t*)&sm[nl][kl];
    }
}

// ---------------------------------------------------------------------------
// LayerNorm: one 256-thread block per row of 1024; fp16 A-frag output.
// ---------------------------------------------------------------------------
__global__ __launch_bounds__(256) void ln_kernel(
    const float* __restrict__ x, const float* __restrict__ g,
    const float* __restrict__ be, __half* __restrict__ out)
{
    const int row = blockIdx.x;
    const int tid = threadIdx.x;
    const float4 v = *(const float4*)(x + (size_t)row * DIM + (tid << 2));
    float s = v.x + v.y + v.z + v.w;
    float q = v.x * v.x + v.y * v.y + v.z * v.z + v.w * v.w;
    #pragma unroll
    for (int off = 16; off; off >>= 1) {
        s += __shfl_xor_sync(0xffffffffu, s, off);
        q += __shfl_xor_sync(0xffffffffu, q, off);
    }
    __shared__ float ss[8], sq[8];
    if ((tid & 31) == 0) { ss[tid >> 5] = s; sq[tid >> 5] = q; }
    __syncthreads();
    float ts = 0.f, tq = 0.f;
    #pragma unroll
    for (int i = 0; i < 8; i++) { ts += ss[i]; tq += sq[i]; }
    const float mu  = ts * (1.0f / DIM);
    const float var = tq * (1.0f / DIM) - mu * mu;
    const float inv = rsqrtf(var + 1e-5f);
    const float4 gg = *(const float4*)(g  + (tid << 2));
    const float4 bb = *(const float4*)(be + (tid << 2));
    const int col = tid << 2;
    *(__half2*)(out + fragA_h(row, col, DIM)) =
        __floats2half2_rn((v.x - mu) * inv * gg.x + bb.x,
                          (v.y - mu) * inv * gg.y + bb.y);
    *(__half2*)(out + fragA_h(row, col + 2, DIM)) =
        __floats2half2_rn((v.z - mu) * inv * gg.z + bb.z,
                          (v.w - mu) * inv * gg.w + bb.w);
}

// ---------------------------------------------------------------------------
// fp16 GEMM (unchanged from R16): C = A @ W + bias (opt GELU / +residual;
// output fp32-row / half-row / half A-frag).  CTA 128x128, k-tile 64,
// 3-stage cp.async, one barrier per k-tile.  4 warps, warp tile 64x64.
// ---------------------------------------------------------------------------
#define STG_U32 4096
#define GEMM_SMEM (6 * STG_U32 * 4)        // 98304 B

template <bool GELU_, bool RESID_, bool HROW_, bool FRAGOUT_>
__global__ __launch_bounds__(128, 1) void gemm_kernel(
    const __half* __restrict__ A, const __half* __restrict__ Wt,
    const float* __restrict__ bias, const float* __restrict__ R,
    float* __restrict__ Cf, __half* __restrict__ Ch, int M, int N, int K)
{
    extern __shared__ uint32_t gsm[];
    uint32_t* Asm = gsm;
    uint32_t* Bsm = gsm + 3 * STG_U32;

    const int tid  = threadIdx.x;
    const int warp = tid >> 5, lane = tid & 31;
    const int wm = warp >> 1, wn = warp & 1;
    const int KT = K >> 6;

    const uint32_t As_u = (uint32_t)__cvta_generic_to_shared(Asm);
    const uint32_t Bs_u = (uint32_t)__cvta_generic_to_shared(Bsm);

    float acc[4][8][4];
    #pragma unroll
    for (int i = 0; i < 4; i++)
        #pragma unroll
        for (int j = 0; j < 8; j++)
            #pragma unroll
            for (int k = 0; k < 4; k++) acc[i][j][k] = 0.f;

    auto load_stage = [&](int s, int kt_) {
        const __half* asrc = A  + (((size_t)blockIdx.y * KT + kt_) << 13);
        const __half* bsrc = Wt + (((size_t)blockIdx.x * KT + kt_) << 13);
        #pragma unroll
        for (int i = 0; i < 8; i++) {
            int c = tid + (i << 7);
            cpa16(As_u + (uint32_t)((s * STG_U32 + (c << 2)) << 2), asrc + (c << 3));
            cpa16(Bs_u + (uint32_t)((s * STG_U32 + (c << 2)) << 2), bsrc + (c << 3));
        }
    };

    load_stage(0, 0); CP_COMMIT();
    load_stage(1, 1); CP_COMMIT();

    for (int kt = 0; kt < KT; kt++) {
        CP_WAIT1();
        __syncthreads();
        if (kt + 2 < KT) load_stage((kt + 2) % 3, kt + 2);
        CP_COMMIT();

        const uint32_t* As_ = Asm + (kt % 3) * STG_U32;
        const uint32_t* Bs_ = Bsm + (kt % 3) * STG_U32;

        #pragma unroll
        for (int kki = 0; kki < 4; kki++) {
            uint32_t af[4][4], bf[8][2];
            #pragma unroll
            for (int mt = 0; mt < 4; mt++) {
                uint4 qa = *(const uint4*)(As_ +
                    (size_t)(((((kki << 1) + wm) << 2) + mt) << 7) + (lane << 2));
                af[mt][0] = qa.x; af[mt][1] = qa.y; af[mt][2] = qa.z; af[mt][3] = qa.w;
            }
            #pragma unroll
            for (int j = 0; j < 4; j++) {
                uint4 qb = *(const uint4*)(Bs_ +
                    (size_t)(((((kki << 1) + wn) << 2) + j) << 7) + (lane << 2));
                bf[2 * j    ][0] = qb.x; bf[2 * j    ][1] = qb.y;
                bf[2 * j + 1][0] = qb.z; bf[2 * j + 1][1] = qb.w;
            }
            #pragma unroll
            for (int mt = 0; mt < 4; mt++)
                #pragma unroll
                for (int nt = 0; nt < 8; nt++)
                    mma16(acc[mt][nt], af[mt], bf[nt]);
        }
    }

    // Epilogue
    const int bm = blockIdx.y << 7;
    const int bn = blockIdx.x << 7;
    #pragma unroll
    for (int mt = 0; mt < 4; mt++) {
        #pragma unroll
        for (int nt = 0; nt < 8; nt++) {
            int row0 = bm + (wm << 6) + (mt << 4) + (lane >> 2);
            int col  = bn + (wn << 6) + (nt << 3) + ((lane & 3) << 1);
            const float b0 = __ldg(bias + col);
            const float b1 = __ldg(bias + col + 1);
            #pragma unroll
            for (int half = 0; half < 2; half++) {
                int row = row0 + half * 8;
                float v0 = acc[mt][nt][half * 2 + 0] + b0;
                float v1 = acc[mt][nt][half * 2 + 1] + b1;
                if (GELU_) { v0 = gelu_f(v0); v1 = gelu_f(v1); }
                if (RESID_) {
                    v0 += __ldg(R + (size_t)row * N + col);
                    v1 += __ldg(R + (size_t)row * N + col + 1);
                }
                if (FRAGOUT_) {
                    *(__half2*)(Ch + fragA_h(row, col, N)) = __floats2half2_rn(v0, v1);
                } else if (HROW_) {
                    *(__half2*)(Ch + (size_t)row * N + col) = __floats2half2_rn(v0, v1);
                } else {
                    Cf[(size_t)row * N + col]     = v0;
                    Cf[(size_t)row * N + col + 1] = v1;
                }
            }
        }
    }
}

// ---------------------------------------------------------------------------
// Causal flash attention, fp16 m16n8k16, P-in-registers + ldmatrix.
// qkv fp16 row-major; output fp16 A-frag (K=DIM).
// grid = (S/128, NH, B); 256 threads = 8 warps, each warp 16 q rows.
// Smem: Q(128)+K(64)+V(64) rows x 72 halfs = 36864 B.
// ---------------------------------------------------------------------------
#define ASTR 72
#define ATTN_SMEM (256 * ASTR * 2)   // 36864 B

__global__ __launch_bounds__(256, 2) void attn_kernel(
    const __half* __restrict__ qkv, __half* __restrict__ outp)
{
    extern __shared__ __half smh[];
    __half (*Qs)[ASTR] = (__half(*)[ASTR])(smh);               // 128 q rows
    __half (*Ks)[ASTR] = (__half(*)[ASTR])(smh + 128 * ASTR);  //  64 kv rows
    __half (*Vs)[ASTR] = (__half(*)[ASTR])(smh + 192 * ASTR);  //  64 kv rows

    const int qb = blockIdx.x, h = blockIdx.y, b = blockIdx.z;
    const int tid = threadIdx.x, warp = tid >> 5, lane = tid & 31;
    const int q0 = qb << 7;

    // Load Q block (128 x 64 halfs) as 16B chunks
    const __half* qbase = qkv + (size_t)(b * SEQ + q0) * (3 * DIM) + h * HD;
    #pragma unroll
    for (int i = 0; i < 4; i++) {
        int idx = tid + (i << 8);
        int r = idx >> 3, c = (idx & 7) << 3;
        *(uint4*)&Qs[r][c] = *(const uint4*)(qbase + (size_t)r * (3 * DIM) + c);
    }

    float o[8][4];
    #pragma unroll
    for (int i = 0; i < 8; i++)
        #pragma unroll
        for (int j = 0; j < 4; j++) o[i][j] = 0.f;
    float m0 = -1e30f, m1 = -1e30f, l0 = 0.f, l1 = 0.f;

    const int ar = (warp << 4) + (lane >> 2);   // local q row; +8 for c2/c3
    const int nkb = (q0 >> 6) + 2;              // causal KV-block count

    // Per-lane ldmatrix source addresses (row/col patterns fixed per lane)
    const int lm_r  = (lane & 7) + (((lane >> 3) & 1) << 3);  // 0..15 pattern
    const int lm_hi = (lane >> 4);                            // 0/1

    for (int kb = 0; kb < nkb; kb++) {
        __syncthreads();   // previous K/V fully consumed
        const __half* kptr = qkv + (size_t)(b * SEQ + (kb << 6)) * (3 * DIM) + DIM + h * HD;
        const __half* vptr = kptr + DIM;
        #pragma unroll
        for (int i = 0; i < 2; i++) {
            int idx = tid + (i << 8);
            int r = idx >> 3, c = (idx & 7) << 3;
            *(uint4*)&Ks[r][c] = *(const uint4*)(kptr + (size_t)r * (3 * DIM) + c);
            *(uint4*)&Vs[r][c] = *(const uint4*)(vptr + (size_t)r * (3 * DIM) + c);
        }
        __syncthreads();

        // S = Q @ K^T  (warp: 16 q rows x 64 kv cols, K=64 head dim)
        float s[8][4];
        #pragma unroll
        for (int i = 0; i < 8; i++)
            #pragma unroll
            for (int j = 0; j < 4; j++) s[i][j] = 0.f;

        #pragma unroll
        for (int kki = 0; kki < 4; kki++) {
            const int ck = kki << 4;
            uint32_t a[4];
            ldsm4(a[0], a[1], a[2], a[3],
                  s2u(&Qs[(warp << 4) + lm_r][ck + (lm_hi << 3)]));
            #pragma unroll
            for (int q = 0; q < 4; q++) {
                // K b-frags: M0/M1 = n rows of nt=2q (k lo/hi), M2/M3 = nt=2q+1
                int nrow = (((q << 1) + lm_hi) << 3) + (lane & 7);
                int kcol = ck + (((lane >> 3) & 1) << 3);
                uint32_t b0, b1, b2, b3;
                ldsm4(b0, b1, b2, b3, s2u(&Ks[nrow][kcol]));
                uint32_t f0[2] = {b0, b1}, f1[2] = {b2, b3};
                mma16(s[2 * q],     a, f0);
                mma16(s[2 * q + 1], a, f1);
            }
        }

        // scale + causal mask + online softmax
        const int grow0 = q0 + ar;
        const int grow1 = grow0 + 8;
        const int cbase = (kb << 6) + ((lane & 3) << 1);
        float mn0 = m0, mn1 = m1;
        #pragma unroll
        for (int nt = 0; nt < 8; nt++) {
            int c0 = cbase + (nt << 3);
            s[nt][0] = (c0     <= grow0) ? s[nt][0] * 0.125f : -1e30f;
            s[nt][1] = (c0 + 1 <= grow0) ? s[nt][1] * 0.125f : -1e30f;
            s[nt][2] = (c0     <= grow1) ? s[nt][2] * 0.125f : -1e30f;
            s[nt][3] = (c0 + 1 <= grow1) ? s[nt][3] * 0.125f : -1e30f;
            mn0 = fmaxf(mn0, fmaxf(s[nt][0], s[nt][1]));
            mn1 = fmaxf(mn1, fmaxf(s[nt][2], s[nt][3]));
        }
        mn0 = fmaxf(mn0, __shfl_xor_sync(0xffffffffu, mn0, 1));
        mn0 = fmaxf(mn0, __shfl_xor_sync(0xffffffffu, mn0, 2));
        mn1 = fmaxf(mn1, __shfl_xor_sync(0xffffffffu, mn1, 1));
        mn1 = fmaxf(mn1, __shfl_xor_sync(0xffffffffu, mn1, 2));

        const float corr0 = __expf(m0 - mn0);
        const float corr1 = __expf(m1 - mn1);
        m0 = mn0; m1 = mn1;

        // P stays in registers: C-frag of S == A-frag of P
        uint32_t pa[8][2];
        float rs0 = 0.f, rs1 = 0.f;
        #pragma unroll
        for (int nt = 0; nt < 8; nt++) {
            float p0 = __expf(s[nt][0] - m0);
            float p1 = __expf(s[nt][1] - m0);
            float p2 = __expf(s[nt][2] - m1);
            float p3 = __expf(s[nt][3] - m1);
            rs0 += p0 + p1; rs1 += p2 + p3;
            __half2 h0 = __floats2half2_rn(p0, p1);
            __half2 h1 = __floats2half2_rn(p2, p3);
            pa[nt][0] = *(const uint32_t*)&h0;
            pa[nt][1] = *(const uint32_t*)&h1;
        }
        rs0 += __shfl_xor_sync(0xffffffffu, rs0, 1);
        rs0 += __shfl_xor_sync(0xffffffffu, rs0, 2);
        rs1 += __shfl_xor_sync(0xffffffffu, rs1, 1);
        rs1 += __shfl_xor_sync(0xffffffffu, rs1, 2);
        l0 = l0 * corr0 + rs0;
        l1 = l1 * corr1 + rs1;
        #pragma unroll
        for (int nt = 0; nt < 8; nt++) {
            o[nt][0] *= corr0; o[nt][1] *= corr0;
            o[nt][2] *= corr1; o[nt][3] *= corr1;
        }

        // O += P @ V : A-frags from pa, B-frags via ldmatrix.trans on Vs
        #pragma unroll
        for (int kki = 0; kki < 4; kki++) {
            const int ck = kki << 4;
            uint32_t a[4] = { pa[2 * kki][0], pa[2 * kki][1],
                              pa[2 * kki + 1][0], pa[2 * kki + 1][1] };
            #pragma unroll
            for (int q = 0; q < 4; q++) {
                // V b-frags: rows = kv (k), cols = d (n); .trans
                int vrow = ck + (((lane >> 3) & 1) << 3) + (lane & 7);
                int vcol = (((q << 1) + lm_hi) << 3);
                uint32_t b0, b1, b2, b3;
                ldsm4t(b0, b1, b2, b3, s2u(&Vs[vrow][vcol]));
                uint32_t f0[2] = {b0, b1}, f1[2] = {b2, b3};
                mma16(o[2 * q],     a, f0);
                mma16(o[2 * q + 1], a, f1);
            }
        }
    }

    // fp16 A-frag output for proj GEMM (K = DIM)
    const float inv0 = 1.0f / l0;
    const float inv1 = 1.0f / l1;
    const int row0 = b * SEQ + q0 + ar;
    const int row1 = row0 + 8;
    #pragma unroll
    for (int nt = 0; nt < 8; nt++) {
        int col = h * HD + (nt << 3) + ((lane & 3) << 1);
        *(__half2*)(outp + fragA_h(row0, col, DIM)) =
            __floats2half2_rn(o[nt][0] * inv0, o[nt][1] * inv0);
        *(__half2*)(outp + fragA_h(row1, col, DIM)) =
            __floats2half2_rn(o[nt][2] * inv1, o[nt][3] * inv1);
    }
}

// ---------------------------------------------------------------------------
// Launch
// ---------------------------------------------------------------------------
extern "C" void kernel_launch(void* const* d_in, const int* in_sizes, int n_in,
                              void* d_out, int out_size)
{
    const float* x      = (const float*)d_in[0];
    const float* w_qkv  = (const float*)d_in[1];
    const float* b_qkv  = (const float*)d_in[2];
    const float* w_proj = (const float*)d_in[3];
    const float* b_proj = (const float*)d_in[4];
    const float* g1     = (const float*)d_in[5];
    const float* beta1  = (const float*)d_in[6];
    const float* g2     = (const float*)d_in[7];
    const float* beta2  = (const float*)d_in[8];
    const float* w_fc1  = (const float*)d_in[9];
    const float* b_fc1  = (const float*)d_in[10];
    const float* w_fc2  = (const float*)d_in[11];
    const float* b_fc2  = (const float*)d_in[12];
    float* out = (float*)d_out;

    __half *h, *qkv, *attn, *mid, *wqkv, *wproj, *wfc1, *wfc2;
    float *x1;
    cudaGetSymbolAddress((void**)&h,     g_h);
    cudaGetSymbolAddress((void**)&qkv,   g_qkv);
    cudaGetSymbolAddress((void**)&attn,  g_attn);
    cudaGetSymbolAddress((void**)&x1,    g_x1);
    cudaGetSymbolAddress((void**)&mid,   g_mid);
    cudaGetSymbolAddress((void**)&wqkv,  g_wqkv);
    cudaGetSymbolAddress((void**)&wproj, g_wproj);
    cudaGetSymbolAddress((void**)&wfc1,  g_wfc1);
    cudaGetSymbolAddress((void**)&wfc2,  g_wfc2);

    cudaFuncSetAttribute(attn_kernel, cudaFuncAttributeMaxDynamicSharedMemorySize, ATTN_SMEM);
    cudaFuncSetAttribute(gemm_kernel<false, false, true, false>,
                         cudaFuncAttributeMaxDynamicSharedMemorySize, GEMM_SMEM);
    cudaFuncSetAttribute(gemm_kernel<false, true, false, false>,
                         cudaFuncAttributeMaxDynamicSharedMemorySize, GEMM_SMEM);
    cudaFuncSetAttribute(gemm_kernel<true, false, false, true>,
                         cudaFuncAttributeMaxDynamicSharedMemorySize, GEMM_SMEM);

    // 0) Fused weight prep (1 launch).  Tiles: qkv 384, proj 128, fc1 512,
    //    fc2 512 -> prefix counts 384 / 512 / 1024; total 1536.
    wprep<<<1536, 256>>>(w_qkv,  wqkv,  3 * DIM, DIM,
                         w_proj, wproj, DIM,     DIM,
                         w_fc1,  wfc1,  HIDDEN,  DIM,
                         w_fc2,  wfc2,  DIM,     HIDDEN,
                         384, 512, 1024);

    // 1) LN1 (fp16 A-frag out)
    ln_kernel<<<NTOK, 256>>>(x, g1, beta1, h);
    // 2) QKV = h @ w_qkv + b_qkv  [4096,1024]x[1024,3072], fp16 row-major out
    gemm_kernel<false, false, true, false><<<dim3(3 * DIM / 128, NTOK / 128), 128, GEMM_SMEM>>>(
        h, wqkv, b_qkv, nullptr, nullptr, qkv, NTOK, 3 * DIM, DIM);
    // 3) Causal MHA (fp16 in, fp16 A-frag out)
    attn_kernel<<<dim3(SEQ / 128, NH, 2), 256, ATTN_SMEM>>>(qkv, attn);
    // 4) x1 = x + attn @ w_proj + b_proj (fp32 row-major residual)
    gemm_kernel<false, true, false, false><<<dim3(DIM / 128, NTOK / 128), 128, GEMM_SMEM>>>(
        attn, wproj, b_proj, x, x1, nullptr, NTOK, DIM, DIM);
    // 5) LN2 (fp16 A-frag out)
    ln_kernel<<<NTOK, 256>>>(x1, g2, beta2, h);
    // 6) mid = gelu(h @ w_fc1 + b_fc1)  [4096,1024]x[1024,4096], fp16 A-frag out
    gemm_kernel<true, false, false, true><<<dim3(HIDDEN / 128, NTOK / 128), 128, GEMM_SMEM>>>(
        h, wfc1, b_fc1, nullptr, nullptr, mid, NTOK, HIDDEN, DIM);
    // 7) out = x1 + mid @ w_fc2 + b_fc2  [4096,4096]x[4096,1024], fp32 row-major
    gemm_kernel<false, true, false, false><<<dim3(DIM / 128, NTOK / 128), 128, GEMM_SMEM>>>(
        mid, wfc2, b_fc2, x1, out, nullptr, NTOK, DIM, HIDDEN);
}